// round 8
// baseline (speedup 1.0000x reference)
#include <cuda_runtime.h>
#include <cuda_bf16.h>
#include <cstdint>

#define BB 8
#define LL 4096
#define DM 512
#define HH 8
#define DD 64
#define UU 45
#define NCH 16
#define CHUNK (LL / NCH)
#define SCALE 0.125f
#define BL (BB * LL)

// ---------------- scratch ----------------
__device__ float g_Q[BB * HH * LL * DD];
__device__ float g_K[BB * HH * LL * DD];
__device__ float g_V[BB * HH * LL * DD];
__device__ float g_M[BB * HH * LL];
__device__ int   g_top[BB * HH * UU];
__device__ float g_meanV[BB * HH * DD];
__device__ float g_base[BB * DM];
__device__ float g_pm[BB * HH * NCH * UU];
__device__ float g_pl[BB * HH * NCH * UU];
__device__ float g_pacc[BB * HH * NCH * UU * DD];
__device__ float g_attn[BB * HH * UU * DD];
__device__ __align__(16) __nv_bfloat16 g_Wth[3][DM * DM];
__device__ __align__(16) __nv_bfloat16 g_Wtl[3][DM * DM];
__device__ __align__(16) __nv_bfloat16 g_Ah[3][BL * DM];
__device__ __align__(16) __nv_bfloat16 g_Al[3][BL * DM];

// ================= PTX helpers =================
__device__ __forceinline__ uint32_t smem_u32(const void* p) {
    uint32_t a;
    asm("{ .reg .u64 t; cvta.to.shared.u64 t, %1; cvt.u32.u64 %0, t; }"
        : "=r"(a) : "l"(p));
    return a;
}
#define SWZ128(off)   ((off) ^ (((off) >> 3) & 0x70))

#define CP_ASYNC16(dst, src) \
    asm volatile("cp.async.cg.shared.global [%0], [%1], 16;" :: "r"(dst), "l"(src))
#define CP_COMMIT() asm volatile("cp.async.commit_group;" ::: "memory")
#define CP_WAIT(n)  asm volatile("cp.async.wait_group %0;" :: "n"(n) : "memory")

__device__ __forceinline__ void ldsm_x4(uint32_t* r, uint32_t addr) {
    asm volatile("ldmatrix.sync.aligned.m8n8.x4.shared.b16 {%0,%1,%2,%3}, [%4];"
        : "=r"(r[0]), "=r"(r[1]), "=r"(r[2]), "=r"(r[3]) : "r"(addr));
}
__device__ __forceinline__ void mma16816(float* d, const uint32_t* a,
                                         const uint32_t* b, const float* c) {
    asm volatile(
        "mma.sync.aligned.m16n8k16.row.col.f32.bf16.bf16.f32 "
        "{%0,%1,%2,%3},{%4,%5,%6,%7},{%8,%9},{%10,%11,%12,%13};"
        : "=f"(d[0]), "=f"(d[1]), "=f"(d[2]), "=f"(d[3])
        : "r"(a[0]), "r"(a[1]), "r"(a[2]), "r"(a[3]),
          "r"(b[0]), "r"(b[1]),
          "f"(c[0]), "f"(c[1]), "f"(c[2]), "f"(c[3]));
}

// round-4 stage layout: 4 tiles of 128x64 bf16 (16KB each), 2 stages
#define T_AH 0
#define T_AL 16384
#define T_WH 32768
#define T_WL 49152
#define STAGE_SZ 65536
#define OFF_BIAS 131072
#define DYN_SMEM (131072 + 1024)
// Q-kernel extras: K_sample (2 heads x 45 x 64 fp32) + sample indices
#define OFF_KS   131584
#define OFF_SSI  (OFF_KS + 2 * UU * 64 * 4)      /* 154624 */
#define DYN_SMEM_Q (OFF_SSI + 256)

// ---------------- W prep: transpose + split to bf16 hi/lo ----------------
__global__ __launch_bounds__(256) void prep_w(const float* __restrict__ Wq,
                                              const float* __restrict__ Wk,
                                              const float* __restrict__ Wv)
{
    int which = blockIdx.y;
    const float* W = (which == 0) ? Wq : (which == 1) ? Wk : Wv;
    int idx = (blockIdx.x * 256 + threadIdx.x) * 4;
    int n = idx >> 9, k = idx & 511;
#pragma unroll
    for (int i = 0; i < 4; i++) {
        float x = W[(size_t)(k + i) * DM + n];
        __nv_bfloat16 hb = __float2bfloat16(x);
        g_Wth[which][(size_t)n * DM + k + i] = hb;
        g_Wtl[which][(size_t)n * DM + k + i] = __float2bfloat16(x - __bfloat162float(hb));
    }
}

// ---------------- activation split: fp32 -> bf16 hi/lo ----------------
__global__ __launch_bounds__(256) void split_act(const float* __restrict__ q,
                                                 const float* __restrict__ k,
                                                 const float* __restrict__ v)
{
    int which = blockIdx.y;
    const float* A = (which == 0) ? q : (which == 1) ? k : v;
    size_t i0 = ((size_t)blockIdx.x * 256 + threadIdx.x) * 8;
    float4 f0 = *(const float4*)(A + i0);
    float4 f1 = *(const float4*)(A + i0 + 4);
    float xs[8] = {f0.x, f0.y, f0.z, f0.w, f1.x, f1.y, f1.z, f1.w};
    __align__(16) __nv_bfloat16 h[8], l[8];
#pragma unroll
    for (int i = 0; i < 8; i++) {
        __nv_bfloat16 hb = __float2bfloat16(xs[i]);
        h[i] = hb;
        l[i] = __float2bfloat16(xs[i] - __bfloat162float(hb));
    }
    *(uint4*)&g_Ah[which][i0] = *(uint4*)h;
    *(uint4*)&g_Al[which][i0] = *(uint4*)l;
}

// ================= shared GEMM body (round-4 config) =================
// computes the 128x128 fp32 tile into Cs (dsm as float*, stride 132), bias added.
template<int WHICH>
__device__ __forceinline__ void gemm_tile_body(
    char* dsm, const float* bias, int m0, int n0)
{
    const __nv_bfloat16* Ah = g_Ah[WHICH];
    const __nv_bfloat16* Al = g_Al[WHICH];
    const __nv_bfloat16* Wh = g_Wth[WHICH];
    const __nv_bfloat16* Wl = g_Wtl[WHICH];

    uint32_t su = smem_u32(dsm);
    int tid = threadIdx.x;
    int lane = tid & 31, wid = tid >> 5;
    int wm = wid & 3, wn = wid >> 2;

    float* bias_s = (float*)(dsm + OFF_BIAS);
    if (tid < 128) bias_s[tid] = bias[n0 + tid];

    float acc[2][8][4];
#pragma unroll
    for (int a = 0; a < 2; a++)
#pragma unroll
        for (int b = 0; b < 8; b++)
#pragma unroll
            for (int c = 0; c < 4; c++) acc[a][b][c] = 0.f;

    auto load_stage = [&](int stage, int k0) {
        uint32_t sb = su + stage * STAGE_SZ;
#pragma unroll
        for (int t = 0; t < 4; t++) {
            int idx = tid + 256 * t;
            int r = idx >> 3, c = idx & 7;
            uint32_t sw = SWZ128((uint32_t)(r * 128 + c * 16));
            CP_ASYNC16(sb + T_AH + sw, Ah + (size_t)(m0 + r) * DM + k0 + c * 8);
            CP_ASYNC16(sb + T_AL + sw, Al + (size_t)(m0 + r) * DM + k0 + c * 8);
            CP_ASYNC16(sb + T_WH + sw, Wh + (size_t)(n0 + r) * DM + k0 + c * 8);
            CP_ASYNC16(sb + T_WL + sw, Wl + (size_t)(n0 + r) * DM + k0 + c * 8);
        }
        CP_COMMIT();
    };

    load_stage(0, 0);

    int a_row = (lane & 15), a_k16 = (lane >> 4) << 4;
    int b_grp = lane >> 3;
    int b_row = ((b_grp >> 1) << 3) + (lane & 7);
    int b_k16 = (b_grp & 1) << 4;

    for (int chunk = 0; chunk < 8; chunk++) {
        if (chunk < 7) load_stage((chunk + 1) & 1, (chunk + 1) * 64);
        if (chunk < 7) { CP_WAIT(1); } else { CP_WAIT(0); }
        __syncthreads();

        uint32_t sb = su + (chunk & 1) * STAGE_SZ;
#pragma unroll
        for (int ks = 0; ks < 4; ks++) {
            uint32_t ah[2][4], al[2][4], bh[16], bl[16];
#pragma unroll
            for (int mf = 0; mf < 2; mf++) {
                int row = wm * 32 + mf * 16 + a_row;
                uint32_t off = SWZ128((uint32_t)(row * 128 + ks * 32 + a_k16));
                ldsm_x4(ah[mf], sb + T_AH + off);
                ldsm_x4(al[mf], sb + T_AL + off);
            }
#pragma unroll
            for (int g2 = 0; g2 < 4; g2++) {
                int row = wn * 64 + g2 * 16 + b_row;
                uint32_t off = SWZ128((uint32_t)(row * 128 + ks * 32 + b_k16));
                ldsm_x4(&bh[g2 * 4], sb + T_WH + off);
                ldsm_x4(&bl[g2 * 4], sb + T_WL + off);
            }
#pragma unroll
            for (int mf = 0; mf < 2; mf++)
#pragma unroll
                for (int nf = 0; nf < 8; nf++)
                    mma16816(acc[mf][nf], ah[mf], &bh[nf * 2], acc[mf][nf]);
#pragma unroll
            for (int mf = 0; mf < 2; mf++)
#pragma unroll
                for (int nf = 0; nf < 8; nf++)
                    mma16816(acc[mf][nf], ah[mf], &bl[nf * 2], acc[mf][nf]);
#pragma unroll
            for (int mf = 0; mf < 2; mf++)
#pragma unroll
                for (int nf = 0; nf < 8; nf++)
                    mma16816(acc[mf][nf], al[mf], &bh[nf * 2], acc[mf][nf]);
        }
        __syncthreads();
    }

    float* Cs = (float*)dsm;
#pragma unroll
    for (int mf = 0; mf < 2; mf++)
#pragma unroll
        for (int nf = 0; nf < 8; nf++) {
            int r = wm * 32 + mf * 16 + (lane >> 2);
            int col = wn * 64 + nf * 8 + (lane & 3) * 2;
            Cs[r * 132 + col]           = acc[mf][nf][0] + bias_s[col];
            Cs[r * 132 + col + 1]       = acc[mf][nf][1] + bias_s[col + 1];
            Cs[(r + 8) * 132 + col]     = acc[mf][nf][2] + bias_s[col];
            Cs[(r + 8) * 132 + col + 1] = acc[mf][nf][3] + bias_s[col + 1];
        }
    __syncthreads();
}

// shared scatter of the Cs tile to (B,H,L,D) layout
__device__ __forceinline__ void scatter_tile(char* dsm, float* P, int m0, int n0)
{
    float* Cs = (float*)dsm;
    int tid = threadIdx.x;
#pragma unroll
    for (int it = 0; it < 16; it++) {
        int idx = tid + it * 256;
        int row = idx >> 5, c4 = idx & 31;
        int m = m0 + row;
        int b = m >> 12, l = m & (LL - 1);
        int n = n0 + c4 * 4;
        int h = n >> 6, d = n & 63;
        float4 v;
        v.x = Cs[row * 132 + c4 * 4 + 0];
        v.y = Cs[row * 132 + c4 * 4 + 1];
        v.z = Cs[row * 132 + c4 * 4 + 2];
        v.w = Cs[row * 132 + c4 * 4 + 3];
        *(float4*)&P[((size_t)(b * HH + h) * LL + l) * DD + d] = v;
    }
}

// ---------------- K / V projections ----------------
__global__ __launch_bounds__(256) void proj_kv(
    const float* __restrict__ bk, const float* __restrict__ bv)
{
    extern __shared__ char dsm[];
    int m0 = blockIdx.y * 128, n0 = blockIdx.x * 128;
    if (blockIdx.z == 0) {
        gemm_tile_body<1>(dsm, bk, m0, n0);
        scatter_tile(dsm, g_K, m0, n0);
    } else {
        gemm_tile_body<2>(dsm, bv, m0, n0);
        scatter_tile(dsm, g_V, m0, n0);
    }
}

// ---------------- Q projection + fused sampled scoring (M) ----------------
__global__ __launch_bounds__(256) void proj_q_score(
    const float* __restrict__ bq, const int* __restrict__ sidx)
{
    extern __shared__ char dsm[];
    int tid = threadIdx.x;
    int m0 = blockIdx.y * 128, n0 = blockIdx.x * 128;
    int b = m0 >> 12;
    int h0 = n0 >> 6;                 // first of the 2 heads in this tile

    // preload K_sample for both heads into smem (g_K ready from proj_kv)
    int* ssi = (int*)(dsm + OFF_SSI);
    float* Ksm = (float*)(dsm + OFF_KS);
    if (tid < UU) ssi[tid] = sidx[tid];
    __syncthreads();
    for (int i = tid; i < 2 * UU * 16; i += 256) {
        int hh = i / (UU * 16);
        int r = i % (UU * 16);
        int j = r >> 4, c4 = r & 15;
        *(float4*)&Ksm[hh * UU * 64 + j * 64 + c4 * 4] =
            *(const float4*)&g_K[((size_t)(b * HH + h0 + hh) * LL + ssi[j]) * DD + c4 * 4];
    }
    // NOTE: no sync needed here vs gemm body start (bias area disjoint from KS);
    // gemm body's internal syncs cover visibility before the epilogue reads Ksm.

    gemm_tile_body<0>(dsm, bq, m0, n0);
    scatter_tile(dsm, g_Q, m0, n0);

    // ---- fused sampled scoring: M = (max - mean) * scale ----
    float* Cs = (float*)dsm;
    int row = tid >> 1, hh = tid & 1;
    const float* qr = Cs + row * 132 + hh * 64;
    const float* kk = Ksm + hh * UU * 64;

    float s[UU];
#pragma unroll
    for (int j = 0; j < UU; j++) s[j] = 0.f;

    for (int c = 0; c < DD; c += 4) {
        float4 q4 = *(const float4*)(qr + c);
#pragma unroll
        for (int j = 0; j < UU; j++) {
            float4 k4 = *(const float4*)(kk + j * 64 + c);
            s[j] += q4.x * k4.x + q4.y * k4.y + q4.z * k4.z + q4.w * k4.w;
        }
    }
    float mx = s[0], sm = s[0];
#pragma unroll
    for (int j = 1; j < UU; j++) {
        mx = fmaxf(mx, s[j]);
        sm += s[j];
    }
    int l = (m0 & (LL - 1)) + row;
    g_M[((size_t)(b * HH + h0 + hh)) * LL + l] = (mx - sm * (1.f / UU)) * SCALE;
}

// ---------------- top-45 selection per (b,h), 512 threads ----------------
__global__ __launch_bounds__(512) void topk_kernel()
{
    __shared__ float vals[LL];
    __shared__ float rv[512];
    __shared__ int ri[512];
    int bh = blockIdx.x, tid = threadIdx.x;
    for (int i = tid; i < LL; i += 512) vals[i] = g_M[(size_t)bh * LL + i];
    __syncthreads();
    for (int it = 0; it < UU; it++) {
        float bv = -1e38f; int bi = 0x7fffffff;
        for (int i = tid; i < LL; i += 512) {
            float v = vals[i];
            if (v > bv) { bv = v; bi = i; }
        }
        rv[tid] = bv; ri[tid] = bi;
        __syncthreads();
        for (int s = 256; s > 0; s >>= 1) {
            if (tid < s) {
                float v2 = rv[tid + s]; int i2 = ri[tid + s];
                if (v2 > rv[tid] || (v2 == rv[tid] && i2 < ri[tid])) {
                    rv[tid] = v2; ri[tid] = i2;
                }
            }
            __syncthreads();
        }
        if (tid == 0) {
            g_top[bh * UU + it] = ri[0];
            vals[ri[0]] = -1e38f;
        }
        __syncthreads();
    }
}

// ---------------- mean(V) over L per (b,h,d) ----------------
__global__ __launch_bounds__(256) void meanv_kernel()
{
    __shared__ float red[4][64];
    int bh = blockIdx.x, tid = threadIdx.x;
    int d = tid & 63, part = tid >> 6;
    const float* base = g_V + ((size_t)bh * LL + part * (LL / 4)) * DD + d;
    float s0 = 0.f, s1 = 0.f, s2 = 0.f, s3 = 0.f;
    for (int i = 0; i < LL / 4; i += 4) {
        s0 += base[(size_t)(i + 0) * DD];
        s1 += base[(size_t)(i + 1) * DD];
        s2 += base[(size_t)(i + 2) * DD];
        s3 += base[(size_t)(i + 3) * DD];
    }
    red[part][d] = (s0 + s1) + (s2 + s3);
    __syncthreads();
    if (part == 0)
        g_meanV[bh * DD + d] =
            (red[0][d] + red[1][d] + red[2][d] + red[3][d]) * (1.f / LL);
}

// ---------------- base row per batch ----------------
__global__ __launch_bounds__(512) void base_kernel(const float* __restrict__ Wo,
                                                   const float* __restrict__ bo)
{
    int b = blockIdx.x, c = threadIdx.x;
    float acc = bo[c];
    const float* mv = g_meanV + b * DM;
    for (int k = 0; k < DM; k++) acc += mv[k] * Wo[(size_t)k * DM + c];
    g_base[b * DM + c] = acc;
}

// ---------------- flash attention for top-45 queries ----------------
__global__ __launch_bounds__(384) void att_kernel()
{
    __shared__ __align__(16) float Qs[UU * 64];
    __shared__ __align__(16) float Ks[64 * 68];
    __shared__ __align__(16) float Vs[64 * 64];
    int bh = blockIdx.x, ch = blockIdx.y;
    int tid = threadIdx.x;
    int q = tid >> 3, lane8 = tid & 7;
    int qe = (q < UU) ? q : (UU - 1);

    for (int i = tid; i < UU * 64; i += 384) {
        int qq = i >> 6, d = i & 63;
        int l = g_top[bh * UU + qq];
        Qs[i] = g_Q[((size_t)bh * LL + l) * DD + d];
    }
    __syncthreads();

    float4 q4[16];
#pragma unroll
    for (int dd = 0; dd < 16; dd++) q4[dd] = *(const float4*)(Qs + qe * 64 + dd * 4);

    float m = -1e30f, lsum = 0.f;
    float acc[8];
#pragma unroll
    for (int i = 0; i < 8; i++) acc[i] = 0.f;

    int key0 = ch * CHUNK;
    for (int t0 = 0; t0 < CHUNK; t0 += 64) {
        __syncthreads();
        for (int i = tid; i < 1024; i += 384) {
            int r = i >> 4, c4 = (i & 15) << 2;
            size_t gidx = ((size_t)bh * LL + key0 + t0 + r) * DD + c4;
            *(float4*)&Ks[r * 68 + c4] = *(const float4*)&g_K[gidx];
            *(float4*)&Vs[r * 64 + c4] = *(const float4*)&g_V[gidx];
        }
        __syncthreads();

        float s[8];
#pragma unroll
        for (int tt = 0; tt < 8; tt++) {
            int j = lane8 + 8 * tt;
            const float* kr = Ks + j * 68;
            float sv = 0.f;
#pragma unroll
            for (int dd = 0; dd < 16; dd++) {
                float4 kv = *(const float4*)(kr + dd * 4);
                sv += q4[dd].x * kv.x + q4[dd].y * kv.y +
                      q4[dd].z * kv.z + q4[dd].w * kv.w;
            }
            s[tt] = sv * SCALE;
        }
        float tmax = s[0];
#pragma unroll
        for (int tt = 1; tt < 8; tt++) tmax = fmaxf(tmax, s[tt]);
#pragma unroll
        for (int off = 4; off; off >>= 1)
            tmax = fmaxf(tmax, __shfl_xor_sync(0xffffffffu, tmax, off));
        float mnew = fmaxf(m, tmax);
        float alpha = __expf(m - mnew);
        lsum *= alpha;
#pragma unroll
        for (int i = 0; i < 8; i++) acc[i] *= alpha;
        float p[8];
#pragma unroll
        for (int tt = 0; tt < 8; tt++) {
            p[tt] = __expf(s[tt] - mnew);
            lsum += p[tt];
        }
        m = mnew;
#pragma unroll
        for (int j = 0; j < 64; j++) {
            float pj = __shfl_sync(0xffffffffu, p[j >> 3], j & 7, 8);
            const float* vr = Vs + j * 64 + lane8 * 8;
            float4 v0 = *(const float4*)vr;
            float4 v1 = *(const float4*)(vr + 4);
            acc[0] += pj * v0.x; acc[1] += pj * v0.y;
            acc[2] += pj * v0.z; acc[3] += pj * v0.w;
            acc[4] += pj * v1.x; acc[5] += pj * v1.y;
            acc[6] += pj * v1.z; acc[7] += pj * v1.w;
        }
    }
#pragma unroll
    for (int off = 4; off; off >>= 1)
        lsum += __shfl_xor_sync(0xffffffffu, lsum, off);

    if (q < UU) {
        int idx = (bh * NCH + ch) * UU + q;
        if (lane8 == 0) { g_pm[idx] = m; g_pl[idx] = lsum; }
        float* pa = g_pacc + (size_t)idx * DD + lane8 * 8;
#pragma unroll
        for (int i = 0; i < 8; i++) pa[i] = acc[i];
    }
}

// ---------------- merge split-L partials ----------------
__global__ __launch_bounds__(64) void combine_kernel()
{
    int r = blockIdx.x;
    int d = threadIdx.x;
    int bh = r / UU, q = r % UU;
    float M = -1e30f;
#pragma unroll
    for (int c = 0; c < NCH; c++)
        M = fmaxf(M, g_pm[(bh * NCH + c) * UU + q]);
    float Ltot = 0.f, acc = 0.f;
#pragma unroll
    for (int c = 0; c < NCH; c++) {
        int idx = (bh * NCH + c) * UU + q;
        float e = __expf(g_pm[idx] - M);
        Ltot += g_pl[idx] * e;
        acc  += e * g_pacc[(size_t)idx * DD + d];
    }
    g_attn[(size_t)(bh * UU + q) * DD + d] = acc / Ltot;
}

// ---------------- final output: 4 rows per block ----------------
__global__ __launch_bounds__(128) void final_kernel4(const float* __restrict__ Wo,
                                                     float* __restrict__ out)
{
    __shared__ int tops[HH * UU];
    __shared__ float delta[64];
    int b = blockIdx.y;
    int q0 = blockIdx.x * 4;
    int tid = threadIdx.x;
    int c0 = tid * 4;

    for (int i = tid; i < HH * UU; i += 128) tops[i] = g_top[b * HH * UU + i];
    __syncthreads();

    float4 bsv = *(const float4*)&g_base[b * DM + c0];
    float4 acc[4] = {bsv, bsv, bsv, bsv};

    for (int i = 0; i < HH * UU; i++) {
        int t = tops[i];
        int r = t - q0;
        if (r >= 0 && r < 4) {
            int h = i / UU, j = i % UU;
            if (tid < 64)
                delta[tid] = g_attn[((size_t)(b * HH + h) * UU + j) * DD + tid] -
                             g_meanV[(b * HH + h) * DD + tid];
            __syncthreads();
#pragma unroll 4
            for (int d = 0; d < 64; d++) {
                float dv = delta[d];
                float4 w = *(const float4*)&Wo[(size_t)(h * 64 + d) * DM + c0];
                acc[r].x += dv * w.x; acc[r].y += dv * w.y;
                acc[r].z += dv * w.z; acc[r].w += dv * w.w;
            }
            __syncthreads();
        }
    }
#pragma unroll
    for (int r = 0; r < 4; r++)
        *(float4*)&out[((size_t)b * LL + q0 + r) * DM + c0] = acc[r];
}

// ---------------- launcher ----------------
extern "C" void kernel_launch(void* const* d_in, const int* in_sizes, int n_in,
                              void* d_out, int out_size)
{
    const float* queries = (const float*)d_in[0];
    const float* keys    = (const float*)d_in[1];
    const float* values  = (const float*)d_in[2];
    const int*   sidx    = (const int*)d_in[3];
    const float* Wq = (const float*)d_in[4];
    const float* bq = (const float*)d_in[5];
    const float* Wk = (const float*)d_in[6];
    const float* bk = (const float*)d_in[7];
    const float* Wv = (const float*)d_in[8];
    const float* bv = (const float*)d_in[9];
    const float* Wo = (const float*)d_in[10];
    const float* bo = (const float*)d_in[11];
    float* out = (float*)d_out;

    static int smem_set = 0;
    if (!smem_set) {
        cudaFuncSetAttribute(proj_kv, cudaFuncAttributeMaxDynamicSharedMemorySize, DYN_SMEM);
        cudaFuncSetAttribute(proj_q_score, cudaFuncAttributeMaxDynamicSharedMemorySize, DYN_SMEM_Q);
        smem_set = 1;
    }

    prep_w<<<dim3(256, 3), 256>>>(Wq, Wk, Wv);
    split_act<<<dim3(BL * DM / (256 * 8), 3), 256>>>(queries, keys, values);

    proj_kv<<<dim3(DM / 128, BL / 128, 2), 256, DYN_SMEM>>>(bk, bv);
    proj_q_score<<<dim3(DM / 128, BL / 128), 256, DYN_SMEM_Q>>>(bq, sidx);

    topk_kernel<<<BB * HH, 512>>>();
    meanv_kernel<<<BB * HH, 256>>>();
    base_kernel<<<BB, 512>>>(Wo, bo);
    att_kernel<<<dim3(BB * HH, NCH), 384>>>();
    combine_kernel<<<BB * HH * UU, 64>>>();
    final_kernel4<<<dim3(LL / 4, BB), 128>>>(Wo, out);
}

// round 9
// speedup vs baseline: 1.0648x; 1.0648x over previous
#include <cuda_runtime.h>
#include <cuda_bf16.h>
#include <cstdint>

#define BB 8
#define LL 4096
#define DM 512
#define HH 8
#define DD 64
#define UU 45
#define NCH 16
#define CHUNK (LL / NCH)
#define SCALE 0.125f
#define BL (BB * LL)

// ---------------- scratch ----------------
__device__ float g_Q[BB * HH * LL * DD];
__device__ float g_K[BB * HH * LL * DD];
__device__ float g_V[BB * HH * LL * DD];
__device__ float g_M[BB * HH * LL];
__device__ int   g_top[BB * HH * UU];
__device__ float g_meanV[BB * HH * DD];
__device__ float g_base[BB * DM];
__device__ float g_pm[BB * HH * NCH * UU];
__device__ float g_pl[BB * HH * NCH * UU];
__device__ float g_pacc[BB * HH * NCH * UU * DD];
__device__ float g_attn[BB * HH * UU * DD];
__device__ __align__(16) __nv_bfloat16 g_Wth[3][DM * DM];
__device__ __align__(16) __nv_bfloat16 g_Wtl[3][DM * DM];
__device__ __align__(16) __nv_bfloat16 g_Ah[3][BL * DM];
__device__ __align__(16) __nv_bfloat16 g_Al[3][BL * DM];

// ================= PTX helpers =================
__device__ __forceinline__ uint32_t smem_u32(const void* p) {
    uint32_t a;
    asm("{ .reg .u64 t; cvta.to.shared.u64 t, %1; cvt.u32.u64 %0, t; }"
        : "=r"(a) : "l"(p));
    return a;
}
#define SWZ128(off)   ((off) ^ (((off) >> 3) & 0x70))

#define CP_ASYNC16(dst, src) \
    asm volatile("cp.async.cg.shared.global [%0], [%1], 16;" :: "r"(dst), "l"(src))
#define CP_COMMIT() asm volatile("cp.async.commit_group;" ::: "memory")
#define CP_WAIT(n)  asm volatile("cp.async.wait_group %0;" :: "n"(n) : "memory")

__device__ __forceinline__ void ldsm_x4(uint32_t* r, uint32_t addr) {
    asm volatile("ldmatrix.sync.aligned.m8n8.x4.shared.b16 {%0,%1,%2,%3}, [%4];"
        : "=r"(r[0]), "=r"(r[1]), "=r"(r[2]), "=r"(r[3]) : "r"(addr));
}
__device__ __forceinline__ void mma16816(float* d, const uint32_t* a,
                                         const uint32_t* b, const float* c) {
    asm volatile(
        "mma.sync.aligned.m16n8k16.row.col.f32.bf16.bf16.f32 "
        "{%0,%1,%2,%3},{%4,%5,%6,%7},{%8,%9},{%10,%11,%12,%13};"
        : "=f"(d[0]), "=f"(d[1]), "=f"(d[2]), "=f"(d[3])
        : "r"(a[0]), "r"(a[1]), "r"(a[2]), "r"(a[3]),
          "r"(b[0]), "r"(b[1]),
          "f"(c[0]), "f"(c[1]), "f"(c[2]), "f"(c[3]));
}

// M=256 x N=128 tile, K-chunk 64, 2 stages
// A tiles: 256x64 bf16 = 32KB (hi,lo); W tiles: 128x64 bf16 = 16KB (hi,lo)
#define T_AH 0
#define T_AL 32768
#define T_WH 65536
#define T_WL 81920
#define STAGE_SZ 98304
#define OFF_BIAS (STAGE_SZ * 2)          /* 196608 */
#define DYN_SMEM (OFF_BIAS + 1024)

// ---------------- W prep: transpose + split to bf16 hi/lo ----------------
__global__ __launch_bounds__(256) void prep_w(const float* __restrict__ Wq,
                                              const float* __restrict__ Wk,
                                              const float* __restrict__ Wv)
{
    int which = blockIdx.y;
    const float* W = (which == 0) ? Wq : (which == 1) ? Wk : Wv;
    int idx = (blockIdx.x * 256 + threadIdx.x) * 4;
    int n = idx >> 9, k = idx & 511;
#pragma unroll
    for (int i = 0; i < 4; i++) {
        float x = W[(size_t)(k + i) * DM + n];
        __nv_bfloat16 hb = __float2bfloat16(x);
        g_Wth[which][(size_t)n * DM + k + i] = hb;
        g_Wtl[which][(size_t)n * DM + k + i] = __float2bfloat16(x - __bfloat162float(hb));
    }
}

// ---------------- activation split: fp32 -> bf16 hi/lo ----------------
__global__ __launch_bounds__(256) void split_act(const float* __restrict__ q,
                                                 const float* __restrict__ k,
                                                 const float* __restrict__ v)
{
    int which = blockIdx.y;
    const float* A = (which == 0) ? q : (which == 1) ? k : v;
    size_t i0 = ((size_t)blockIdx.x * 256 + threadIdx.x) * 8;
    float4 f0 = *(const float4*)(A + i0);
    float4 f1 = *(const float4*)(A + i0 + 4);
    float xs[8] = {f0.x, f0.y, f0.z, f0.w, f1.x, f1.y, f1.z, f1.w};
    __align__(16) __nv_bfloat16 h[8], l[8];
#pragma unroll
    for (int i = 0; i < 8; i++) {
        __nv_bfloat16 hb = __float2bfloat16(xs[i]);
        h[i] = hb;
        l[i] = __float2bfloat16(xs[i] - __bfloat162float(hb));
    }
    *(uint4*)&g_Ah[which][i0] = *(uint4*)h;
    *(uint4*)&g_Al[which][i0] = *(uint4*)l;
}

// ---------------- split-bf16 mma.sync GEMM: 256x128 tile, 512 threads ----------------
__global__ __launch_bounds__(512) void proj_mma(
    const float* __restrict__ bq, const float* __restrict__ bk,
    const float* __restrict__ bv)
{
    extern __shared__ char dsm[];
    int which = blockIdx.z;
    float* P = (which == 0) ? g_Q : (which == 1) ? g_K : g_V;
    const float* bias = (which == 0) ? bq : (which == 1) ? bk : bv;
    const __nv_bfloat16* Ah = g_Ah[which];
    const __nv_bfloat16* Al = g_Al[which];
    const __nv_bfloat16* Wh = g_Wth[which];
    const __nv_bfloat16* Wl = g_Wtl[which];

    uint32_t su = smem_u32(dsm);
    int tid = threadIdx.x;
    int lane = tid & 31, wid = tid >> 5;
    int wm = wid & 7, wn = wid >> 3;       // 8 m-groups x 2 n-groups
    int m0 = blockIdx.y * 256, n0 = blockIdx.x * 128;

    float* bias_s = (float*)(dsm + OFF_BIAS);
    if (tid < 128) bias_s[tid] = bias[n0 + tid];

    float acc[2][8][4];
#pragma unroll
    for (int a = 0; a < 2; a++)
#pragma unroll
        for (int b = 0; b < 8; b++)
#pragma unroll
            for (int c = 0; c < 4; c++) acc[a][b][c] = 0.f;

    auto load_stage = [&](int stage, int k0) {
        uint32_t sb = su + stage * STAGE_SZ;
#pragma unroll
        for (int t = 0; t < 4; t++) {        // A tiles: 2048 16B chunks
            int idx = tid + 512 * t;
            int r = idx >> 3, c = idx & 7;
            uint32_t sw = SWZ128((uint32_t)(r * 128 + c * 16));
            CP_ASYNC16(sb + T_AH + sw, Ah + (size_t)(m0 + r) * DM + k0 + c * 8);
            CP_ASYNC16(sb + T_AL + sw, Al + (size_t)(m0 + r) * DM + k0 + c * 8);
        }
#pragma unroll
        for (int t = 0; t < 2; t++) {        // W tiles: 1024 16B chunks
            int idx = tid + 512 * t;
            int r = idx >> 3, c = idx & 7;
            uint32_t sw = SWZ128((uint32_t)(r * 128 + c * 16));
            CP_ASYNC16(sb + T_WH + sw, Wh + (size_t)(n0 + r) * DM + k0 + c * 8);
            CP_ASYNC16(sb + T_WL + sw, Wl + (size_t)(n0 + r) * DM + k0 + c * 8);
        }
        CP_COMMIT();
    };

    load_stage(0, 0);

    int a_row = (lane & 15), a_k16 = (lane >> 4) << 4;
    int b_grp = lane >> 3;
    int b_row = ((b_grp >> 1) << 3) + (lane & 7);
    int b_k16 = (b_grp & 1) << 4;

    for (int chunk = 0; chunk < 8; chunk++) {
        if (chunk < 7) load_stage((chunk + 1) & 1, (chunk + 1) * 64);
        if (chunk < 7) { CP_WAIT(1); } else { CP_WAIT(0); }
        __syncthreads();

        uint32_t sb = su + (chunk & 1) * STAGE_SZ;
#pragma unroll
        for (int ks = 0; ks < 4; ks++) {
            uint32_t ah[2][4], al[2][4];
#pragma unroll
            for (int mf = 0; mf < 2; mf++) {
                int row = wm * 32 + mf * 16 + a_row;
                uint32_t off = SWZ128((uint32_t)(row * 128 + ks * 32 + a_k16));
                ldsm_x4(ah[mf], sb + T_AH + off);
                ldsm_x4(al[mf], sb + T_AL + off);
            }
#pragma unroll
            for (int half = 0; half < 2; half++) {
                uint32_t bh8[8], bl8[8];
#pragma unroll
                for (int g = 0; g < 2; g++) {
                    int row = wn * 64 + (half * 2 + g) * 16 + b_row;
                    uint32_t off = SWZ128((uint32_t)(row * 128 + ks * 32 + b_k16));
                    ldsm_x4(&bh8[g * 4], sb + T_WH + off);
                    ldsm_x4(&bl8[g * 4], sb + T_WL + off);
                }
#pragma unroll
                for (int mf = 0; mf < 2; mf++)
#pragma unroll
                    for (int nl = 0; nl < 4; nl++)
                        mma16816(acc[mf][half * 4 + nl], ah[mf], &bh8[nl * 2],
                                 acc[mf][half * 4 + nl]);
#pragma unroll
                for (int mf = 0; mf < 2; mf++)
#pragma unroll
                    for (int nl = 0; nl < 4; nl++)
                        mma16816(acc[mf][half * 4 + nl], ah[mf], &bl8[nl * 2],
                                 acc[mf][half * 4 + nl]);
#pragma unroll
                for (int mf = 0; mf < 2; mf++)
#pragma unroll
                    for (int nl = 0; nl < 4; nl++)
                        mma16816(acc[mf][half * 4 + nl], al[mf], &bh8[nl * 2],
                                 acc[mf][half * 4 + nl]);
            }
        }
        __syncthreads();
    }

    // epilogue: frags -> smem (256 x stride 132) -> coalesced scatter
    float* Cs = (float*)dsm;
#pragma unroll
    for (int mf = 0; mf < 2; mf++)
#pragma unroll
        for (int nf = 0; nf < 8; nf++) {
            int r = wm * 32 + mf * 16 + (lane >> 2);
            int col = wn * 64 + nf * 8 + (lane & 3) * 2;
            Cs[r * 132 + col]           = acc[mf][nf][0] + bias_s[col];
            Cs[r * 132 + col + 1]       = acc[mf][nf][1] + bias_s[col + 1];
            Cs[(r + 8) * 132 + col]     = acc[mf][nf][2] + bias_s[col];
            Cs[(r + 8) * 132 + col + 1] = acc[mf][nf][3] + bias_s[col + 1];
        }
    __syncthreads();

#pragma unroll
    for (int it = 0; it < 16; it++) {
        int idx = tid + it * 512;           // [0,8192) float4 slots
        int row = idx >> 5, c4 = idx & 31;
        int m = m0 + row;
        int b = m >> 12, l = m & (LL - 1);
        int n = n0 + c4 * 4;
        int h = n >> 6, d = n & 63;
        float4 v;
        v.x = Cs[row * 132 + c4 * 4 + 0];
        v.y = Cs[row * 132 + c4 * 4 + 1];
        v.z = Cs[row * 132 + c4 * 4 + 2];
        v.w = Cs[row * 132 + c4 * 4 + 3];
        *(float4*)&P[((size_t)(b * HH + h) * LL + l) * DD + d] = v;
    }
}

// ---------------- sampled scoring: one thread per query, s[45] in regs ----------------
__global__ __launch_bounds__(128) void score_kernel(const int* __restrict__ sidx)
{
    __shared__ __align__(16) float Ks[UU * DD];
    __shared__ __align__(16) float Qt[DD * 129];
    __shared__ int ssi[UU];
    int bh = blockIdx.x;
    int tid = threadIdx.x;
    if (tid < UU) ssi[tid] = sidx[tid];
    __syncthreads();
    for (int i = tid; i < UU * 16; i += 128) {
        int j = i >> 4, c4 = i & 15;
        *(float4*)&Ks[j * 64 + c4 * 4] =
            *(const float4*)&g_K[((size_t)bh * LL + ssi[j]) * DD + c4 * 4];
    }
    int l0 = blockIdx.y * 128;
#pragma unroll
    for (int it = 0; it < 16; it++) {
        int idx = tid + it * 128;
        int qi = idx >> 4, c4 = idx & 15;
        float4 v = *(const float4*)&g_Q[((size_t)bh * LL + l0 + qi) * DD + c4 * 4];
        Qt[(c4 * 4 + 0) * 129 + qi] = v.x;
        Qt[(c4 * 4 + 1) * 129 + qi] = v.y;
        Qt[(c4 * 4 + 2) * 129 + qi] = v.z;
        Qt[(c4 * 4 + 3) * 129 + qi] = v.w;
    }
    __syncthreads();

    float s[UU];
#pragma unroll
    for (int j = 0; j < UU; j++) s[j] = 0.f;

    int qi = tid;
    for (int c = 0; c < DD; c += 4) {
        float q0 = Qt[(c + 0) * 129 + qi];
        float q1 = Qt[(c + 1) * 129 + qi];
        float q2 = Qt[(c + 2) * 129 + qi];
        float q3 = Qt[(c + 3) * 129 + qi];
#pragma unroll
        for (int j = 0; j < UU; j++) {
            float4 k4 = *(const float4*)&Ks[j * 64 + c];
            s[j] += q0 * k4.x + q1 * k4.y + q2 * k4.z + q3 * k4.w;
        }
    }

    float mx = s[0], sm = s[0];
#pragma unroll
    for (int j = 1; j < UU; j++) {
        mx = fmaxf(mx, s[j]);
        sm += s[j];
    }
    g_M[(size_t)bh * LL + l0 + qi] = (mx - sm * (1.f / UU)) * SCALE;
}

// ---------------- top-45 selection per (b,h) ----------------
__global__ __launch_bounds__(256) void topk_kernel()
{
    __shared__ float vals[LL];
    __shared__ float rv[256];
    __shared__ int ri[256];
    int bh = blockIdx.x, tid = threadIdx.x;
    for (int i = tid; i < LL; i += 256) vals[i] = g_M[(size_t)bh * LL + i];
    __syncthreads();
    for (int it = 0; it < UU; it++) {
        float bv = -1e38f; int bi = 0x7fffffff;
        for (int i = tid; i < LL; i += 256) {
            float v = vals[i];
            if (v > bv) { bv = v; bi = i; }
        }
        rv[tid] = bv; ri[tid] = bi;
        __syncthreads();
        for (int s = 128; s > 0; s >>= 1) {
            if (tid < s) {
                float v2 = rv[tid + s]; int i2 = ri[tid + s];
                if (v2 > rv[tid] || (v2 == rv[tid] && i2 < ri[tid])) {
                    rv[tid] = v2; ri[tid] = i2;
                }
            }
            __syncthreads();
        }
        if (tid == 0) {
            g_top[bh * UU + it] = ri[0];
            vals[ri[0]] = -1e38f;
        }
        __syncthreads();
    }
}

// ---------------- mean(V) over L per (b,h,d) ----------------
__global__ __launch_bounds__(256) void meanv_kernel()
{
    __shared__ float red[4][64];
    int bh = blockIdx.x, tid = threadIdx.x;
    int d = tid & 63, part = tid >> 6;
    const float* base = g_V + ((size_t)bh * LL + part * (LL / 4)) * DD + d;
    float s0 = 0.f, s1 = 0.f, s2 = 0.f, s3 = 0.f;
    for (int i = 0; i < LL / 4; i += 4) {
        s0 += base[(size_t)(i + 0) * DD];
        s1 += base[(size_t)(i + 1) * DD];
        s2 += base[(size_t)(i + 2) * DD];
        s3 += base[(size_t)(i + 3) * DD];
    }
    red[part][d] = (s0 + s1) + (s2 + s3);
    __syncthreads();
    if (part == 0)
        g_meanV[bh * DD + d] =
            (red[0][d] + red[1][d] + red[2][d] + red[3][d]) * (1.f / LL);
}

// ---------------- base row per batch ----------------
__global__ __launch_bounds__(512) void base_kernel(const float* __restrict__ Wo,
                                                   const float* __restrict__ bo)
{
    int b = blockIdx.x, c = threadIdx.x;
    float acc = bo[c];
    const float* mv = g_meanV + b * DM;
    for (int k = 0; k < DM; k++) acc += mv[k] * Wo[(size_t)k * DM + c];
    g_base[b * DM + c] = acc;
}

// ---------------- flash attention for top-45 queries ----------------
__global__ __launch_bounds__(384) void att_kernel()
{
    __shared__ __align__(16) float Qs[UU * 64];
    __shared__ __align__(16) float Ks[64 * 68];
    __shared__ __align__(16) float Vs[64 * 64];
    int bh = blockIdx.x, ch = blockIdx.y;
    int tid = threadIdx.x;
    int q = tid >> 3, lane8 = tid & 7;
    int qe = (q < UU) ? q : (UU - 1);

    for (int i = tid; i < UU * 64; i += 384) {
        int qq = i >> 6, d = i & 63;
        int l = g_top[bh * UU + qq];
        Qs[i] = g_Q[((size_t)bh * LL + l) * DD + d];
    }
    __syncthreads();

    float4 q4[16];
#pragma unroll
    for (int dd = 0; dd < 16; dd++) q4[dd] = *(const float4*)(Qs + qe * 64 + dd * 4);

    float m = -1e30f, lsum = 0.f;
    float acc[8];
#pragma unroll
    for (int i = 0; i < 8; i++) acc[i] = 0.f;

    int key0 = ch * CHUNK;
    for (int t0 = 0; t0 < CHUNK; t0 += 64) {
        __syncthreads();
        for (int i = tid; i < 1024; i += 384) {
            int r = i >> 4, c4 = (i & 15) << 2;
            size_t gidx = ((size_t)bh * LL + key0 + t0 + r) * DD + c4;
            *(float4*)&Ks[r * 68 + c4] = *(const float4*)&g_K[gidx];
            *(float4*)&Vs[r * 64 + c4] = *(const float4*)&g_V[gidx];
        }
        __syncthreads();

        float s[8];
#pragma unroll
        for (int tt = 0; tt < 8; tt++) {
            int j = lane8 + 8 * tt;
            const float* kr = Ks + j * 68;
            float sv = 0.f;
#pragma unroll
            for (int dd = 0; dd < 16; dd++) {
                float4 kv = *(const float4*)(kr + dd * 4);
                sv += q4[dd].x * kv.x + q4[dd].y * kv.y +
                      q4[dd].z * kv.z + q4[dd].w * kv.w;
            }
            s[tt] = sv * SCALE;
        }
        float tmax = s[0];
#pragma unroll
        for (int tt = 1; tt < 8; tt++) tmax = fmaxf(tmax, s[tt]);
#pragma unroll
        for (int off = 4; off; off >>= 1)
            tmax = fmaxf(tmax, __shfl_xor_sync(0xffffffffu, tmax, off));
        float mnew = fmaxf(m, tmax);
        float alpha = __expf(m - mnew);
        lsum *= alpha;
#pragma unroll
        for (int i = 0; i < 8; i++) acc[i] *= alpha;
        float p[8];
#pragma unroll
        for (int tt = 0; tt < 8; tt++) {
            p[tt] = __expf(s[tt] - mnew);
            lsum += p[tt];
        }
        m = mnew;
#pragma unroll
        for (int j = 0; j < 64; j++) {
            float pj = __shfl_sync(0xffffffffu, p[j >> 3], j & 7, 8);
            const float* vr = Vs + j * 64 + lane8 * 8;
            float4 v0 = *(const float4*)vr;
            float4 v1 = *(const float4*)(vr + 4);
            acc[0] += pj * v0.x; acc[1] += pj * v0.y;
            acc[2] += pj * v0.z; acc[3] += pj * v0.w;
            acc[4] += pj * v1.x; acc[5] += pj * v1.y;
            acc[6] += pj * v1.z; acc[7] += pj * v1.w;
        }
    }
#pragma unroll
    for (int off = 4; off; off >>= 1)
        lsum += __shfl_xor_sync(0xffffffffu, lsum, off);

    if (q < UU) {
        int idx = (bh * NCH + ch) * UU + q;
        if (lane8 == 0) { g_pm[idx] = m; g_pl[idx] = lsum; }
        float* pa = g_pacc + (size_t)idx * DD + lane8 * 8;
#pragma unroll
        for (int i = 0; i < 8; i++) pa[i] = acc[i];
    }
}

// ---------------- merge split-L partials ----------------
__global__ __launch_bounds__(64) void combine_kernel()
{
    int r = blockIdx.x;
    int d = threadIdx.x;
    int bh = r / UU, q = r % UU;
    float M = -1e30f;
#pragma unroll
    for (int c = 0; c < NCH; c++)
        M = fmaxf(M, g_pm[(bh * NCH + c) * UU + q]);
    float Ltot = 0.f, acc = 0.f;
#pragma unroll
    for (int c = 0; c < NCH; c++) {
        int idx = (bh * NCH + c) * UU + q;
        float e = __expf(g_pm[idx] - M);
        Ltot += g_pl[idx] * e;
        acc  += e * g_pacc[(size_t)idx * DD + d];
    }
    g_attn[(size_t)(bh * UU + q) * DD + d] = acc / Ltot;
}

// ---------------- final output: 4 rows per block ----------------
__global__ __launch_bounds__(128) void final_kernel4(const float* __restrict__ Wo,
                                                     float* __restrict__ out)
{
    __shared__ int tops[HH * UU];
    __shared__ float delta[64];
    int b = blockIdx.y;
    int q0 = blockIdx.x * 4;
    int tid = threadIdx.x;
    int c0 = tid * 4;

    for (int i = tid; i < HH * UU; i += 128) tops[i] = g_top[b * HH * UU + i];
    __syncthreads();

    float4 bsv = *(const float4*)&g_base[b * DM + c0];
    float4 acc[4] = {bsv, bsv, bsv, bsv};

    for (int i = 0; i < HH * UU; i++) {
        int t = tops[i];
        int r = t - q0;
        if (r >= 0 && r < 4) {
            int h = i / UU, j = i % UU;
            if (tid < 64)
                delta[tid] = g_attn[((size_t)(b * HH + h) * UU + j) * DD + tid] -
                             g_meanV[(b * HH + h) * DD + tid];
            __syncthreads();
#pragma unroll 4
            for (int d = 0; d < 64; d++) {
                float dv = delta[d];
                float4 w = *(const float4*)&Wo[(size_t)(h * 64 + d) * DM + c0];
                acc[r].x += dv * w.x; acc[r].y += dv * w.y;
                acc[r].z += dv * w.z; acc[r].w += dv * w.w;
            }
            __syncthreads();
        }
    }
#pragma unroll
    for (int r = 0; r < 4; r++)
        *(float4*)&out[((size_t)b * LL + q0 + r) * DM + c0] = acc[r];
}

// ---------------- launcher ----------------
extern "C" void kernel_launch(void* const* d_in, const int* in_sizes, int n_in,
                              void* d_out, int out_size)
{
    const float* queries = (const float*)d_in[0];
    const float* keys    = (const float*)d_in[1];
    const float* values  = (const float*)d_in[2];
    const int*   sidx    = (const int*)d_in[3];
    const float* Wq = (const float*)d_in[4];
    const float* bq = (const float*)d_in[5];
    const float* Wk = (const float*)d_in[6];
    const float* bk = (const float*)d_in[7];
    const float* Wv = (const float*)d_in[8];
    const float* bv = (const float*)d_in[9];
    const float* Wo = (const float*)d_in[10];
    const float* bo = (const float*)d_in[11];
    float* out = (float*)d_out;

    static int smem_set = 0;
    if (!smem_set) {
        cudaFuncSetAttribute(proj_mma, cudaFuncAttributeMaxDynamicSharedMemorySize, DYN_SMEM);
        smem_set = 1;
    }

    prep_w<<<dim3(256, 3), 256>>>(Wq, Wk, Wv);
    split_act<<<dim3(BL * DM / (256 * 8), 3), 256>>>(queries, keys, values);

    proj_mma<<<dim3(DM / 128, BL / 256, 3), 512, DYN_SMEM>>>(bq, bk, bv);

    score_kernel<<<dim3(BB * HH, LL / 128), 128>>>(sidx);
    topk_kernel<<<BB * HH, 256>>>();
    meanv_kernel<<<BB * HH, 256>>>();
    base_kernel<<<BB, 512>>>(Wo, bo);
    att_kernel<<<dim3(BB * HH, NCH), 384>>>();
    combine_kernel<<<BB * HH * UU, 64>>>();
    final_kernel4<<<dim3(LL / 4, BB), 128>>>(Wo, out);
}

// round 10
// speedup vs baseline: 1.1529x; 1.0828x over previous
#include <cuda_runtime.h>
#include <cuda_bf16.h>
#include <cstdint>

#define BB 8
#define LL 4096
#define DM 512
#define HH 8
#define DD 64
#define UU 45
#define NCH 16
#define CHUNK (LL / NCH)
#define SCALE 0.125f
#define BL (BB * LL)

// ---------------- scratch ----------------
__device__ float g_Q[BB * HH * LL * DD];
__device__ float g_K[BB * HH * LL * DD];
__device__ float g_V[BB * HH * LL * DD];
__device__ float g_M[BB * HH * LL];
__device__ int   g_top[BB * HH * UU];
__device__ float g_meanV[BB * HH * DD];
__device__ float g_base[BB * DM];
__device__ float g_pm[BB * HH * NCH * UU];
__device__ float g_pl[BB * HH * NCH * UU];
__device__ float g_pacc[BB * HH * NCH * UU * DD];
__device__ float g_attn[BB * HH * UU * DD];
__device__ __align__(16) __nv_bfloat16 g_Wth[3][DM * DM];
__device__ __align__(16) __nv_bfloat16 g_Wtl[3][DM * DM];

// ================= PTX helpers =================
__device__ __forceinline__ uint32_t smem_u32(const void* p) {
    uint32_t a;
    asm("{ .reg .u64 t; cvta.to.shared.u64 t, %1; cvt.u32.u64 %0, t; }"
        : "=r"(a) : "l"(p));
    return a;
}
#define SWZ128(off)   ((off) ^ (((off) >> 3) & 0x70))

#define CP_ASYNC16(dst, src) \
    asm volatile("cp.async.cg.shared.global [%0], [%1], 16;" :: "r"(dst), "l"(src))
#define CP_COMMIT() asm volatile("cp.async.commit_group;" ::: "memory")
#define CP_WAIT(n)  asm volatile("cp.async.wait_group %0;" :: "n"(n) : "memory")

__device__ __forceinline__ void ldsm_x4(uint32_t* r, uint32_t addr) {
    asm volatile("ldmatrix.sync.aligned.m8n8.x4.shared.b16 {%0,%1,%2,%3}, [%4];"
        : "=r"(r[0]), "=r"(r[1]), "=r"(r[2]), "=r"(r[3]) : "r"(addr));
}
__device__ __forceinline__ void mma16816(float* d, const uint32_t* a,
                                         const uint32_t* b, const float* c) {
    asm volatile(
        "mma.sync.aligned.m16n8k16.row.col.f32.bf16.bf16.f32 "
        "{%0,%1,%2,%3},{%4,%5,%6,%7},{%8,%9},{%10,%11,%12,%13};"
        : "=f"(d[0]), "=f"(d[1]), "=f"(d[2]), "=f"(d[3])
        : "r"(a[0]), "r"(a[1]), "r"(a[2]), "r"(a[3]),
          "r"(b[0]), "r"(b[1]),
          "f"(c[0]), "f"(c[1]), "f"(c[2]), "f"(c[3]));
}

// round-4 stage layout: 4 tiles of 128x64 bf16 (16KB each), 2 stages
#define T_AH 0
#define T_AL 16384
#define T_WH 32768
#define T_WL 49152
#define STAGE_SZ 65536
#define OFF_BIAS 131072
#define DYN_SMEM (131072 + 1024)

// ---------------- W prep: transpose + split to bf16 hi/lo ----------------
__global__ __launch_bounds__(256) void prep_w(const float* __restrict__ Wq,
                                              const float* __restrict__ Wk,
                                              const float* __restrict__ Wv)
{
    int which = blockIdx.y;
    const float* W = (which == 0) ? Wq : (which == 1) ? Wk : Wv;
    int idx = (blockIdx.x * 256 + threadIdx.x) * 4;
    int n = idx >> 9, k = idx & 511;
#pragma unroll
    for (int i = 0; i < 4; i++) {
        float x = W[(size_t)(k + i) * DM + n];
        __nv_bfloat16 hb = __float2bfloat16(x);
        g_Wth[which][(size_t)n * DM + k + i] = hb;
        g_Wtl[which][(size_t)n * DM + k + i] = __float2bfloat16(x - __bfloat162float(hb));
    }
}

// ---------------- split-bf16 mma.sync GEMM with fused fp32->bf16 A split ----------------
__global__ __launch_bounds__(256) void proj_mma(
    const float* __restrict__ qin, const float* __restrict__ kin,
    const float* __restrict__ vin,
    const float* __restrict__ bq, const float* __restrict__ bk,
    const float* __restrict__ bv)
{
    extern __shared__ char dsm[];
    int which = blockIdx.z;
    float* P = (which == 0) ? g_Q : (which == 1) ? g_K : g_V;
    const float* bias = (which == 0) ? bq : (which == 1) ? bk : bv;
    const float* Afp = (which == 0) ? qin : (which == 1) ? kin : vin;
    const __nv_bfloat16* Wh = g_Wth[which];
    const __nv_bfloat16* Wl = g_Wtl[which];

    uint32_t su = smem_u32(dsm);
    int tid = threadIdx.x;
    int lane = tid & 31, wid = tid >> 5;
    int wm = wid & 3, wn = wid >> 2;
    int m0 = blockIdx.y * 128, n0 = blockIdx.x * 128;

    float* bias_s = (float*)(dsm + OFF_BIAS);
    if (tid < 128) bias_s[tid] = bias[n0 + tid];

    float acc[2][8][4];
#pragma unroll
    for (int a = 0; a < 2; a++)
#pragma unroll
        for (int b = 0; b < 8; b++)
#pragma unroll
            for (int c = 0; c < 4; c++) acc[a][b][c] = 0.f;

    // ---- A path: fp32 LDG -> regs -> convert -> STS (software pipelined) ----
    float4 areg[4][2];
    auto ldA = [&](int k0) {
#pragma unroll
        for (int t = 0; t < 4; t++) {
            int idx = tid + 256 * t;
            int r = idx >> 3, c = idx & 7;
            const float* src = Afp + (size_t)(m0 + r) * DM + k0 + c * 8;
            areg[t][0] = *(const float4*)src;
            areg[t][1] = *(const float4*)(src + 4);
        }
    };
    auto stsA = [&](int stage) {
#pragma unroll
        for (int t = 0; t < 4; t++) {
            int idx = tid + 256 * t;
            int r = idx >> 3, c = idx & 7;
            float xs[8] = {areg[t][0].x, areg[t][0].y, areg[t][0].z, areg[t][0].w,
                           areg[t][1].x, areg[t][1].y, areg[t][1].z, areg[t][1].w};
            __align__(16) __nv_bfloat16 h[8], l[8];
#pragma unroll
            for (int i = 0; i < 8; i++) {
                __nv_bfloat16 hb = __float2bfloat16(xs[i]);
                h[i] = hb;
                l[i] = __float2bfloat16(xs[i] - __bfloat162float(hb));
            }
            uint32_t sw = SWZ128((uint32_t)(r * 128 + c * 16));
            *(uint4*)(dsm + stage * STAGE_SZ + T_AH + sw) = *(uint4*)h;
            *(uint4*)(dsm + stage * STAGE_SZ + T_AL + sw) = *(uint4*)l;
        }
    };
    // ---- W path: cp.async as before ----
    auto cpW = [&](int stage, int k0) {
        uint32_t sb = su + stage * STAGE_SZ;
#pragma unroll
        for (int t = 0; t < 4; t++) {
            int idx = tid + 256 * t;
            int r = idx >> 3, c = idx & 7;
            uint32_t sw = SWZ128((uint32_t)(r * 128 + c * 16));
            CP_ASYNC16(sb + T_WH + sw, Wh + (size_t)(n0 + r) * DM + k0 + c * 8);
            CP_ASYNC16(sb + T_WL + sw, Wl + (size_t)(n0 + r) * DM + k0 + c * 8);
        }
        CP_COMMIT();
    };

    // prologue: A(0) loaded+stored, A(1) in regs, W(0) in flight
    ldA(0);
    cpW(0, 0);
    stsA(0);
    ldA(64);

    int a_row = (lane & 15), a_k16 = (lane >> 4) << 4;
    int b_grp = lane >> 3;
    int b_row = ((b_grp >> 1) << 3) + (lane & 7);
    int b_k16 = (b_grp & 1) << 4;

    for (int chunk = 0; chunk < 8; chunk++) {
        if (chunk < 7) cpW((chunk + 1) & 1, (chunk + 1) * 64);
        if (chunk < 7) { CP_WAIT(1); } else { CP_WAIT(0); }
        __syncthreads();

        // stage A for next chunk (regs already resident), prefetch chunk+2
        if (chunk < 7) stsA((chunk + 1) & 1);
        if (chunk < 6) ldA((chunk + 2) * 64);

        uint32_t sb = su + (chunk & 1) * STAGE_SZ;
#pragma unroll
        for (int ks = 0; ks < 4; ks++) {
            uint32_t ah[2][4], al[2][4], bh[16], bl[16];
#pragma unroll
            for (int mf = 0; mf < 2; mf++) {
                int row = wm * 32 + mf * 16 + a_row;
                uint32_t off = SWZ128((uint32_t)(row * 128 + ks * 32 + a_k16));
                ldsm_x4(ah[mf], sb + T_AH + off);
                ldsm_x4(al[mf], sb + T_AL + off);
            }
#pragma unroll
            for (int g2 = 0; g2 < 4; g2++) {
                int row = wn * 64 + g2 * 16 + b_row;
                uint32_t off = SWZ128((uint32_t)(row * 128 + ks * 32 + b_k16));
                ldsm_x4(&bh[g2 * 4], sb + T_WH + off);
                ldsm_x4(&bl[g2 * 4], sb + T_WL + off);
            }
#pragma unroll
            for (int mf = 0; mf < 2; mf++)
#pragma unroll
                for (int nf = 0; nf < 8; nf++)
                    mma16816(acc[mf][nf], ah[mf], &bh[nf * 2], acc[mf][nf]);
#pragma unroll
            for (int mf = 0; mf < 2; mf++)
#pragma unroll
                for (int nf = 0; nf < 8; nf++)
                    mma16816(acc[mf][nf], ah[mf], &bl[nf * 2], acc[mf][nf]);
#pragma unroll
            for (int mf = 0; mf < 2; mf++)
#pragma unroll
                for (int nf = 0; nf < 8; nf++)
                    mma16816(acc[mf][nf], al[mf], &bh[nf * 2], acc[mf][nf]);
        }
        __syncthreads();
    }

    float* Cs = (float*)dsm;
#pragma unroll
    for (int mf = 0; mf < 2; mf++)
#pragma unroll
        for (int nf = 0; nf < 8; nf++) {
            int r = wm * 32 + mf * 16 + (lane >> 2);
            int col = wn * 64 + nf * 8 + (lane & 3) * 2;
            Cs[r * 132 + col]           = acc[mf][nf][0] + bias_s[col];
            Cs[r * 132 + col + 1]       = acc[mf][nf][1] + bias_s[col + 1];
            Cs[(r + 8) * 132 + col]     = acc[mf][nf][2] + bias_s[col];
            Cs[(r + 8) * 132 + col + 1] = acc[mf][nf][3] + bias_s[col + 1];
        }
    __syncthreads();

#pragma unroll
    for (int it = 0; it < 16; it++) {
        int idx = tid + it * 256;
        int row = idx >> 5, c4 = idx & 31;
        int m = m0 + row;
        int b = m >> 12, l = m & (LL - 1);
        int n = n0 + c4 * 4;
        int h = n >> 6, d = n & 63;
        float4 v;
        v.x = Cs[row * 132 + c4 * 4 + 0];
        v.y = Cs[row * 132 + c4 * 4 + 1];
        v.z = Cs[row * 132 + c4 * 4 + 2];
        v.w = Cs[row * 132 + c4 * 4 + 3];
        *(float4*)&P[((size_t)(b * HH + h) * LL + l) * DD + d] = v;
    }
}

// ---------------- sampled scoring: one thread per query, s[45] in regs ----------------
__global__ __launch_bounds__(128) void score_kernel(const int* __restrict__ sidx)
{
    __shared__ __align__(16) float Ks[UU * DD];
    __shared__ __align__(16) float Qt[DD * 129];
    __shared__ int ssi[UU];
    int bh = blockIdx.x;
    int tid = threadIdx.x;
    if (tid < UU) ssi[tid] = sidx[tid];
    __syncthreads();
    for (int i = tid; i < UU * 16; i += 128) {
        int j = i >> 4, c4 = i & 15;
        *(float4*)&Ks[j * 64 + c4 * 4] =
            *(const float4*)&g_K[((size_t)bh * LL + ssi[j]) * DD + c4 * 4];
    }
    int l0 = blockIdx.y * 128;
#pragma unroll
    for (int it = 0; it < 16; it++) {
        int idx = tid + it * 128;
        int qi = idx >> 4, c4 = idx & 15;
        float4 v = *(const float4*)&g_Q[((size_t)bh * LL + l0 + qi) * DD + c4 * 4];
        Qt[(c4 * 4 + 0) * 129 + qi] = v.x;
        Qt[(c4 * 4 + 1) * 129 + qi] = v.y;
        Qt[(c4 * 4 + 2) * 129 + qi] = v.z;
        Qt[(c4 * 4 + 3) * 129 + qi] = v.w;
    }
    __syncthreads();

    float s[UU];
#pragma unroll
    for (int j = 0; j < UU; j++) s[j] = 0.f;

    int qi = tid;
    for (int c = 0; c < DD; c += 4) {
        float q0 = Qt[(c + 0) * 129 + qi];
        float q1 = Qt[(c + 1) * 129 + qi];
        float q2 = Qt[(c + 2) * 129 + qi];
        float q3 = Qt[(c + 3) * 129 + qi];
#pragma unroll
        for (int j = 0; j < UU; j++) {
            float4 k4 = *(const float4*)&Ks[j * 64 + c];
            s[j] += q0 * k4.x + q1 * k4.y + q2 * k4.z + q3 * k4.w;
        }
    }

    float mx = s[0], sm = s[0];
#pragma unroll
    for (int j = 1; j < UU; j++) {
        mx = fmaxf(mx, s[j]);
        sm += s[j];
    }
    g_M[(size_t)bh * LL + l0 + qi] = (mx - sm * (1.f / UU)) * SCALE;
}

// ---------------- top-45 selection per (b,h) ----------------
__global__ __launch_bounds__(256) void topk_kernel()
{
    __shared__ float vals[LL];
    __shared__ float rv[256];
    __shared__ int ri[256];
    int bh = blockIdx.x, tid = threadIdx.x;
    for (int i = tid; i < LL; i += 256) vals[i] = g_M[(size_t)bh * LL + i];
    __syncthreads();
    for (int it = 0; it < UU; it++) {
        float bv = -1e38f; int bi = 0x7fffffff;
        for (int i = tid; i < LL; i += 256) {
            float v = vals[i];
            if (v > bv) { bv = v; bi = i; }
        }
        rv[tid] = bv; ri[tid] = bi;
        __syncthreads();
        for (int s = 128; s > 0; s >>= 1) {
            if (tid < s) {
                float v2 = rv[tid + s]; int i2 = ri[tid + s];
                if (v2 > rv[tid] || (v2 == rv[tid] && i2 < ri[tid])) {
                    rv[tid] = v2; ri[tid] = i2;
                }
            }
            __syncthreads();
        }
        if (tid == 0) {
            g_top[bh * UU + it] = ri[0];
            vals[ri[0]] = -1e38f;
        }
        __syncthreads();
    }
}

// ---------------- mean(V) over L per (b,h,d) ----------------
__global__ __launch_bounds__(256) void meanv_kernel()
{
    __shared__ float red[4][64];
    int bh = blockIdx.x, tid = threadIdx.x;
    int d = tid & 63, part = tid >> 6;
    const float* base = g_V + ((size_t)bh * LL + part * (LL / 4)) * DD + d;
    float s0 = 0.f, s1 = 0.f, s2 = 0.f, s3 = 0.f;
    for (int i = 0; i < LL / 4; i += 4) {
        s0 += base[(size_t)(i + 0) * DD];
        s1 += base[(size_t)(i + 1) * DD];
        s2 += base[(size_t)(i + 2) * DD];
        s3 += base[(size_t)(i + 3) * DD];
    }
    red[part][d] = (s0 + s1) + (s2 + s3);
    __syncthreads();
    if (part == 0)
        g_meanV[bh * DD + d] =
            (red[0][d] + red[1][d] + red[2][d] + red[3][d]) * (1.f / LL);
}

// ---------------- base row per batch ----------------
__global__ __launch_bounds__(512) void base_kernel(const float* __restrict__ Wo,
                                                   const float* __restrict__ bo)
{
    int b = blockIdx.x, c = threadIdx.x;
    float acc = bo[c];
    const float* mv = g_meanV + b * DM;
    for (int k = 0; k < DM; k++) acc += mv[k] * Wo[(size_t)k * DM + c];
    g_base[b * DM + c] = acc;
}

// ---------------- flash attention for top-45 queries ----------------
__global__ __launch_bounds__(384) void att_kernel()
{
    __shared__ __align__(16) float Qs[UU * 64];
    __shared__ __align__(16) float Ks[64 * 68];
    __shared__ __align__(16) float Vs[64 * 64];
    int bh = blockIdx.x, ch = blockIdx.y;
    int tid = threadIdx.x;
    int q = tid >> 3, lane8 = tid & 7;
    int qe = (q < UU) ? q : (UU - 1);

    for (int i = tid; i < UU * 64; i += 384) {
        int qq = i >> 6, d = i & 63;
        int l = g_top[bh * UU + qq];
        Qs[i] = g_Q[((size_t)bh * LL + l) * DD + d];
    }
    __syncthreads();

    float4 q4[16];
#pragma unroll
    for (int dd = 0; dd < 16; dd++) q4[dd] = *(const float4*)(Qs + qe * 64 + dd * 4);

    float m = -1e30f, lsum = 0.f;
    float acc[8];
#pragma unroll
    for (int i = 0; i < 8; i++) acc[i] = 0.f;

    int key0 = ch * CHUNK;
    for (int t0 = 0; t0 < CHUNK; t0 += 64) {
        __syncthreads();
        for (int i = tid; i < 1024; i += 384) {
            int r = i >> 4, c4 = (i & 15) << 2;
            size_t gidx = ((size_t)bh * LL + key0 + t0 + r) * DD + c4;
            *(float4*)&Ks[r * 68 + c4] = *(const float4*)&g_K[gidx];
            *(float4*)&Vs[r * 64 + c4] = *(const float4*)&g_V[gidx];
        }
        __syncthreads();

        float s[8];
#pragma unroll
        for (int tt = 0; tt < 8; tt++) {
            int j = lane8 + 8 * tt;
            const float* kr = Ks + j * 68;
            float sv = 0.f;
#pragma unroll
            for (int dd = 0; dd < 16; dd++) {
                float4 kv = *(const float4*)(kr + dd * 4);
                sv += q4[dd].x * kv.x + q4[dd].y * kv.y +
                      q4[dd].z * kv.z + q4[dd].w * kv.w;
            }
            s[tt] = sv * SCALE;
        }
        float tmax = s[0];
#pragma unroll
        for (int tt = 1; tt < 8; tt++) tmax = fmaxf(tmax, s[tt]);
#pragma unroll
        for (int off = 4; off; off >>= 1)
            tmax = fmaxf(tmax, __shfl_xor_sync(0xffffffffu, tmax, off));
        float mnew = fmaxf(m, tmax);
        float alpha = __expf(m - mnew);
        lsum *= alpha;
#pragma unroll
        for (int i = 0; i < 8; i++) acc[i] *= alpha;
        float p[8];
#pragma unroll
        for (int tt = 0; tt < 8; tt++) {
            p[tt] = __expf(s[tt] - mnew);
            lsum += p[tt];
        }
        m = mnew;
#pragma unroll
        for (int j = 0; j < 64; j++) {
            float pj = __shfl_sync(0xffffffffu, p[j >> 3], j & 7, 8);
            const float* vr = Vs + j * 64 + lane8 * 8;
            float4 v0 = *(const float4*)vr;
            float4 v1 = *(const float4*)(vr + 4);
            acc[0] += pj * v0.x; acc[1] += pj * v0.y;
            acc[2] += pj * v0.z; acc[3] += pj * v0.w;
            acc[4] += pj * v1.x; acc[5] += pj * v1.y;
            acc[6] += pj * v1.z; acc[7] += pj * v1.w;
        }
    }
#pragma unroll
    for (int off = 4; off; off >>= 1)
        lsum += __shfl_xor_sync(0xffffffffu, lsum, off);

    if (q < UU) {
        int idx = (bh * NCH + ch) * UU + q;
        if (lane8 == 0) { g_pm[idx] = m; g_pl[idx] = lsum; }
        float* pa = g_pacc + (size_t)idx * DD + lane8 * 8;
#pragma unroll
        for (int i = 0; i < 8; i++) pa[i] = acc[i];
    }
}

// ---------------- merge split-L partials ----------------
__global__ __launch_bounds__(64) void combine_kernel()
{
    int r = blockIdx.x;
    int d = threadIdx.x;
    int bh = r / UU, q = r % UU;
    float M = -1e30f;
#pragma unroll
    for (int c = 0; c < NCH; c++)
        M = fmaxf(M, g_pm[(bh * NCH + c) * UU + q]);
    float Ltot = 0.f, acc = 0.f;
#pragma unroll
    for (int c = 0; c < NCH; c++) {
        int idx = (bh * NCH + c) * UU + q;
        float e = __expf(g_pm[idx] - M);
        Ltot += g_pl[idx] * e;
        acc  += e * g_pacc[(size_t)idx * DD + d];
    }
    g_attn[(size_t)(bh * UU + q) * DD + d] = acc / Ltot;
}

// ---------------- final output: broadcast base + rank-64 corrections ----------------
__global__ __launch_bounds__(128) void final_kernel(const float* __restrict__ Wo,
                                                    float* __restrict__ out)
{
    __shared__ int s_hits[HH];
    __shared__ float delta[64];
    int qrow = blockIdx.x, b = blockIdx.y;
    int tid = threadIdx.x;
    int c0 = tid * 4;

    if (tid < HH) s_hits[tid] = -1;
    __syncthreads();
    if (tid < UU) {
#pragma unroll
        for (int h = 0; h < HH; h++)
            if (g_top[(b * HH + h) * UU + tid] == qrow) s_hits[h] = tid;
    }
    __syncthreads();

    float4 acc = *(const float4*)&g_base[b * DM + c0];
    for (int h = 0; h < HH; h++) {
        int hit = s_hits[h];
        if (hit >= 0) {
            if (tid < 64)
                delta[tid] = g_attn[((size_t)(b * HH + h) * UU + hit) * DD + tid] -
                             g_meanV[(b * HH + h) * DD + tid];
            __syncthreads();
#pragma unroll 4
            for (int d = 0; d < 64; d++) {
                float dv = delta[d];
                float4 w = *(const float4*)&Wo[(size_t)(h * 64 + d) * DM + c0];
                acc.x += dv * w.x; acc.y += dv * w.y;
                acc.z += dv * w.z; acc.w += dv * w.w;
            }
            __syncthreads();
        }
    }
    *(float4*)&out[((size_t)b * LL + qrow) * DM + c0] = acc;
}

// ---------------- launcher ----------------
extern "C" void kernel_launch(void* const* d_in, const int* in_sizes, int n_in,
                              void* d_out, int out_size)
{
    const float* queries = (const float*)d_in[0];
    const float* keys    = (const float*)d_in[1];
    const float* values  = (const float*)d_in[2];
    const int*   sidx    = (const int*)d_in[3];
    const float* Wq = (const float*)d_in[4];
    const float* bq = (const float*)d_in[5];
    const float* Wk = (const float*)d_in[6];
    const float* bk = (const float*)d_in[7];
    const float* Wv = (const float*)d_in[8];
    const float* bv = (const float*)d_in[9];
    const float* Wo = (const float*)d_in[10];
    const float* bo = (const float*)d_in[11];
    float* out = (float*)d_out;

    static int smem_set = 0;
    if (!smem_set) {
        cudaFuncSetAttribute(proj_mma, cudaFuncAttributeMaxDynamicSharedMemorySize, DYN_SMEM);
        smem_set = 1;
    }

    prep_w<<<dim3(256, 3), 256>>>(Wq, Wk, Wv);

    proj_mma<<<dim3(DM / 128, BL / 128, 3), 256, DYN_SMEM>>>(
        queries, keys, values, bq, bk, bv);

    score_kernel<<<dim3(BB * HH, LL / 128), 128>>>(sidx);
    topk_kernel<<<BB * HH, 256>>>();
    meanv_kernel<<<BB * HH, 256>>>();
    base_kernel<<<BB, 512>>>(Wo, bo);
    att_kernel<<<dim3(BB * HH, NCH), 384>>>();
    combine_kernel<<<BB * HH * UU, 64>>>();
    final_kernel<<<dim3(LL, BB), 128>>>(Wo, out);
}

// round 11
// speedup vs baseline: 1.1812x; 1.0245x over previous
#include <cuda_runtime.h>
#include <cuda_bf16.h>
#include <cstdint>

#define BB 8
#define LL 4096
#define DM 512
#define HH 8
#define DD 64
#define UU 45
#define NCH 16
#define CHUNK (LL / NCH)
#define SCALE 0.125f
#define BL (BB * LL)

// ---------------- scratch ----------------
__device__ float g_Q[BB * HH * LL * DD];
__device__ float g_K[BB * HH * LL * DD];
__device__ float g_V[BB * HH * LL * DD];
__device__ float g_M[BB * HH * LL];
__device__ int   g_top[BB * HH * UU];
__device__ float g_meanV[BB * HH * DD];
__device__ float g_base[BB * DM];
__device__ float g_pm[BB * HH * NCH * UU];
__device__ float g_pl[BB * HH * NCH * UU];
__device__ float g_pacc[BB * HH * NCH * UU * DD];
__device__ float g_attn[BB * HH * UU * DD];
__device__ __align__(16) __nv_bfloat16 g_Wth[3][DM * DM];
__device__ __align__(16) __nv_bfloat16 g_Wtl[3][DM * DM];

// ================= PTX helpers =================
__device__ __forceinline__ uint32_t smem_u32(const void* p) {
    uint32_t a;
    asm("{ .reg .u64 t; cvta.to.shared.u64 t, %1; cvt.u32.u64 %0, t; }"
        : "=r"(a) : "l"(p));
    return a;
}
#define SWZ128(off)   ((off) ^ (((off) >> 3) & 0x70))

#define CP_ASYNC16(dst, src) \
    asm volatile("cp.async.cg.shared.global [%0], [%1], 16;" :: "r"(dst), "l"(src))
#define CP_COMMIT() asm volatile("cp.async.commit_group;" ::: "memory")
#define CP_WAIT(n)  asm volatile("cp.async.wait_group %0;" :: "n"(n) : "memory")

__device__ __forceinline__ void ldsm_x4(uint32_t* r, uint32_t addr) {
    asm volatile("ldmatrix.sync.aligned.m8n8.x4.shared.b16 {%0,%1,%2,%3}, [%4];"
        : "=r"(r[0]), "=r"(r[1]), "=r"(r[2]), "=r"(r[3]) : "r"(addr));
}
__device__ __forceinline__ void mma16816(float* d, const uint32_t* a,
                                         const uint32_t* b, const float* c) {
    asm volatile(
        "mma.sync.aligned.m16n8k16.row.col.f32.bf16.bf16.f32 "
        "{%0,%1,%2,%3},{%4,%5,%6,%7},{%8,%9},{%10,%11,%12,%13};"
        : "=f"(d[0]), "=f"(d[1]), "=f"(d[2]), "=f"(d[3])
        : "r"(a[0]), "r"(a[1]), "r"(a[2]), "r"(a[3]),
          "r"(b[0]), "r"(b[1]),
          "f"(c[0]), "f"(c[1]), "f"(c[2]), "f"(c[3]));
}

// round-4 stage layout: 4 tiles of 128x64 bf16 (16KB each), 2 stages
#define T_AH 0
#define T_AL 16384
#define T_WH 32768
#define T_WL 49152
#define STAGE_SZ 65536
#define OFF_BIAS 131072
#define DYN_SMEM (131072 + 1024)

// ---------------- W prep: transpose + split to bf16 hi/lo ----------------
__global__ __launch_bounds__(256) void prep_w(const float* __restrict__ Wq,
                                              const float* __restrict__ Wk,
                                              const float* __restrict__ Wv)
{
    int which = blockIdx.y;
    const float* W = (which == 0) ? Wq : (which == 1) ? Wk : Wv;
    int idx = (blockIdx.x * 256 + threadIdx.x) * 4;
    int n = idx >> 9, k = idx & 511;
#pragma unroll
    for (int i = 0; i < 4; i++) {
        float x = W[(size_t)(k + i) * DM + n];
        __nv_bfloat16 hb = __float2bfloat16(x);
        g_Wth[which][(size_t)n * DM + k + i] = hb;
        g_Wtl[which][(size_t)n * DM + k + i] = __float2bfloat16(x - __bfloat162float(hb));
    }
}

// ---------------- split-bf16 mma.sync GEMM with fused fp32->bf16 A split ----------------
__global__ __launch_bounds__(256) void proj_mma(
    const float* __restrict__ qin, const float* __restrict__ kin,
    const float* __restrict__ vin,
    const float* __restrict__ bq, const float* __restrict__ bk,
    const float* __restrict__ bv)
{
    extern __shared__ char dsm[];
    int which = blockIdx.z;
    float* P = (which == 0) ? g_Q : (which == 1) ? g_K : g_V;
    const float* bias = (which == 0) ? bq : (which == 1) ? bk : bv;
    const float* Afp = (which == 0) ? qin : (which == 1) ? kin : vin;
    const __nv_bfloat16* Wh = g_Wth[which];
    const __nv_bfloat16* Wl = g_Wtl[which];

    uint32_t su = smem_u32(dsm);
    int tid = threadIdx.x;
    int lane = tid & 31, wid = tid >> 5;
    int wm = wid & 3, wn = wid >> 2;
    int m0 = blockIdx.y * 128, n0 = blockIdx.x * 128;

    float* bias_s = (float*)(dsm + OFF_BIAS);
    if (tid < 128) bias_s[tid] = bias[n0 + tid];

    float acc[2][8][4];
#pragma unroll
    for (int a = 0; a < 2; a++)
#pragma unroll
        for (int b = 0; b < 8; b++)
#pragma unroll
            for (int c = 0; c < 4; c++) acc[a][b][c] = 0.f;

    float4 areg[4][2];
    auto ldA = [&](int k0) {
#pragma unroll
        for (int t = 0; t < 4; t++) {
            int idx = tid + 256 * t;
            int r = idx >> 3, c = idx & 7;
            const float* src = Afp + (size_t)(m0 + r) * DM + k0 + c * 8;
            areg[t][0] = *(const float4*)src;
            areg[t][1] = *(const float4*)(src + 4);
        }
    };
    auto stsA = [&](int stage) {
#pragma unroll
        for (int t = 0; t < 4; t++) {
            int idx = tid + 256 * t;
            int r = idx >> 3, c = idx & 7;
            float xs[8] = {areg[t][0].x, areg[t][0].y, areg[t][0].z, areg[t][0].w,
                           areg[t][1].x, areg[t][1].y, areg[t][1].z, areg[t][1].w};
            __align__(16) __nv_bfloat16 h[8], l[8];
#pragma unroll
            for (int i = 0; i < 8; i++) {
                __nv_bfloat16 hb = __float2bfloat16(xs[i]);
                h[i] = hb;
                l[i] = __float2bfloat16(xs[i] - __bfloat162float(hb));
            }
            uint32_t sw = SWZ128((uint32_t)(r * 128 + c * 16));
            *(uint4*)(dsm + stage * STAGE_SZ + T_AH + sw) = *(uint4*)h;
            *(uint4*)(dsm + stage * STAGE_SZ + T_AL + sw) = *(uint4*)l;
        }
    };
    auto cpW = [&](int stage, int k0) {
        uint32_t sb = su + stage * STAGE_SZ;
#pragma unroll
        for (int t = 0; t < 4; t++) {
            int idx = tid + 256 * t;
            int r = idx >> 3, c = idx & 7;
            uint32_t sw = SWZ128((uint32_t)(r * 128 + c * 16));
            CP_ASYNC16(sb + T_WH + sw, Wh + (size_t)(n0 + r) * DM + k0 + c * 8);
            CP_ASYNC16(sb + T_WL + sw, Wl + (size_t)(n0 + r) * DM + k0 + c * 8);
        }
        CP_COMMIT();
    };

    ldA(0);
    cpW(0, 0);
    stsA(0);
    ldA(64);

    int a_row = (lane & 15), a_k16 = (lane >> 4) << 4;
    int b_grp = lane >> 3;
    int b_row = ((b_grp >> 1) << 3) + (lane & 7);
    int b_k16 = (b_grp & 1) << 4;

    for (int chunk = 0; chunk < 8; chunk++) {
        if (chunk < 7) cpW((chunk + 1) & 1, (chunk + 1) * 64);
        if (chunk < 7) { CP_WAIT(1); } else { CP_WAIT(0); }
        __syncthreads();

        if (chunk < 7) stsA((chunk + 1) & 1);
        if (chunk < 6) ldA((chunk + 2) * 64);

        uint32_t sb = su + (chunk & 1) * STAGE_SZ;
#pragma unroll
        for (int ks = 0; ks < 4; ks++) {
            uint32_t ah[2][4], al[2][4], bh[16], bl[16];
#pragma unroll
            for (int mf = 0; mf < 2; mf++) {
                int row = wm * 32 + mf * 16 + a_row;
                uint32_t off = SWZ128((uint32_t)(row * 128 + ks * 32 + a_k16));
                ldsm_x4(ah[mf], sb + T_AH + off);
                ldsm_x4(al[mf], sb + T_AL + off);
            }
#pragma unroll
            for (int g2 = 0; g2 < 4; g2++) {
                int row = wn * 64 + g2 * 16 + b_row;
                uint32_t off = SWZ128((uint32_t)(row * 128 + ks * 32 + b_k16));
                ldsm_x4(&bh[g2 * 4], sb + T_WH + off);
                ldsm_x4(&bl[g2 * 4], sb + T_WL + off);
            }
#pragma unroll
            for (int mf = 0; mf < 2; mf++)
#pragma unroll
                for (int nf = 0; nf < 8; nf++)
                    mma16816(acc[mf][nf], ah[mf], &bh[nf * 2], acc[mf][nf]);
#pragma unroll
            for (int mf = 0; mf < 2; mf++)
#pragma unroll
                for (int nf = 0; nf < 8; nf++)
                    mma16816(acc[mf][nf], ah[mf], &bl[nf * 2], acc[mf][nf]);
#pragma unroll
            for (int mf = 0; mf < 2; mf++)
#pragma unroll
                for (int nf = 0; nf < 8; nf++)
                    mma16816(acc[mf][nf], al[mf], &bh[nf * 2], acc[mf][nf]);
        }
        __syncthreads();
    }

    float* Cs = (float*)dsm;
#pragma unroll
    for (int mf = 0; mf < 2; mf++)
#pragma unroll
        for (int nf = 0; nf < 8; nf++) {
            int r = wm * 32 + mf * 16 + (lane >> 2);
            int col = wn * 64 + nf * 8 + (lane & 3) * 2;
            Cs[r * 132 + col]           = acc[mf][nf][0] + bias_s[col];
            Cs[r * 132 + col + 1]       = acc[mf][nf][1] + bias_s[col + 1];
            Cs[(r + 8) * 132 + col]     = acc[mf][nf][2] + bias_s[col];
            Cs[(r + 8) * 132 + col + 1] = acc[mf][nf][3] + bias_s[col + 1];
        }
    __syncthreads();

#pragma unroll
    for (int it = 0; it < 16; it++) {
        int idx = tid + it * 256;
        int row = idx >> 5, c4 = idx & 31;
        int m = m0 + row;
        int b = m >> 12, l = m & (LL - 1);
        int n = n0 + c4 * 4;
        int h = n >> 6, d = n & 63;
        float4 v;
        v.x = Cs[row * 132 + c4 * 4 + 0];
        v.y = Cs[row * 132 + c4 * 4 + 1];
        v.z = Cs[row * 132 + c4 * 4 + 2];
        v.w = Cs[row * 132 + c4 * 4 + 3];
        *(float4*)&P[((size_t)(b * HH + h) * LL + l) * DD + d] = v;
    }
}

// ---------------- sampled scoring: one thread per query, s[45] in regs ----------------
__global__ __launch_bounds__(128) void score_kernel(const int* __restrict__ sidx)
{
    __shared__ __align__(16) float Ks[UU * DD];
    __shared__ __align__(16) float Qt[DD * 129];
    __shared__ int ssi[UU];
    int bh = blockIdx.x;
    int tid = threadIdx.x;
    if (tid < UU) ssi[tid] = sidx[tid];
    __syncthreads();
    for (int i = tid; i < UU * 16; i += 128) {
        int j = i >> 4, c4 = i & 15;
        *(float4*)&Ks[j * 64 + c4 * 4] =
            *(const float4*)&g_K[((size_t)bh * LL + ssi[j]) * DD + c4 * 4];
    }
    int l0 = blockIdx.y * 128;
#pragma unroll
    for (int it = 0; it < 16; it++) {
        int idx = tid + it * 128;
        int qi = idx >> 4, c4 = idx & 15;
        float4 v = *(const float4*)&g_Q[((size_t)bh * LL + l0 + qi) * DD + c4 * 4];
        Qt[(c4 * 4 + 0) * 129 + qi] = v.x;
        Qt[(c4 * 4 + 1) * 129 + qi] = v.y;
        Qt[(c4 * 4 + 2) * 129 + qi] = v.z;
        Qt[(c4 * 4 + 3) * 129 + qi] = v.w;
    }
    __syncthreads();

    float s[UU];
#pragma unroll
    for (int j = 0; j < UU; j++) s[j] = 0.f;

    int qi = tid;
    for (int c = 0; c < DD; c += 4) {
        float q0 = Qt[(c + 0) * 129 + qi];
        float q1 = Qt[(c + 1) * 129 + qi];
        float q2 = Qt[(c + 2) * 129 + qi];
        float q3 = Qt[(c + 3) * 129 + qi];
#pragma unroll
        for (int j = 0; j < UU; j++) {
            float4 k4 = *(const float4*)&Ks[j * 64 + c];
            s[j] += q0 * k4.x + q1 * k4.y + q2 * k4.z + q3 * k4.w;
        }
    }

    float mx = s[0], sm = s[0];
#pragma unroll
    for (int j = 1; j < UU; j++) {
        mx = fmaxf(mx, s[j]);
        sm += s[j];
    }
    g_M[(size_t)bh * LL + l0 + qi] = (mx - sm * (1.f / UU)) * SCALE;
}

// ---------------- top-45 via radix select (set semantics, lowest-index ties) ----------------
__global__ __launch_bounds__(256) void topk_kernel()
{
    __shared__ uint32_t uvals[LL];     // 16 KB
    __shared__ int hist[256];
    __shared__ int sel_byte, new_k;
    __shared__ int cnt_g, cnt_e;
    __shared__ int eq[256];
    int bh = blockIdx.x, tid = threadIdx.x;

    // monotonic fp32 -> u32 map (larger float => larger uint)
    for (int i = tid; i < LL; i += 256) {
        uint32_t u = __float_as_uint(g_M[(size_t)bh * LL + i]);
        uvals[i] = (u & 0x80000000u) ? ~u : (u | 0x80000000u);
    }

    uint32_t prefix = 0, mask = 0;
    int k = UU;                         // rank within prefix-matching elements
    for (int pass = 0; pass < 4; pass++) {
        int shift = 24 - pass * 8;
        hist[tid] = 0;
        __syncthreads();
        for (int i = tid; i < LL; i += 256) {
            uint32_t u = uvals[i];
            if ((u & mask) == prefix) atomicAdd(&hist[(u >> shift) & 255], 1);
        }
        __syncthreads();
        if (tid == 0) {
            int rem = k, b = 255;
            for (; b > 0; b--) {
                if (hist[b] >= rem) break;
                rem -= hist[b];
            }
            sel_byte = b;
            new_k = rem;
        }
        __syncthreads();
        prefix |= ((uint32_t)sel_byte << shift);
        mask |= (255u << shift);
        k = new_k;
        __syncthreads();
    }
    uint32_t T = prefix;                // exact value of 45th-largest
    // k = number of T-valued elements to include

    if (tid == 0) { cnt_g = 0; cnt_e = 0; }
    __syncthreads();
    for (int i = tid; i < LL; i += 256) {
        uint32_t u = uvals[i];
        if (u > T) {
            int p = atomicAdd(&cnt_g, 1);
            g_top[bh * UU + p] = i;
        } else if (u == T) {
            int p = atomicAdd(&cnt_e, 1);
            if (p < 256) eq[p] = i;
        }
    }
    __syncthreads();
    int ng = cnt_g;
    int need = UU - ng;                 // == k
    if (tid == 0 && need > 0) {
        if (cnt_e <= 256) {
            int ec = cnt_e;
            for (int s = 0; s < need; s++) {   // selection: smallest indices first
                int best = s;
                for (int j = s + 1; j < ec; j++)
                    if (eq[j] < eq[best]) best = j;
                int t = eq[s]; eq[s] = eq[best]; eq[best] = t;
                g_top[bh * UU + ng + s] = eq[s];
            }
        } else {                               // pathological mass-tie fallback
            int got = 0;
            for (int i = 0; i < LL && got < need; i++)
                if (uvals[i] == T) { g_top[bh * UU + ng + got] = i; got++; }
        }
    }
}

// ---------------- mean(V) over L per (b,h,d) ----------------
__global__ __launch_bounds__(256) void meanv_kernel()
{
    __shared__ float red[4][64];
    int bh = blockIdx.x, tid = threadIdx.x;
    int d = tid & 63, part = tid >> 6;
    const float* base = g_V + ((size_t)bh * LL + part * (LL / 4)) * DD + d;
    float s0 = 0.f, s1 = 0.f, s2 = 0.f, s3 = 0.f;
    for (int i = 0; i < LL / 4; i += 4) {
        s0 += base[(size_t)(i + 0) * DD];
        s1 += base[(size_t)(i + 1) * DD];
        s2 += base[(size_t)(i + 2) * DD];
        s3 += base[(size_t)(i + 3) * DD];
    }
    red[part][d] = (s0 + s1) + (s2 + s3);
    __syncthreads();
    if (part == 0)
        g_meanV[bh * DD + d] =
            (red[0][d] + red[1][d] + red[2][d] + red[3][d]) * (1.f / LL);
}

// ---------------- base row per batch ----------------
__global__ __launch_bounds__(512) void base_kernel(const float* __restrict__ Wo,
                                                   const float* __restrict__ bo)
{
    int b = blockIdx.x, c = threadIdx.x;
    float acc = bo[c];
    const float* mv = g_meanV + b * DM;
    for (int k = 0; k < DM; k++) acc += mv[k] * Wo[(size_t)k * DM + c];
    g_base[b * DM + c] = acc;
}

// ---------------- flash attention for top-45 queries ----------------
__global__ __launch_bounds__(384) void att_kernel()
{
    __shared__ __align__(16) float Qs[UU * 64];
    __shared__ __align__(16) float Ks[64 * 68];
    __shared__ __align__(16) float Vs[64 * 64];
    int bh = blockIdx.x, ch = blockIdx.y;
    int tid = threadIdx.x;
    int q = tid >> 3, lane8 = tid & 7;
    int qe = (q < UU) ? q : (UU - 1);

    for (int i = tid; i < UU * 64; i += 384) {
        int qq = i >> 6, d = i & 63;
        int l = g_top[bh * UU + qq];
        Qs[i] = g_Q[((size_t)bh * LL + l) * DD + d];
    }
    __syncthreads();

    float4 q4[16];
#pragma unroll
    for (int dd = 0; dd < 16; dd++) q4[dd] = *(const float4*)(Qs + qe * 64 + dd * 4);

    float m = -1e30f, lsum = 0.f;
    float acc[8];
#pragma unroll
    for (int i = 0; i < 8; i++) acc[i] = 0.f;

    int key0 = ch * CHUNK;
    for (int t0 = 0; t0 < CHUNK; t0 += 64) {
        __syncthreads();
        for (int i = tid; i < 1024; i += 384) {
            int r = i >> 4, c4 = (i & 15) << 2;
            size_t gidx = ((size_t)bh * LL + key0 + t0 + r) * DD + c4;
            *(float4*)&Ks[r * 68 + c4] = *(const float4*)&g_K[gidx];
            *(float4*)&Vs[r * 64 + c4] = *(const float4*)&g_V[gidx];
        }
        __syncthreads();

        float s[8];
#pragma unroll
        for (int tt = 0; tt < 8; tt++) {
            int j = lane8 + 8 * tt;
            const float* kr = Ks + j * 68;
            float sv = 0.f;
#pragma unroll
            for (int dd = 0; dd < 16; dd++) {
                float4 kv = *(const float4*)(kr + dd * 4);
                sv += q4[dd].x * kv.x + q4[dd].y * kv.y +
                      q4[dd].z * kv.z + q4[dd].w * kv.w;
            }
            s[tt] = sv * SCALE;
        }
        float tmax = s[0];
#pragma unroll
        for (int tt = 1; tt < 8; tt++) tmax = fmaxf(tmax, s[tt]);
#pragma unroll
        for (int off = 4; off; off >>= 1)
            tmax = fmaxf(tmax, __shfl_xor_sync(0xffffffffu, tmax, off));
        float mnew = fmaxf(m, tmax);
        float alpha = __expf(m - mnew);
        lsum *= alpha;
#pragma unroll
        for (int i = 0; i < 8; i++) acc[i] *= alpha;
        float p[8];
#pragma unroll
        for (int tt = 0; tt < 8; tt++) {
            p[tt] = __expf(s[tt] - mnew);
            lsum += p[tt];
        }
        m = mnew;
#pragma unroll
        for (int j = 0; j < 64; j++) {
            float pj = __shfl_sync(0xffffffffu, p[j >> 3], j & 7, 8);
            const float* vr = Vs + j * 64 + lane8 * 8;
            float4 v0 = *(const float4*)vr;
            float4 v1 = *(const float4*)(vr + 4);
            acc[0] += pj * v0.x; acc[1] += pj * v0.y;
            acc[2] += pj * v0.z; acc[3] += pj * v0.w;
            acc[4] += pj * v1.x; acc[5] += pj * v1.y;
            acc[6] += pj * v1.z; acc[7] += pj * v1.w;
        }
    }
#pragma unroll
    for (int off = 4; off; off >>= 1)
        lsum += __shfl_xor_sync(0xffffffffu, lsum, off);

    if (q < UU) {
        int idx = (bh * NCH + ch) * UU + q;
        if (lane8 == 0) { g_pm[idx] = m; g_pl[idx] = lsum; }
        float* pa = g_pacc + (size_t)idx * DD + lane8 * 8;
#pragma unroll
        for (int i = 0; i < 8; i++) pa[i] = acc[i];
    }
}

// ---------------- merge split-L partials ----------------
__global__ __launch_bounds__(64) void combine_kernel()
{
    int r = blockIdx.x;
    int d = threadIdx.x;
    int bh = r / UU, q = r % UU;
    float M = -1e30f;
#pragma unroll
    for (int c = 0; c < NCH; c++)
        M = fmaxf(M, g_pm[(bh * NCH + c) * UU + q]);
    float Ltot = 0.f, acc = 0.f;
#pragma unroll
    for (int c = 0; c < NCH; c++) {
        int idx = (bh * NCH + c) * UU + q;
        float e = __expf(g_pm[idx] - M);
        Ltot += g_pl[idx] * e;
        acc  += e * g_pacc[(size_t)idx * DD + d];
    }
    g_attn[(size_t)(bh * UU + q) * DD + d] = acc / Ltot;
}

// ---------------- final output: broadcast base + rank-64 corrections ----------------
__global__ __launch_bounds__(128) void final_kernel(const float* __restrict__ Wo,
                                                    float* __restrict__ out)
{
    __shared__ int s_hits[HH];
    __shared__ float delta[64];
    int qrow = blockIdx.x, b = blockIdx.y;
    int tid = threadIdx.x;
    int c0 = tid * 4;

    if (tid < HH) s_hits[tid] = -1;
    __syncthreads();
    if (tid < UU) {
#pragma unroll
        for (int h = 0; h < HH; h++)
            if (g_top[(b * HH + h) * UU + tid] == qrow) s_hits[h] = tid;
    }
    __syncthreads();

    float4 acc = *(const float4*)&g_base[b * DM + c0];
    for (int h = 0; h < HH; h++) {
        int hit = s_hits[h];
        if (hit >= 0) {
            if (tid < 64)
                delta[tid] = g_attn[((size_t)(b * HH + h) * UU + hit) * DD + tid] -
                             g_meanV[(b * HH + h) * DD + tid];
            __syncthreads();
#pragma unroll 4
            for (int d = 0; d < 64; d++) {
                float dv = delta[d];
                float4 w = *(const float4*)&Wo[(size_t)(h * 64 + d) * DM + c0];
                acc.x += dv * w.x; acc.y += dv * w.y;
                acc.z += dv * w.z; acc.w += dv * w.w;
            }
            __syncthreads();
        }
    }
    *(float4*)&out[((size_t)b * LL + qrow) * DM + c0] = acc;
}

// ---------------- launcher ----------------
extern "C" void kernel_launch(void* const* d_in, const int* in_sizes, int n_in,
                              void* d_out, int out_size)
{
    const float* queries = (const float*)d_in[0];
    const float* keys    = (const float*)d_in[1];
    const float* values  = (const float*)d_in[2];
    const int*   sidx    = (const int*)d_in[3];
    const float* Wq = (const float*)d_in[4];
    const float* bq = (const float*)d_in[5];
    const float* Wk = (const float*)d_in[6];
    const float* bk = (const float*)d_in[7];
    const float* Wv = (const float*)d_in[8];
    const float* bv = (const float*)d_in[9];
    const float* Wo = (const float*)d_in[10];
    const float* bo = (const float*)d_in[11];
    float* out = (float*)d_out;

    static int smem_set = 0;
    if (!smem_set) {
        cudaFuncSetAttribute(proj_mma, cudaFuncAttributeMaxDynamicSharedMemorySize, DYN_SMEM);
        smem_set = 1;
    }

    prep_w<<<dim3(256, 3), 256>>>(Wq, Wk, Wv);

    proj_mma<<<dim3(DM / 128, BL / 128, 3), 256, DYN_SMEM>>>(
        queries, keys, values, bq, bk, bv);

    score_kernel<<<dim3(BB * HH, LL / 128), 128>>>(sidx);
    topk_kernel<<<BB * HH, 256>>>();
    meanv_kernel<<<BB * HH, 256>>>();
    base_kernel<<<BB, 512>>>(Wo, bo);
    att_kernel<<<dim3(BB * HH, NCH), 384>>>();
    combine_kernel<<<BB * HH * UU, 64>>>();
    final_kernel<<<dim3(LL, BB), 128>>>(Wo, out);
}

// round 12
// speedup vs baseline: 1.2175x; 1.0307x over previous
#include <cuda_runtime.h>
#include <cuda_bf16.h>
#include <cstdint>

#define BB 8
#define LL 4096
#define DM 512
#define HH 8
#define DD 64
#define UU 45
#define NCH 16
#define CHUNK (LL / NCH)
#define SCALE 0.125f
#define BL (BB * LL)

// ---------------- scratch ----------------
__device__ float g_Q[BB * HH * LL * DD];
__device__ float g_K[BB * HH * LL * DD];
__device__ float g_V[BB * HH * LL * DD];
__device__ float g_M[BB * HH * LL];
__device__ int   g_top[BB * HH * UU];
__device__ float g_meanV[BB * HH * DD];
__device__ float g_mv4[4][BB * HH * DD];
__device__ float g_base[BB * DM];
__device__ float g_pm[BB * HH * NCH * UU];
__device__ float g_pl[BB * HH * NCH * UU];
__device__ float g_pacc[BB * HH * NCH * UU * DD];
__device__ float g_attn[BB * HH * UU * DD];
__device__ __align__(16) __nv_bfloat16 g_Wth[3][DM * DM];
__device__ __align__(16) __nv_bfloat16 g_Wtl[3][DM * DM];

// ================= PTX helpers =================
__device__ __forceinline__ uint32_t smem_u32(const void* p) {
    uint32_t a;
    asm("{ .reg .u64 t; cvta.to.shared.u64 t, %1; cvt.u32.u64 %0, t; }"
        : "=r"(a) : "l"(p));
    return a;
}
#define SWZ128(off)   ((off) ^ (((off) >> 3) & 0x70))

#define CP_ASYNC16(dst, src) \
    asm volatile("cp.async.cg.shared.global [%0], [%1], 16;" :: "r"(dst), "l"(src))
#define CP_COMMIT() asm volatile("cp.async.commit_group;" ::: "memory")
#define CP_WAIT(n)  asm volatile("cp.async.wait_group %0;" :: "n"(n) : "memory")

__device__ __forceinline__ void ldsm_x4(uint32_t* r, uint32_t addr) {
    asm volatile("ldmatrix.sync.aligned.m8n8.x4.shared.b16 {%0,%1,%2,%3}, [%4];"
        : "=r"(r[0]), "=r"(r[1]), "=r"(r[2]), "=r"(r[3]) : "r"(addr));
}
__device__ __forceinline__ void mma16816(float* d, const uint32_t* a,
                                         const uint32_t* b, const float* c) {
    asm volatile(
        "mma.sync.aligned.m16n8k16.row.col.f32.bf16.bf16.f32 "
        "{%0,%1,%2,%3},{%4,%5,%6,%7},{%8,%9},{%10,%11,%12,%13};"
        : "=f"(d[0]), "=f"(d[1]), "=f"(d[2]), "=f"(d[3])
        : "r"(a[0]), "r"(a[1]), "r"(a[2]), "r"(a[3]),
          "r"(b[0]), "r"(b[1]),
          "f"(c[0]), "f"(c[1]), "f"(c[2]), "f"(c[3]));
}

// round-4 stage layout: 4 tiles of 128x64 bf16 (16KB each), 2 stages
#define T_AH 0
#define T_AL 16384
#define T_WH 32768
#define T_WL 49152
#define STAGE_SZ 65536
#define OFF_BIAS 131072
#define DYN_SMEM (131072 + 1024)

// ---------------- W prep: transpose + split to bf16 hi/lo ----------------
__global__ __launch_bounds__(256) void prep_w(const float* __restrict__ Wq,
                                              const float* __restrict__ Wk,
                                              const float* __restrict__ Wv)
{
    int which = blockIdx.y;
    const float* W = (which == 0) ? Wq : (which == 1) ? Wk : Wv;
    int idx = (blockIdx.x * 256 + threadIdx.x) * 4;
    int n = idx >> 9, k = idx & 511;
#pragma unroll
    for (int i = 0; i < 4; i++) {
        float x = W[(size_t)(k + i) * DM + n];
        __nv_bfloat16 hb = __float2bfloat16(x);
        g_Wth[which][(size_t)n * DM + k + i] = hb;
        g_Wtl[which][(size_t)n * DM + k + i] = __float2bfloat16(x - __bfloat162float(hb));
    }
}

// ---------------- split-bf16 mma.sync GEMM with fused fp32->bf16 A split ----------------
__global__ __launch_bounds__(256) void proj_mma(
    const float* __restrict__ qin, const float* __restrict__ kin,
    const float* __restrict__ vin,
    const float* __restrict__ bq, const float* __restrict__ bk,
    const float* __restrict__ bv)
{
    extern __shared__ char dsm[];
    int which = blockIdx.z;
    float* P = (which == 0) ? g_Q : (which == 1) ? g_K : g_V;
    const float* bias = (which == 0) ? bq : (which == 1) ? bk : bv;
    const float* Afp = (which == 0) ? qin : (which == 1) ? kin : vin;
    const __nv_bfloat16* Wh = g_Wth[which];
    const __nv_bfloat16* Wl = g_Wtl[which];

    uint32_t su = smem_u32(dsm);
    int tid = threadIdx.x;
    int lane = tid & 31, wid = tid >> 5;
    int wm = wid & 3, wn = wid >> 2;
    int m0 = blockIdx.y * 128, n0 = blockIdx.x * 128;

    float* bias_s = (float*)(dsm + OFF_BIAS);
    if (tid < 128) bias_s[tid] = bias[n0 + tid];

    float acc[2][8][4];
#pragma unroll
    for (int a = 0; a < 2; a++)
#pragma unroll
        for (int b = 0; b < 8; b++)
#pragma unroll
            for (int c = 0; c < 4; c++) acc[a][b][c] = 0.f;

    float4 areg[4][2];
    auto ldA = [&](int k0) {
#pragma unroll
        for (int t = 0; t < 4; t++) {
            int idx = tid + 256 * t;
            int r = idx >> 3, c = idx & 7;
            const float* src = Afp + (size_t)(m0 + r) * DM + k0 + c * 8;
            areg[t][0] = *(const float4*)src;
            areg[t][1] = *(const float4*)(src + 4);
        }
    };
    auto stsA = [&](int stage) {
#pragma unroll
        for (int t = 0; t < 4; t++) {
            int idx = tid + 256 * t;
            int r = idx >> 3, c = idx & 7;
            float xs[8] = {areg[t][0].x, areg[t][0].y, areg[t][0].z, areg[t][0].w,
                           areg[t][1].x, areg[t][1].y, areg[t][1].z, areg[t][1].w};
            __align__(16) __nv_bfloat16 h[8], l[8];
#pragma unroll
            for (int i = 0; i < 8; i++) {
                __nv_bfloat16 hb = __float2bfloat16(xs[i]);
                h[i] = hb;
                l[i] = __float2bfloat16(xs[i] - __bfloat162float(hb));
            }
            uint32_t sw = SWZ128((uint32_t)(r * 128 + c * 16));
            *(uint4*)(dsm + stage * STAGE_SZ + T_AH + sw) = *(uint4*)h;
            *(uint4*)(dsm + stage * STAGE_SZ + T_AL + sw) = *(uint4*)l;
        }
    };
    auto cpW = [&](int stage, int k0) {
        uint32_t sb = su + stage * STAGE_SZ;
#pragma unroll
        for (int t = 0; t < 4; t++) {
            int idx = tid + 256 * t;
            int r = idx >> 3, c = idx & 7;
            uint32_t sw = SWZ128((uint32_t)(r * 128 + c * 16));
            CP_ASYNC16(sb + T_WH + sw, Wh + (size_t)(n0 + r) * DM + k0 + c * 8);
            CP_ASYNC16(sb + T_WL + sw, Wl + (size_t)(n0 + r) * DM + k0 + c * 8);
        }
        CP_COMMIT();
    };

    ldA(0);
    cpW(0, 0);
    stsA(0);
    ldA(64);

    int a_row = (lane & 15), a_k16 = (lane >> 4) << 4;
    int b_grp = lane >> 3;
    int b_row = ((b_grp >> 1) << 3) + (lane & 7);
    int b_k16 = (b_grp & 1) << 4;

    for (int chunk = 0; chunk < 8; chunk++) {
        if (chunk < 7) cpW((chunk + 1) & 1, (chunk + 1) * 64);
        if (chunk < 7) { CP_WAIT(1); } else { CP_WAIT(0); }
        __syncthreads();

        if (chunk < 7) stsA((chunk + 1) & 1);
        if (chunk < 6) ldA((chunk + 2) * 64);

        uint32_t sb = su + (chunk & 1) * STAGE_SZ;
#pragma unroll
        for (int ks = 0; ks < 4; ks++) {
            uint32_t ah[2][4], al[2][4], bh[16], bl[16];
#pragma unroll
            for (int mf = 0; mf < 2; mf++) {
                int row = wm * 32 + mf * 16 + a_row;
                uint32_t off = SWZ128((uint32_t)(row * 128 + ks * 32 + a_k16));
                ldsm_x4(ah[mf], sb + T_AH + off);
                ldsm_x4(al[mf], sb + T_AL + off);
            }
#pragma unroll
            for (int g2 = 0; g2 < 4; g2++) {
                int row = wn * 64 + g2 * 16 + b_row;
                uint32_t off = SWZ128((uint32_t)(row * 128 + ks * 32 + b_k16));
                ldsm_x4(&bh[g2 * 4], sb + T_WH + off);
                ldsm_x4(&bl[g2 * 4], sb + T_WL + off);
            }
#pragma unroll
            for (int mf = 0; mf < 2; mf++)
#pragma unroll
                for (int nf = 0; nf < 8; nf++)
                    mma16816(acc[mf][nf], ah[mf], &bh[nf * 2], acc[mf][nf]);
#pragma unroll
            for (int mf = 0; mf < 2; mf++)
#pragma unroll
                for (int nf = 0; nf < 8; nf++)
                    mma16816(acc[mf][nf], ah[mf], &bl[nf * 2], acc[mf][nf]);
#pragma unroll
            for (int mf = 0; mf < 2; mf++)
#pragma unroll
                for (int nf = 0; nf < 8; nf++)
                    mma16816(acc[mf][nf], al[mf], &bh[nf * 2], acc[mf][nf]);
        }
        __syncthreads();
    }

    float* Cs = (float*)dsm;
#pragma unroll
    for (int mf = 0; mf < 2; mf++)
#pragma unroll
        for (int nf = 0; nf < 8; nf++) {
            int r = wm * 32 + mf * 16 + (lane >> 2);
            int col = wn * 64 + nf * 8 + (lane & 3) * 2;
            Cs[r * 132 + col]           = acc[mf][nf][0] + bias_s[col];
            Cs[r * 132 + col + 1]       = acc[mf][nf][1] + bias_s[col + 1];
            Cs[(r + 8) * 132 + col]     = acc[mf][nf][2] + bias_s[col];
            Cs[(r + 8) * 132 + col + 1] = acc[mf][nf][3] + bias_s[col + 1];
        }
    __syncthreads();

#pragma unroll
    for (int it = 0; it < 16; it++) {
        int idx = tid + it * 256;
        int row = idx >> 5, c4 = idx & 31;
        int m = m0 + row;
        int b = m >> 12, l = m & (LL - 1);
        int n = n0 + c4 * 4;
        int h = n >> 6, d = n & 63;
        float4 v;
        v.x = Cs[row * 132 + c4 * 4 + 0];
        v.y = Cs[row * 132 + c4 * 4 + 1];
        v.z = Cs[row * 132 + c4 * 4 + 2];
        v.w = Cs[row * 132 + c4 * 4 + 3];
        *(float4*)&P[((size_t)(b * HH + h) * LL + l) * DD + d] = v;
    }
}

// ---------------- sampled scoring: one thread per query, s[45] in regs ----------------
__global__ __launch_bounds__(128) void score_kernel(const int* __restrict__ sidx)
{
    __shared__ __align__(16) float Ks[UU * DD];
    __shared__ __align__(16) float Qt[DD * 129];
    __shared__ int ssi[UU];
    int bh = blockIdx.x;
    int tid = threadIdx.x;
    if (tid < UU) ssi[tid] = sidx[tid];
    __syncthreads();
    for (int i = tid; i < UU * 16; i += 128) {
        int j = i >> 4, c4 = i & 15;
        *(float4*)&Ks[j * 64 + c4 * 4] =
            *(const float4*)&g_K[((size_t)bh * LL + ssi[j]) * DD + c4 * 4];
    }
    int l0 = blockIdx.y * 128;
#pragma unroll
    for (int it = 0; it < 16; it++) {
        int idx = tid + it * 128;
        int qi = idx >> 4, c4 = idx & 15;
        float4 v = *(const float4*)&g_Q[((size_t)bh * LL + l0 + qi) * DD + c4 * 4];
        Qt[(c4 * 4 + 0) * 129 + qi] = v.x;
        Qt[(c4 * 4 + 1) * 129 + qi] = v.y;
        Qt[(c4 * 4 + 2) * 129 + qi] = v.z;
        Qt[(c4 * 4 + 3) * 129 + qi] = v.w;
    }
    __syncthreads();

    float s[UU];
#pragma unroll
    for (int j = 0; j < UU; j++) s[j] = 0.f;

    int qi = tid;
    for (int c = 0; c < DD; c += 4) {
        float q0 = Qt[(c + 0) * 129 + qi];
        float q1 = Qt[(c + 1) * 129 + qi];
        float q2 = Qt[(c + 2) * 129 + qi];
        float q3 = Qt[(c + 3) * 129 + qi];
#pragma unroll
        for (int j = 0; j < UU; j++) {
            float4 k4 = *(const float4*)&Ks[j * 64 + c];
            s[j] += q0 * k4.x + q1 * k4.y + q2 * k4.z + q3 * k4.w;
        }
    }

    float mx = s[0], sm = s[0];
#pragma unroll
    for (int j = 1; j < UU; j++) {
        mx = fmaxf(mx, s[j]);
        sm += s[j];
    }
    g_M[(size_t)bh * LL + l0 + qi] = (mx - sm * (1.f / UU)) * SCALE;
}

// ---------------- top-45 via radix select (per-warp hists, parallel scan) ----------------
__global__ __launch_bounds__(256) void topk_kernel()
{
    __shared__ uint32_t uvals[LL];       // 16 KB
    __shared__ int histw[8][256];        // per-warp histograms, 8 KB
    __shared__ int cnt[256];
    __shared__ int scan[256];
    __shared__ int sel_byte, new_k;
    __shared__ int cnt_g, cnt_e;
    __shared__ int eq[256];
    int bh = blockIdx.x, tid = threadIdx.x;
    int w = tid >> 5;

    for (int i = tid; i < LL; i += 256) {
        uint32_t u = __float_as_uint(g_M[(size_t)bh * LL + i]);
        uvals[i] = (u & 0x80000000u) ? ~u : (u | 0x80000000u);
    }

    uint32_t prefix = 0, mask = 0;
    int k = UU;
    for (int pass = 0; pass < 4; pass++) {
        int shift = 24 - pass * 8;
#pragma unroll
        for (int ww = 0; ww < 8; ww++) histw[ww][tid] = 0;
        __syncthreads();
        for (int i = tid; i < LL; i += 256) {
            uint32_t u = uvals[i];
            if ((u & mask) == prefix)
                atomicAdd(&histw[w][(u >> shift) & 255], 1);
        }
        __syncthreads();
        int c = 0;
#pragma unroll
        for (int ww = 0; ww < 8; ww++) c += histw[ww][tid];
        cnt[tid] = c;
        scan[tid] = c;
        __syncthreads();
        // inclusive suffix scan: scan[t] = sum_{i>=t} cnt[i]
#pragma unroll
        for (int off = 1; off < 256; off <<= 1) {
            int v = (tid + off < 256) ? scan[tid + off] : 0;
            __syncthreads();
            scan[tid] += v;
            __syncthreads();
        }
        // select bucket b: scan[b] >= k and (b==255 or scan[b+1] < k)
        {
            int snext = (tid < 255) ? scan[tid + 1] : 0;
            if (scan[tid] >= k && snext < k) {
                sel_byte = tid;
                new_k = k - snext;
            }
        }
        __syncthreads();
        prefix |= ((uint32_t)sel_byte << shift);
        mask |= (255u << shift);
        k = new_k;
        __syncthreads();
    }
    uint32_t T = prefix;

    if (tid == 0) { cnt_g = 0; cnt_e = 0; }
    __syncthreads();
    for (int i = tid; i < LL; i += 256) {
        uint32_t u = uvals[i];
        if (u > T) {
            int p = atomicAdd(&cnt_g, 1);
            g_top[bh * UU + p] = i;
        } else if (u == T) {
            int p = atomicAdd(&cnt_e, 1);
            if (p < 256) eq[p] = i;
        }
    }
    __syncthreads();
    int ng = cnt_g;
    int need = UU - ng;
    if (tid == 0 && need > 0) {
        if (cnt_e <= 256) {
            int ec = cnt_e;
            for (int s = 0; s < need; s++) {
                int best = s;
                for (int j = s + 1; j < ec; j++)
                    if (eq[j] < eq[best]) best = j;
                int t = eq[s]; eq[s] = eq[best]; eq[best] = t;
                g_top[bh * UU + ng + s] = eq[s];
            }
        } else {
            int got = 0;
            for (int i = 0; i < LL && got < need; i++)
                if (uvals[i] == T) { g_top[bh * UU + ng + got] = i; got++; }
        }
    }
}

// ---------------- mean(V): 4-way split partials + reduce ----------------
__global__ __launch_bounds__(256) void meanv_part()
{
    __shared__ float red[4][64];
    int bh = blockIdx.x, part = blockIdx.y, tid = threadIdx.x;
    int d = tid & 63, sub = tid >> 6;
    const float* base =
        g_V + ((size_t)bh * LL + part * (LL / 4) + sub * (LL / 16)) * DD + d;
    float s0 = 0.f, s1 = 0.f, s2 = 0.f, s3 = 0.f;
    for (int i = 0; i < LL / 16; i += 4) {
        s0 += base[(size_t)(i + 0) * DD];
        s1 += base[(size_t)(i + 1) * DD];
        s2 += base[(size_t)(i + 2) * DD];
        s3 += base[(size_t)(i + 3) * DD];
    }
    red[sub][d] = (s0 + s1) + (s2 + s3);
    __syncthreads();
    if (sub == 0)
        g_mv4[part][bh * DD + d] =
            (red[0][d] + red[1][d]) + (red[2][d] + red[3][d]);
}

__global__ __launch_bounds__(64) void mv_reduce()
{
    int bh = blockIdx.x, d = threadIdx.x;
    g_meanV[bh * DD + d] =
        ((g_mv4[0][bh * DD + d] + g_mv4[1][bh * DD + d]) +
         (g_mv4[2][bh * DD + d] + g_mv4[3][bh * DD + d])) * (1.f / LL);
}

// ---------------- base row per batch ----------------
__global__ __launch_bounds__(512) void base_kernel(const float* __restrict__ Wo,
                                                   const float* __restrict__ bo)
{
    int b = blockIdx.x, c = threadIdx.x;
    float acc = bo[c];
    const float* mv = g_meanV + b * DM;
    for (int k = 0; k < DM; k++) acc += mv[k] * Wo[(size_t)k * DM + c];
    g_base[b * DM + c] = acc;
}

// ---------------- flash attention for top-45 queries ----------------
__global__ __launch_bounds__(384) void att_kernel()
{
    __shared__ __align__(16) float Qs[UU * 64];
    __shared__ __align__(16) float Ks[64 * 68];
    __shared__ __align__(16) float Vs[64 * 64];
    int bh = blockIdx.x, ch = blockIdx.y;
    int tid = threadIdx.x;
    int q = tid >> 3, lane8 = tid & 7;
    int qe = (q < UU) ? q : (UU - 1);

    for (int i = tid; i < UU * 64; i += 384) {
        int qq = i >> 6, d = i & 63;
        int l = g_top[bh * UU + qq];
        Qs[i] = g_Q[((size_t)bh * LL + l) * DD + d];
    }
    __syncthreads();

    float4 q4[16];
#pragma unroll
    for (int dd = 0; dd < 16; dd++) q4[dd] = *(const float4*)(Qs + qe * 64 + dd * 4);

    float m = -1e30f, lsum = 0.f;
    float acc[8];
#pragma unroll
    for (int i = 0; i < 8; i++) acc[i] = 0.f;

    int key0 = ch * CHUNK;
    for (int t0 = 0; t0 < CHUNK; t0 += 64) {
        __syncthreads();
        for (int i = tid; i < 1024; i += 384) {
            int r = i >> 4, c4 = (i & 15) << 2;
            size_t gidx = ((size_t)bh * LL + key0 + t0 + r) * DD + c4;
            *(float4*)&Ks[r * 68 + c4] = *(const float4*)&g_K[gidx];
            *(float4*)&Vs[r * 64 + c4] = *(const float4*)&g_V[gidx];
        }
        __syncthreads();

        float s[8];
#pragma unroll
        for (int tt = 0; tt < 8; tt++) {
            int j = lane8 + 8 * tt;
            const float* kr = Ks + j * 68;
            float sv = 0.f;
#pragma unroll
            for (int dd = 0; dd < 16; dd++) {
                float4 kv = *(const float4*)(kr + dd * 4);
                sv += q4[dd].x * kv.x + q4[dd].y * kv.y +
                      q4[dd].z * kv.z + q4[dd].w * kv.w;
            }
            s[tt] = sv * SCALE;
        }
        float tmax = s[0];
#pragma unroll
        for (int tt = 1; tt < 8; tt++) tmax = fmaxf(tmax, s[tt]);
#pragma unroll
        for (int off = 4; off; off >>= 1)
            tmax = fmaxf(tmax, __shfl_xor_sync(0xffffffffu, tmax, off));
        float mnew = fmaxf(m, tmax);
        float alpha = __expf(m - mnew);
        lsum *= alpha;
#pragma unroll
        for (int i = 0; i < 8; i++) acc[i] *= alpha;
        float p[8];
#pragma unroll
        for (int tt = 0; tt < 8; tt++) {
            p[tt] = __expf(s[tt] - mnew);
            lsum += p[tt];
        }
        m = mnew;
#pragma unroll
        for (int j = 0; j < 64; j++) {
            float pj = __shfl_sync(0xffffffffu, p[j >> 3], j & 7, 8);
            const float* vr = Vs + j * 64 + lane8 * 8;
            float4 v0 = *(const float4*)vr;
            float4 v1 = *(const float4*)(vr + 4);
            acc[0] += pj * v0.x; acc[1] += pj * v0.y;
            acc[2] += pj * v0.z; acc[3] += pj * v0.w;
            acc[4] += pj * v1.x; acc[5] += pj * v1.y;
            acc[6] += pj * v1.z; acc[7] += pj * v1.w;
        }
    }
#pragma unroll
    for (int off = 4; off; off >>= 1)
        lsum += __shfl_xor_sync(0xffffffffu, lsum, off);

    if (q < UU) {
        int idx = (bh * NCH + ch) * UU + q;
        if (lane8 == 0) { g_pm[idx] = m; g_pl[idx] = lsum; }
        float* pa = g_pacc + (size_t)idx * DD + lane8 * 8;
#pragma unroll
        for (int i = 0; i < 8; i++) pa[i] = acc[i];
    }
}

// ---------------- merge split-L partials ----------------
__global__ __launch_bounds__(64) void combine_kernel()
{
    int r = blockIdx.x;
    int d = threadIdx.x;
    int bh = r / UU, q = r % UU;
    float M = -1e30f;
#pragma unroll
    for (int c = 0; c < NCH; c++)
        M = fmaxf(M, g_pm[(bh * NCH + c) * UU + q]);
    float Ltot = 0.f, acc = 0.f;
#pragma unroll
    for (int c = 0; c < NCH; c++) {
        int idx = (bh * NCH + c) * UU + q;
        float e = __expf(g_pm[idx] - M);
        Ltot += g_pl[idx] * e;
        acc  += e * g_pacc[(size_t)idx * DD + d];
    }
    g_attn[(size_t)(bh * UU + q) * DD + d] = acc / Ltot;
}

// ---------------- final output: broadcast base + rank-64 corrections ----------------
__global__ __launch_bounds__(128) void final_kernel(const float* __restrict__ Wo,
                                                    float* __restrict__ out)
{
    __shared__ int s_hits[HH];
    __shared__ float delta[64];
    int qrow = blockIdx.x, b = blockIdx.y;
    int tid = threadIdx.x;
    int c0 = tid * 4;

    if (tid < HH) s_hits[tid] = -1;
    __syncthreads();
    if (tid < UU) {
#pragma unroll
        for (int h = 0; h < HH; h++)
            if (g_top[(b * HH + h) * UU + tid] == qrow) s_hits[h] = tid;
    }
    __syncthreads();

    float4 acc = *(const float4*)&g_base[b * DM + c0];
    for (int h = 0; h < HH; h++) {
        int hit = s_hits[h];
        if (hit >= 0) {
            if (tid < 64)
                delta[tid] = g_attn[((size_t)(b * HH + h) * UU + hit) * DD + tid] -
                             g_meanV[(b * HH + h) * DD + tid];
            __syncthreads();
#pragma unroll 4
            for (int d = 0; d < 64; d++) {
                float dv = delta[d];
                float4 w = *(const float4*)&Wo[(size_t)(h * 64 + d) * DM + c0];
                acc.x += dv * w.x; acc.y += dv * w.y;
                acc.z += dv * w.z; acc.w += dv * w.w;
            }
            __syncthreads();
        }
    }
    *(float4*)&out[((size_t)b * LL + qrow) * DM + c0] = acc;
}

// ---------------- launcher ----------------
extern "C" void kernel_launch(void* const* d_in, const int* in_sizes, int n_in,
                              void* d_out, int out_size)
{
    const float* queries = (const float*)d_in[0];
    const float* keys    = (const float*)d_in[1];
    const float* values  = (const float*)d_in[2];
    const int*   sidx    = (const int*)d_in[3];
    const float* Wq = (const float*)d_in[4];
    const float* bq = (const float*)d_in[5];
    const float* Wk = (const float*)d_in[6];
    const float* bk = (const float*)d_in[7];
    const float* Wv = (const float*)d_in[8];
    const float* bv = (const float*)d_in[9];
    const float* Wo = (const float*)d_in[10];
    const float* bo = (const float*)d_in[11];
    float* out = (float*)d_out;

    static int smem_set = 0;
    if (!smem_set) {
        cudaFuncSetAttribute(proj_mma, cudaFuncAttributeMaxDynamicSharedMemorySize, DYN_SMEM);
        smem_set = 1;
    }

    prep_w<<<dim3(256, 3), 256>>>(Wq, Wk, Wv);

    proj_mma<<<dim3(DM / 128, BL / 128, 3), 256, DYN_SMEM>>>(
        queries, keys, values, bq, bk, bv);

    meanv_part<<<dim3(BB * HH, 4), 256>>>();
    score_kernel<<<dim3(BB * HH, LL / 128), 128>>>(sidx);
    topk_kernel<<<BB * HH, 256>>>();
    mv_reduce<<<BB * HH, 64>>>();
    base_kernel<<<BB, 512>>>(Wo, bo);
    att_kernel<<<dim3(BB * HH, NCH), 384>>>();
    combine_kernel<<<BB * HH * UU, 64>>>();
    final_kernel<<<dim3(LL, BB), 128>>>(Wo, out);
}

// round 13
// speedup vs baseline: 1.2614x; 1.0361x over previous
#include <cuda_runtime.h>
#include <cuda_bf16.h>
#include <cstdint>

#define BB 8
#define LL 4096
#define DM 512
#define HH 8
#define DD 64
#define UU 45
#define NCH 16
#define CHUNK (LL / NCH)
#define SCALE 0.125f
#define BL (BB * LL)

// ---------------- scratch ----------------
__device__ float g_Q[BB * HH * LL * DD];
__device__ float g_K[BB * HH * LL * DD];
__device__ float g_V[BB * HH * LL * DD];
__device__ float g_M[BB * HH * LL];
__device__ int   g_top[BB * HH * UU];
__device__ float g_meanV[BB * HH * DD];
__device__ float g_mv4[4][BB * HH * DD];
__device__ float g_base[BB * DM];
__device__ float g_pm[BB * HH * NCH * UU];
__device__ float g_pl[BB * HH * NCH * UU];
__device__ float g_pacc[BB * HH * NCH * UU * DD];
__device__ float g_attn[BB * HH * UU * DD];
__device__ __align__(16) __nv_bfloat16 g_Wth[3][DM * DM];
__device__ __align__(16) __nv_bfloat16 g_Wtl[3][DM * DM];

// ================= PTX helpers =================
__device__ __forceinline__ uint32_t smem_u32(const void* p) {
    uint32_t a;
    asm("{ .reg .u64 t; cvta.to.shared.u64 t, %1; cvt.u32.u64 %0, t; }"
        : "=r"(a) : "l"(p));
    return a;
}
#define SWZ128(off)   ((off) ^ (((off) >> 3) & 0x70))

#define CP_ASYNC16(dst, src) \
    asm volatile("cp.async.cg.shared.global [%0], [%1], 16;" :: "r"(dst), "l"(src))
#define CP_COMMIT() asm volatile("cp.async.commit_group;" ::: "memory")
#define CP_WAIT(n)  asm volatile("cp.async.wait_group %0;" :: "n"(n) : "memory")

__device__ __forceinline__ void ldsm_x4(uint32_t* r, uint32_t addr) {
    asm volatile("ldmatrix.sync.aligned.m8n8.x4.shared.b16 {%0,%1,%2,%3}, [%4];"
        : "=r"(r[0]), "=r"(r[1]), "=r"(r[2]), "=r"(r[3]) : "r"(addr));
}
__device__ __forceinline__ void mma16816(float* d, const uint32_t* a,
                                         const uint32_t* b, const float* c) {
    asm volatile(
        "mma.sync.aligned.m16n8k16.row.col.f32.bf16.bf16.f32 "
        "{%0,%1,%2,%3},{%4,%5,%6,%7},{%8,%9},{%10,%11,%12,%13};"
        : "=f"(d[0]), "=f"(d[1]), "=f"(d[2]), "=f"(d[3])
        : "r"(a[0]), "r"(a[1]), "r"(a[2]), "r"(a[3]),
          "r"(b[0]), "r"(b[1]),
          "f"(c[0]), "f"(c[1]), "f"(c[2]), "f"(c[3]));
}

__device__ __forceinline__ void split8(const float* xs, __nv_bfloat16* h,
                                       __nv_bfloat16* l) {
#pragma unroll
    for (int i = 0; i < 8; i++) {
        __nv_bfloat16 hb = __float2bfloat16(xs[i]);
        h[i] = hb;
        l[i] = __float2bfloat16(xs[i] - __bfloat162float(hb));
    }
}

// round-4 stage layout: 4 tiles of 128x64 bf16 (16KB each), 2 stages
#define T_AH 0
#define T_AL 16384
#define T_WH 32768
#define T_WL 49152
#define STAGE_SZ 65536
#define OFF_BIAS 131072
#define DYN_SMEM (131072 + 1024)

// ---------------- W prep: transpose + split to bf16 hi/lo ----------------
__global__ __launch_bounds__(256) void prep_w(const float* __restrict__ Wq,
                                              const float* __restrict__ Wk,
                                              const float* __restrict__ Wv)
{
    int which = blockIdx.y;
    const float* W = (which == 0) ? Wq : (which == 1) ? Wk : Wv;
    int idx = (blockIdx.x * 256 + threadIdx.x) * 4;
    int n = idx >> 9, k = idx & 511;
#pragma unroll
    for (int i = 0; i < 4; i++) {
        float x = W[(size_t)(k + i) * DM + n];
        __nv_bfloat16 hb = __float2bfloat16(x);
        g_Wth[which][(size_t)n * DM + k + i] = hb;
        g_Wtl[which][(size_t)n * DM + k + i] = __float2bfloat16(x - __bfloat162float(hb));
    }
}

// ---------------- split-bf16 mma.sync GEMM with fused fp32->bf16 A split ----------------
__global__ __launch_bounds__(256) void proj_mma(
    const float* __restrict__ qin, const float* __restrict__ kin,
    const float* __restrict__ vin,
    const float* __restrict__ bq, const float* __restrict__ bk,
    const float* __restrict__ bv)
{
    extern __shared__ char dsm[];
    int which = blockIdx.z;
    float* P = (which == 0) ? g_Q : (which == 1) ? g_K : g_V;
    const float* bias = (which == 0) ? bq : (which == 1) ? bk : bv;
    const float* Afp = (which == 0) ? qin : (which == 1) ? kin : vin;
    const __nv_bfloat16* Wh = g_Wth[which];
    const __nv_bfloat16* Wl = g_Wtl[which];

    uint32_t su = smem_u32(dsm);
    int tid = threadIdx.x;
    int lane = tid & 31, wid = tid >> 5;
    int wm = wid & 3, wn = wid >> 2;
    int m0 = blockIdx.y * 128, n0 = blockIdx.x * 128;

    float* bias_s = (float*)(dsm + OFF_BIAS);
    if (tid < 128) bias_s[tid] = bias[n0 + tid];

    float acc[2][8][4];
#pragma unroll
    for (int a = 0; a < 2; a++)
#pragma unroll
        for (int b = 0; b < 8; b++)
#pragma unroll
            for (int c = 0; c < 4; c++) acc[a][b][c] = 0.f;

    float4 areg[4][2];
    auto ldA = [&](int k0) {
#pragma unroll
        for (int t = 0; t < 4; t++) {
            int idx = tid + 256 * t;
            int r = idx >> 3, c = idx & 7;
            const float* src = Afp + (size_t)(m0 + r) * DM + k0 + c * 8;
            areg[t][0] = *(const float4*)src;
            areg[t][1] = *(const float4*)(src + 4);
        }
    };
    auto stsA = [&](int stage) {
#pragma unroll
        for (int t = 0; t < 4; t++) {
            int idx = tid + 256 * t;
            int r = idx >> 3, c = idx & 7;
            float xs[8] = {areg[t][0].x, areg[t][0].y, areg[t][0].z, areg[t][0].w,
                           areg[t][1].x, areg[t][1].y, areg[t][1].z, areg[t][1].w};
            __align__(16) __nv_bfloat16 h[8], l[8];
            split8(xs, h, l);
            uint32_t sw = SWZ128((uint32_t)(r * 128 + c * 16));
            *(uint4*)(dsm + stage * STAGE_SZ + T_AH + sw) = *(uint4*)h;
            *(uint4*)(dsm + stage * STAGE_SZ + T_AL + sw) = *(uint4*)l;
        }
    };
    auto cpW = [&](int stage, int k0) {
        uint32_t sb = su + stage * STAGE_SZ;
#pragma unroll
        for (int t = 0; t < 4; t++) {
            int idx = tid + 256 * t;
            int r = idx >> 3, c = idx & 7;
            uint32_t sw = SWZ128((uint32_t)(r * 128 + c * 16));
            CP_ASYNC16(sb + T_WH + sw, Wh + (size_t)(n0 + r) * DM + k0 + c * 8);
            CP_ASYNC16(sb + T_WL + sw, Wl + (size_t)(n0 + r) * DM + k0 + c * 8);
        }
        CP_COMMIT();
    };

    ldA(0);
    cpW(0, 0);
    stsA(0);
    ldA(64);

    int a_row = (lane & 15), a_k16 = (lane >> 4) << 4;
    int b_grp = lane >> 3;
    int b_row = ((b_grp >> 1) << 3) + (lane & 7);
    int b_k16 = (b_grp & 1) << 4;

    for (int chunk = 0; chunk < 8; chunk++) {
        if (chunk < 7) cpW((chunk + 1) & 1, (chunk + 1) * 64);
        if (chunk < 7) { CP_WAIT(1); } else { CP_WAIT(0); }
        __syncthreads();

        if (chunk < 7) stsA((chunk + 1) & 1);
        if (chunk < 6) ldA((chunk + 2) * 64);

        uint32_t sb = su + (chunk & 1) * STAGE_SZ;
#pragma unroll
        for (int ks = 0; ks < 4; ks++) {
            uint32_t ah[2][4], al[2][4], bh[16], bl[16];
#pragma unroll
            for (int mf = 0; mf < 2; mf++) {
                int row = wm * 32 + mf * 16 + a_row;
                uint32_t off = SWZ128((uint32_t)(row * 128 + ks * 32 + a_k16));
                ldsm_x4(ah[mf], sb + T_AH + off);
                ldsm_x4(al[mf], sb + T_AL + off);
            }
#pragma unroll
            for (int g2 = 0; g2 < 4; g2++) {
                int row = wn * 64 + g2 * 16 + b_row;
                uint32_t off = SWZ128((uint32_t)(row * 128 + ks * 32 + b_k16));
                ldsm_x4(&bh[g2 * 4], sb + T_WH + off);
                ldsm_x4(&bl[g2 * 4], sb + T_WL + off);
            }
#pragma unroll
            for (int mf = 0; mf < 2; mf++)
#pragma unroll
                for (int nf = 0; nf < 8; nf++)
                    mma16816(acc[mf][nf], ah[mf], &bh[nf * 2], acc[mf][nf]);
#pragma unroll
            for (int mf = 0; mf < 2; mf++)
#pragma unroll
                for (int nf = 0; nf < 8; nf++)
                    mma16816(acc[mf][nf], ah[mf], &bl[nf * 2], acc[mf][nf]);
#pragma unroll
            for (int mf = 0; mf < 2; mf++)
#pragma unroll
                for (int nf = 0; nf < 8; nf++)
                    mma16816(acc[mf][nf], al[mf], &bh[nf * 2], acc[mf][nf]);
        }
        __syncthreads();
    }

    float* Cs = (float*)dsm;
#pragma unroll
    for (int mf = 0; mf < 2; mf++)
#pragma unroll
        for (int nf = 0; nf < 8; nf++) {
            int r = wm * 32 + mf * 16 + (lane >> 2);
            int col = wn * 64 + nf * 8 + (lane & 3) * 2;
            Cs[r * 132 + col]           = acc[mf][nf][0] + bias_s[col];
            Cs[r * 132 + col + 1]       = acc[mf][nf][1] + bias_s[col + 1];
            Cs[(r + 8) * 132 + col]     = acc[mf][nf][2] + bias_s[col];
            Cs[(r + 8) * 132 + col + 1] = acc[mf][nf][3] + bias_s[col + 1];
        }
    __syncthreads();

#pragma unroll
    for (int it = 0; it < 16; it++) {
        int idx = tid + it * 256;
        int row = idx >> 5, c4 = idx & 31;
        int m = m0 + row;
        int b = m >> 12, l = m & (LL - 1);
        int n = n0 + c4 * 4;
        int h = n >> 6, d = n & 63;
        float4 v;
        v.x = Cs[row * 132 + c4 * 4 + 0];
        v.y = Cs[row * 132 + c4 * 4 + 1];
        v.z = Cs[row * 132 + c4 * 4 + 2];
        v.w = Cs[row * 132 + c4 * 4 + 3];
        *(float4*)&P[((size_t)(b * HH + h) * LL + l) * DD + d] = v;
    }
}

// ---------------- sampled scoring via MMA: 128x48x64 per block ----------------
__global__ __launch_bounds__(128) void score_mma(const int* __restrict__ sidx)
{
    __shared__ __align__(16) char AH[16384];
    __shared__ __align__(16) char AL[16384];
    __shared__ __align__(16) char BHs[6144];
    __shared__ __align__(16) char BLs[6144];
    __shared__ int ssi[UU];
    int bh = blockIdx.x, m0 = blockIdx.y * 128;
    int tid = threadIdx.x, lane = tid & 31, wm = tid >> 5;

    if (tid < UU) ssi[tid] = sidx[tid];
    // zero B (covers pad rows 45..47)
    for (int i = tid; i < 6144 / 16; i += 128) {
        ((uint4*)BHs)[i] = make_uint4(0, 0, 0, 0);
        ((uint4*)BLs)[i] = make_uint4(0, 0, 0, 0);
    }
    __syncthreads();

    // K_sample -> split bf16, swizzled (45 rows x 64)
    for (int u = tid; u < UU * 8; u += 128) {
        int j = u >> 3, c = u & 7;
        const float* src = g_K + ((size_t)bh * LL + ssi[j]) * DD + c * 8;
        float4 f0 = *(const float4*)src, f1 = *(const float4*)(src + 4);
        float xs[8] = {f0.x, f0.y, f0.z, f0.w, f1.x, f1.y, f1.z, f1.w};
        __align__(16) __nv_bfloat16 h[8], l[8];
        split8(xs, h, l);
        uint32_t sw = SWZ128((uint32_t)(j * 128 + c * 16));
        *(uint4*)(BHs + sw) = *(uint4*)h;
        *(uint4*)(BLs + sw) = *(uint4*)l;
    }
    // Q tile -> split bf16, swizzled (128 rows x 64)
#pragma unroll
    for (int t = 0; t < 8; t++) {
        int idx = tid + 128 * t;
        int r = idx >> 3, c = idx & 7;
        const float* src = g_Q + ((size_t)bh * LL + m0 + r) * DD + c * 8;
        float4 f0 = *(const float4*)src, f1 = *(const float4*)(src + 4);
        float xs[8] = {f0.x, f0.y, f0.z, f0.w, f1.x, f1.y, f1.z, f1.w};
        __align__(16) __nv_bfloat16 h[8], l[8];
        split8(xs, h, l);
        uint32_t sw = SWZ128((uint32_t)(r * 128 + c * 16));
        *(uint4*)(AH + sw) = *(uint4*)h;
        *(uint4*)(AL + sw) = *(uint4*)l;
    }
    __syncthreads();

    float acc[2][6][4];
#pragma unroll
    for (int a = 0; a < 2; a++)
#pragma unroll
        for (int b = 0; b < 6; b++)
#pragma unroll
            for (int c = 0; c < 4; c++) acc[a][b][c] = 0.f;

    uint32_t suA_h = smem_u32(AH), suA_l = smem_u32(AL);
    uint32_t suB_h = smem_u32(BHs), suB_l = smem_u32(BLs);
    int a_row = (lane & 15), a_k16 = (lane >> 4) << 4;
    int b_grp = lane >> 3;
    int b_row = ((b_grp >> 1) << 3) + (lane & 7);
    int b_k16 = (b_grp & 1) << 4;

#pragma unroll
    for (int ks = 0; ks < 4; ks++) {
        uint32_t ah[2][4], al[2][4], bhf[12], blf[12];
#pragma unroll
        for (int mf = 0; mf < 2; mf++) {
            int row = wm * 32 + mf * 16 + a_row;
            uint32_t off = SWZ128((uint32_t)(row * 128 + ks * 32 + a_k16));
            ldsm_x4(ah[mf], suA_h + off);
            ldsm_x4(al[mf], suA_l + off);
        }
#pragma unroll
        for (int g2 = 0; g2 < 3; g2++) {
            int row = g2 * 16 + b_row;
            uint32_t off = SWZ128((uint32_t)(row * 128 + ks * 32 + b_k16));
            ldsm_x4(&bhf[g2 * 4], suB_h + off);
            ldsm_x4(&blf[g2 * 4], suB_l + off);
        }
#pragma unroll
        for (int mf = 0; mf < 2; mf++)
#pragma unroll
            for (int nf = 0; nf < 6; nf++)
                mma16816(acc[mf][nf], ah[mf], &bhf[nf * 2], acc[mf][nf]);
#pragma unroll
        for (int mf = 0; mf < 2; mf++)
#pragma unroll
            for (int nf = 0; nf < 6; nf++)
                mma16816(acc[mf][nf], ah[mf], &blf[nf * 2], acc[mf][nf]);
#pragma unroll
        for (int mf = 0; mf < 2; mf++)
#pragma unroll
            for (int nf = 0; nf < 6; nf++)
                mma16816(acc[mf][nf], al[mf], &bhf[nf * 2], acc[mf][nf]);
    }

    // epilogue: per-row max & mean over j<45, reduce across lane quads
    int cbase = (lane & 3) * 2;
#pragma unroll
    for (int mf = 0; mf < 2; mf++) {
        float mx0 = -1e30f, sm0 = 0.f, mx1 = -1e30f, sm1 = 0.f;
#pragma unroll
        for (int nf = 0; nf < 6; nf++) {
            int c0 = nf * 8 + cbase, c1 = c0 + 1;
            if (c0 < UU) { mx0 = fmaxf(mx0, acc[mf][nf][0]); sm0 += acc[mf][nf][0]; }
            if (c1 < UU) { mx0 = fmaxf(mx0, acc[mf][nf][1]); sm0 += acc[mf][nf][1]; }
            if (c0 < UU) { mx1 = fmaxf(mx1, acc[mf][nf][2]); sm1 += acc[mf][nf][2]; }
            if (c1 < UU) { mx1 = fmaxf(mx1, acc[mf][nf][3]); sm1 += acc[mf][nf][3]; }
        }
#pragma unroll
        for (int off = 1; off < 4; off <<= 1) {
            mx0 = fmaxf(mx0, __shfl_xor_sync(0xffffffffu, mx0, off));
            sm0 += __shfl_xor_sync(0xffffffffu, sm0, off);
            mx1 = fmaxf(mx1, __shfl_xor_sync(0xffffffffu, mx1, off));
            sm1 += __shfl_xor_sync(0xffffffffu, sm1, off);
        }
        if ((lane & 3) == 0) {
            int r = wm * 32 + mf * 16 + (lane >> 2);
            g_M[(size_t)bh * LL + m0 + r]     = (mx0 - sm0 * (1.f / UU)) * SCALE;
            g_M[(size_t)bh * LL + m0 + r + 8] = (mx1 - sm1 * (1.f / UU)) * SCALE;
        }
    }
}

// ---------------- top-45 via radix select (per-warp hists, parallel scan) ----------------
__global__ __launch_bounds__(256) void topk_kernel()
{
    __shared__ uint32_t uvals[LL];
    __shared__ int histw[8][256];
    __shared__ int scan[256];
    __shared__ int sel_byte, new_k;
    __shared__ int cnt_g, cnt_e;
    __shared__ int eq[256];
    int bh = blockIdx.x, tid = threadIdx.x;
    int w = tid >> 5;

    for (int i = tid; i < LL; i += 256) {
        uint32_t u = __float_as_uint(g_M[(size_t)bh * LL + i]);
        uvals[i] = (u & 0x80000000u) ? ~u : (u | 0x80000000u);
    }

    uint32_t prefix = 0, mask = 0;
    int k = UU;
    for (int pass = 0; pass < 4; pass++) {
        int shift = 24 - pass * 8;
#pragma unroll
        for (int ww = 0; ww < 8; ww++) histw[ww][tid] = 0;
        __syncthreads();
        for (int i = tid; i < LL; i += 256) {
            uint32_t u = uvals[i];
            if ((u & mask) == prefix)
                atomicAdd(&histw[w][(u >> shift) & 255], 1);
        }
        __syncthreads();
        int c = 0;
#pragma unroll
        for (int ww = 0; ww < 8; ww++) c += histw[ww][tid];
        scan[tid] = c;
        __syncthreads();
#pragma unroll
        for (int off = 1; off < 256; off <<= 1) {
            int v = (tid + off < 256) ? scan[tid + off] : 0;
            __syncthreads();
            scan[tid] += v;
            __syncthreads();
        }
        {
            int snext = (tid < 255) ? scan[tid + 1] : 0;
            if (scan[tid] >= k && snext < k) {
                sel_byte = tid;
                new_k = k - snext;
            }
        }
        __syncthreads();
        prefix |= ((uint32_t)sel_byte << shift);
        mask |= (255u << shift);
        k = new_k;
        __syncthreads();
    }
    uint32_t T = prefix;

    if (tid == 0) { cnt_g = 0; cnt_e = 0; }
    __syncthreads();
    for (int i = tid; i < LL; i += 256) {
        uint32_t u = uvals[i];
        if (u > T) {
            int p = atomicAdd(&cnt_g, 1);
            g_top[bh * UU + p] = i;
        } else if (u == T) {
            int p = atomicAdd(&cnt_e, 1);
            if (p < 256) eq[p] = i;
        }
    }
    __syncthreads();
    int ng = cnt_g;
    int need = UU - ng;
    if (tid == 0 && need > 0) {
        if (cnt_e <= 256) {
            int ec = cnt_e;
            for (int s = 0; s < need; s++) {
                int best = s;
                for (int j = s + 1; j < ec; j++)
                    if (eq[j] < eq[best]) best = j;
                int t = eq[s]; eq[s] = eq[best]; eq[best] = t;
                g_top[bh * UU + ng + s] = eq[s];
            }
        } else {
            int got = 0;
            for (int i = 0; i < LL && got < need; i++)
                if (uvals[i] == T) { g_top[bh * UU + ng + got] = i; got++; }
        }
    }
}

// ---------------- mean(V): 4-way split partials + reduce ----------------
__global__ __launch_bounds__(256) void meanv_part()
{
    __shared__ float red[4][64];
    int bh = blockIdx.x, part = blockIdx.y, tid = threadIdx.x;
    int d = tid & 63, sub = tid >> 6;
    const float* base =
        g_V + ((size_t)bh * LL + part * (LL / 4) + sub * (LL / 16)) * DD + d;
    float s0 = 0.f, s1 = 0.f, s2 = 0.f, s3 = 0.f;
    for (int i = 0; i < LL / 16; i += 4) {
        s0 += base[(size_t)(i + 0) * DD];
        s1 += base[(size_t)(i + 1) * DD];
        s2 += base[(size_t)(i + 2) * DD];
        s3 += base[(size_t)(i + 3) * DD];
    }
    red[sub][d] = (s0 + s1) + (s2 + s3);
    __syncthreads();
    if (sub == 0)
        g_mv4[part][bh * DD + d] =
            (red[0][d] + red[1][d]) + (red[2][d] + red[3][d]);
}

__global__ __launch_bounds__(64) void mv_reduce()
{
    int bh = blockIdx.x, d = threadIdx.x;
    g_meanV[bh * DD + d] =
        ((g_mv4[0][bh * DD + d] + g_mv4[1][bh * DD + d]) +
         (g_mv4[2][bh * DD + d] + g_mv4[3][bh * DD + d])) * (1.f / LL);
}

// ---------------- base row per batch ----------------
__global__ __launch_bounds__(512) void base_kernel(const float* __restrict__ Wo,
                                                   const float* __restrict__ bo)
{
    int b = blockIdx.x, c = threadIdx.x;
    float acc = bo[c];
    const float* mv = g_meanV + b * DM;
    for (int k = 0; k < DM; k++) acc += mv[k] * Wo[(size_t)k * DM + c];
    g_base[b * DM + c] = acc;
}

// ---------------- flash attention for top-45 queries ----------------
__global__ __launch_bounds__(384) void att_kernel()
{
    __shared__ __align__(16) float Qs[UU * 64];
    __shared__ __align__(16) float Ks[64 * 68];
    __shared__ __align__(16) float Vs[64 * 64];
    int bh = blockIdx.x, ch = blockIdx.y;
    int tid = threadIdx.x;
    int q = tid >> 3, lane8 = tid & 7;
    int qe = (q < UU) ? q : (UU - 1);

    for (int i = tid; i < UU * 64; i += 384) {
        int qq = i >> 6, d = i & 63;
        int l = g_top[bh * UU + qq];
        Qs[i] = g_Q[((size_t)bh * LL + l) * DD + d];
    }
    __syncthreads();

    float4 q4[16];
#pragma unroll
    for (int dd = 0; dd < 16; dd++) q4[dd] = *(const float4*)(Qs + qe * 64 + dd * 4);

    float m = -1e30f, lsum = 0.f;
    float acc[8];
#pragma unroll
    for (int i = 0; i < 8; i++) acc[i] = 0.f;

    int key0 = ch * CHUNK;
    for (int t0 = 0; t0 < CHUNK; t0 += 64) {
        __syncthreads();
        for (int i = tid; i < 1024; i += 384) {
            int r = i >> 4, c4 = (i & 15) << 2;
            size_t gidx = ((size_t)bh * LL + key0 + t0 + r) * DD + c4;
            *(float4*)&Ks[r * 68 + c4] = *(const float4*)&g_K[gidx];
            *(float4*)&Vs[r * 64 + c4] = *(const float4*)&g_V[gidx];
        }
        __syncthreads();

        float s[8];
#pragma unroll
        for (int tt = 0; tt < 8; tt++) {
            int j = lane8 + 8 * tt;
            const float* kr = Ks + j * 68;
            float sv = 0.f;
#pragma unroll
            for (int dd = 0; dd < 16; dd++) {
                float4 kv = *(const float4*)(kr + dd * 4);
                sv += q4[dd].x * kv.x + q4[dd].y * kv.y +
                      q4[dd].z * kv.z + q4[dd].w * kv.w;
            }
            s[tt] = sv * SCALE;
        }
        float tmax = s[0];
#pragma unroll
        for (int tt = 1; tt < 8; tt++) tmax = fmaxf(tmax, s[tt]);
#pragma unroll
        for (int off = 4; off; off >>= 1)
            tmax = fmaxf(tmax, __shfl_xor_sync(0xffffffffu, tmax, off));
        float mnew = fmaxf(m, tmax);
        float alpha = __expf(m - mnew);
        lsum *= alpha;
#pragma unroll
        for (int i = 0; i < 8; i++) acc[i] *= alpha;
        float p[8];
#pragma unroll
        for (int tt = 0; tt < 8; tt++) {
            p[tt] = __expf(s[tt] - mnew);
            lsum += p[tt];
        }
        m = mnew;
#pragma unroll
        for (int j = 0; j < 64; j++) {
            float pj = __shfl_sync(0xffffffffu, p[j >> 3], j & 7, 8);
            const float* vr = Vs + j * 64 + lane8 * 8;
            float4 v0 = *(const float4*)vr;
            float4 v1 = *(const float4*)(vr + 4);
            acc[0] += pj * v0.x; acc[1] += pj * v0.y;
            acc[2] += pj * v0.z; acc[3] += pj * v0.w;
            acc[4] += pj * v1.x; acc[5] += pj * v1.y;
            acc[6] += pj * v1.z; acc[7] += pj * v1.w;
        }
    }
#pragma unroll
    for (int off = 4; off; off >>= 1)
        lsum += __shfl_xor_sync(0xffffffffu, lsum, off);

    if (q < UU) {
        int idx = (bh * NCH + ch) * UU + q;
        if (lane8 == 0) { g_pm[idx] = m; g_pl[idx] = lsum; }
        float* pa = g_pacc + (size_t)idx * DD + lane8 * 8;
#pragma unroll
        for (int i = 0; i < 8; i++) pa[i] = acc[i];
    }
}

// ---------------- merge split-L partials ----------------
__global__ __launch_bounds__(64) void combine_kernel()
{
    int r = blockIdx.x;
    int d = threadIdx.x;
    int bh = r / UU, q = r % UU;
    float M = -1e30f;
#pragma unroll
    for (int c = 0; c < NCH; c++)
        M = fmaxf(M, g_pm[(bh * NCH + c) * UU + q]);
    float Ltot = 0.f, acc = 0.f;
#pragma unroll
    for (int c = 0; c < NCH; c++) {
        int idx = (bh * NCH + c) * UU + q;
        float e = __expf(g_pm[idx] - M);
        Ltot += g_pl[idx] * e;
        acc  += e * g_pacc[(size_t)idx * DD + d];
    }
    g_attn[(size_t)(bh * UU + q) * DD + d] = acc / Ltot;
}

// ---------------- final output: broadcast base + rank-64 corrections ----------------
__global__ __launch_bounds__(128) void final_kernel(const float* __restrict__ Wo,
                                                    float* __restrict__ out)
{
    __shared__ int s_hits[HH];
    __shared__ float delta[64];
    int qrow = blockIdx.x, b = blockIdx.y;
    int tid = threadIdx.x;
    int c0 = tid * 4;

    if (tid < HH) s_hits[tid] = -1;
    __syncthreads();
    if (tid < UU) {
#pragma unroll
        for (int h = 0; h < HH; h++)
            if (g_top[(b * HH + h) * UU + tid] == qrow) s_hits[h] = tid;
    }
    __syncthreads();

    float4 acc = *(const float4*)&g_base[b * DM + c0];
    for (int h = 0; h < HH; h++) {
        int hit = s_hits[h];
        if (hit >= 0) {
            if (tid < 64)
                delta[tid] = g_attn[((size_t)(b * HH + h) * UU + hit) * DD + tid] -
                             g_meanV[(b * HH + h) * DD + tid];
            __syncthreads();
#pragma unroll 4
            for (int d = 0; d < 64; d++) {
                float dv = delta[d];
                float4 w = *(const float4*)&Wo[(size_t)(h * 64 + d) * DM + c0];
                acc.x += dv * w.x; acc.y += dv * w.y;
                acc.z += dv * w.z; acc.w += dv * w.w;
            }
            __syncthreads();
        }
    }
    *(float4*)&out[((size_t)b * LL + qrow) * DM + c0] = acc;
}

// ---------------- launcher ----------------
extern "C" void kernel_launch(void* const* d_in, const int* in_sizes, int n_in,
                              void* d_out, int out_size)
{
    const float* queries = (const float*)d_in[0];
    const float* keys    = (const float*)d_in[1];
    const float* values  = (const float*)d_in[2];
    const int*   sidx    = (const int*)d_in[3];
    const float* Wq = (const float*)d_in[4];
    const float* bq = (const float*)d_in[5];
    const float* Wk = (const float*)d_in[6];
    const float* bk = (const float*)d_in[7];
    const float* Wv = (const float*)d_in[8];
    const float* bv = (const float*)d_in[9];
    const float* Wo = (const float*)d_in[10];
    const float* bo = (const float*)d_in[11];
    float* out = (float*)d_out;

    static int smem_set = 0;
    if (!smem_set) {
        cudaFuncSetAttribute(proj_mma, cudaFuncAttributeMaxDynamicSharedMemorySize, DYN_SMEM);
        smem_set = 1;
    }

    prep_w<<<dim3(256, 3), 256>>>(Wq, Wk, Wv);

    proj_mma<<<dim3(DM / 128, BL / 128, 3), 256, DYN_SMEM>>>(
        queries, keys, values, bq, bk, bv);

    meanv_part<<<dim3(BB * HH, 4), 256>>>();
    score_mma<<<dim3(BB * HH, LL / 128), 128>>>(sidx);
    topk_kernel<<<BB * HH, 256>>>();
    mv_reduce<<<BB * HH, 64>>>();
    base_kernel<<<BB, 512>>>(Wo, bo);
    att_kernel<<<dim3(BB * HH, NCH), 384>>>();
    combine_kernel<<<BB * HH * UU, 64>>>();
    final_kernel<<<dim3(LL, BB), 128>>>(Wo, out);
}

// round 14
// speedup vs baseline: 1.2623x; 1.0007x over previous
#include <cuda_runtime.h>
#include <cuda_bf16.h>
#include <cstdint>

#define BB 8
#define LL 4096
#define DM 512
#define HH 8
#define DD 64
#define UU 45
#define NCH 16
#define CHUNK (LL / NCH)
#define SCALE 0.125f
#define BL (BB * LL)

// ---------------- scratch ----------------
__device__ float g_Q[BB * HH * LL * DD];
__device__ float g_K[BB * HH * LL * DD];
__device__ float g_V[BB * HH * LL * DD];
__device__ float g_M[BB * HH * LL];
__device__ int   g_top[BB * HH * UU];
__device__ float g_meanV[BB * HH * DD];
__device__ float g_mv4[4][BB * HH * DD];
__device__ float g_base[BB * DM];
__device__ float g_pm[BB * HH * NCH * UU];
__device__ float g_pl[BB * HH * NCH * UU];
__device__ float g_pacc[BB * HH * NCH * UU * DD];
__device__ float g_attn[BB * HH * UU * DD];
__device__ int g_hitcnt[BB * LL];
__device__ int g_hitlist[BB * LL * 8];
__device__ __align__(16) __nv_bfloat16 g_Wth[3][DM * DM];
__device__ __align__(16) __nv_bfloat16 g_Wtl[3][DM * DM];

// ================= PTX helpers =================
__device__ __forceinline__ uint32_t smem_u32(const void* p) {
    uint32_t a;
    asm("{ .reg .u64 t; cvta.to.shared.u64 t, %1; cvt.u32.u64 %0, t; }"
        : "=r"(a) : "l"(p));
    return a;
}
#define SWZ128(off)   ((off) ^ (((off) >> 3) & 0x70))

#define CP_ASYNC16(dst, src) \
    asm volatile("cp.async.cg.shared.global [%0], [%1], 16;" :: "r"(dst), "l"(src))
#define CP_COMMIT() asm volatile("cp.async.commit_group;" ::: "memory")
#define CP_WAIT(n)  asm volatile("cp.async.wait_group %0;" :: "n"(n) : "memory")

__device__ __forceinline__ void ldsm_x4(uint32_t* r, uint32_t addr) {
    asm volatile("ldmatrix.sync.aligned.m8n8.x4.shared.b16 {%0,%1,%2,%3}, [%4];"
        : "=r"(r[0]), "=r"(r[1]), "=r"(r[2]), "=r"(r[3]) : "r"(addr));
}
__device__ __forceinline__ void mma16816(float* d, const uint32_t* a,
                                         const uint32_t* b, const float* c) {
    asm volatile(
        "mma.sync.aligned.m16n8k16.row.col.f32.bf16.bf16.f32 "
        "{%0,%1,%2,%3},{%4,%5,%6,%7},{%8,%9},{%10,%11,%12,%13};"
        : "=f"(d[0]), "=f"(d[1]), "=f"(d[2]), "=f"(d[3])
        : "r"(a[0]), "r"(a[1]), "r"(a[2]), "r"(a[3]),
          "r"(b[0]), "r"(b[1]),
          "f"(c[0]), "f"(c[1]), "f"(c[2]), "f"(c[3]));
}

__device__ __forceinline__ void split8(const float* xs, __nv_bfloat16* h,
                                       __nv_bfloat16* l) {
#pragma unroll
    for (int i = 0; i < 8; i++) {
        __nv_bfloat16 hb = __float2bfloat16(xs[i]);
        h[i] = hb;
        l[i] = __float2bfloat16(xs[i] - __bfloat162float(hb));
    }
}

#define T_AH 0
#define T_AL 16384
#define T_WH 32768
#define T_WL 49152
#define STAGE_SZ 65536
#define OFF_BIAS 131072
#define DYN_SMEM (131072 + 1024)

// ---------------- W prep: transpose + split to bf16 hi/lo ----------------
__global__ __launch_bounds__(256) void prep_w(const float* __restrict__ Wq,
                                              const float* __restrict__ Wk,
                                              const float* __restrict__ Wv)
{
    int which = blockIdx.y;
    const float* W = (which == 0) ? Wq : (which == 1) ? Wk : Wv;
    int idx = (blockIdx.x * 256 + threadIdx.x) * 4;
    int n = idx >> 9, k = idx & 511;
#pragma unroll
    for (int i = 0; i < 4; i++) {
        float x = W[(size_t)(k + i) * DM + n];
        __nv_bfloat16 hb = __float2bfloat16(x);
        g_Wth[which][(size_t)n * DM + k + i] = hb;
        g_Wtl[which][(size_t)n * DM + k + i] = __float2bfloat16(x - __bfloat162float(hb));
    }
}

// ---------------- split-bf16 mma.sync GEMM with fused fp32->bf16 A split ----------------
__global__ __launch_bounds__(256) void proj_mma(
    const float* __restrict__ qin, const float* __restrict__ kin,
    const float* __restrict__ vin,
    const float* __restrict__ bq, const float* __restrict__ bk,
    const float* __restrict__ bv)
{
    extern __shared__ char dsm[];
    int which = blockIdx.z;
    float* P = (which == 0) ? g_Q : (which == 1) ? g_K : g_V;
    const float* bias = (which == 0) ? bq : (which == 1) ? bk : bv;
    const float* Afp = (which == 0) ? qin : (which == 1) ? kin : vin;
    const __nv_bfloat16* Wh = g_Wth[which];
    const __nv_bfloat16* Wl = g_Wtl[which];

    uint32_t su = smem_u32(dsm);
    int tid = threadIdx.x;
    int lane = tid & 31, wid = tid >> 5;
    int wm = wid & 3, wn = wid >> 2;
    int m0 = blockIdx.y * 128, n0 = blockIdx.x * 128;

    float* bias_s = (float*)(dsm + OFF_BIAS);
    if (tid < 128) bias_s[tid] = bias[n0 + tid];

    float acc[2][8][4];
#pragma unroll
    for (int a = 0; a < 2; a++)
#pragma unroll
        for (int b = 0; b < 8; b++)
#pragma unroll
            for (int c = 0; c < 4; c++) acc[a][b][c] = 0.f;

    float4 areg[4][2];
    auto ldA = [&](int k0) {
#pragma unroll
        for (int t = 0; t < 4; t++) {
            int idx = tid + 256 * t;
            int r = idx >> 3, c = idx & 7;
            const float* src = Afp + (size_t)(m0 + r) * DM + k0 + c * 8;
            areg[t][0] = *(const float4*)src;
            areg[t][1] = *(const float4*)(src + 4);
        }
    };
    auto stsA = [&](int stage) {
#pragma unroll
        for (int t = 0; t < 4; t++) {
            int idx = tid + 256 * t;
            int r = idx >> 3, c = idx & 7;
            float xs[8] = {areg[t][0].x, areg[t][0].y, areg[t][0].z, areg[t][0].w,
                           areg[t][1].x, areg[t][1].y, areg[t][1].z, areg[t][1].w};
            __align__(16) __nv_bfloat16 h[8], l[8];
            split8(xs, h, l);
            uint32_t sw = SWZ128((uint32_t)(r * 128 + c * 16));
            *(uint4*)(dsm + stage * STAGE_SZ + T_AH + sw) = *(uint4*)h;
            *(uint4*)(dsm + stage * STAGE_SZ + T_AL + sw) = *(uint4*)l;
        }
    };
    auto cpW = [&](int stage, int k0) {
        uint32_t sb = su + stage * STAGE_SZ;
#pragma unroll
        for (int t = 0; t < 4; t++) {
            int idx = tid + 256 * t;
            int r = idx >> 3, c = idx & 7;
            uint32_t sw = SWZ128((uint32_t)(r * 128 + c * 16));
            CP_ASYNC16(sb + T_WH + sw, Wh + (size_t)(n0 + r) * DM + k0 + c * 8);
            CP_ASYNC16(sb + T_WL + sw, Wl + (size_t)(n0 + r) * DM + k0 + c * 8);
        }
        CP_COMMIT();
    };

    ldA(0);
    cpW(0, 0);
    stsA(0);
    ldA(64);

    int a_row = (lane & 15), a_k16 = (lane >> 4) << 4;
    int b_grp = lane >> 3;
    int b_row = ((b_grp >> 1) << 3) + (lane & 7);
    int b_k16 = (b_grp & 1) << 4;

    for (int chunk = 0; chunk < 8; chunk++) {
        if (chunk < 7) cpW((chunk + 1) & 1, (chunk + 1) * 64);
        if (chunk < 7) { CP_WAIT(1); } else { CP_WAIT(0); }
        __syncthreads();

        if (chunk < 7) stsA((chunk + 1) & 1);
        if (chunk < 6) ldA((chunk + 2) * 64);

        uint32_t sb = su + (chunk & 1) * STAGE_SZ;
#pragma unroll
        for (int ks = 0; ks < 4; ks++) {
            uint32_t ah[2][4], al[2][4], bh[16], bl[16];
#pragma unroll
            for (int mf = 0; mf < 2; mf++) {
                int row = wm * 32 + mf * 16 + a_row;
                uint32_t off = SWZ128((uint32_t)(row * 128 + ks * 32 + a_k16));
                ldsm_x4(ah[mf], sb + T_AH + off);
                ldsm_x4(al[mf], sb + T_AL + off);
            }
#pragma unroll
            for (int g2 = 0; g2 < 4; g2++) {
                int row = wn * 64 + g2 * 16 + b_row;
                uint32_t off = SWZ128((uint32_t)(row * 128 + ks * 32 + b_k16));
                ldsm_x4(&bh[g2 * 4], sb + T_WH + off);
                ldsm_x4(&bl[g2 * 4], sb + T_WL + off);
            }
#pragma unroll
            for (int mf = 0; mf < 2; mf++)
#pragma unroll
                for (int nf = 0; nf < 8; nf++)
                    mma16816(acc[mf][nf], ah[mf], &bh[nf * 2], acc[mf][nf]);
#pragma unroll
            for (int mf = 0; mf < 2; mf++)
#pragma unroll
                for (int nf = 0; nf < 8; nf++)
                    mma16816(acc[mf][nf], ah[mf], &bl[nf * 2], acc[mf][nf]);
#pragma unroll
            for (int mf = 0; mf < 2; mf++)
#pragma unroll
                for (int nf = 0; nf < 8; nf++)
                    mma16816(acc[mf][nf], al[mf], &bh[nf * 2], acc[mf][nf]);
        }
        __syncthreads();
    }

    float* Cs = (float*)dsm;
#pragma unroll
    for (int mf = 0; mf < 2; mf++)
#pragma unroll
        for (int nf = 0; nf < 8; nf++) {
            int r = wm * 32 + mf * 16 + (lane >> 2);
            int col = wn * 64 + nf * 8 + (lane & 3) * 2;
            Cs[r * 132 + col]           = acc[mf][nf][0] + bias_s[col];
            Cs[r * 132 + col + 1]       = acc[mf][nf][1] + bias_s[col + 1];
            Cs[(r + 8) * 132 + col]     = acc[mf][nf][2] + bias_s[col];
            Cs[(r + 8) * 132 + col + 1] = acc[mf][nf][3] + bias_s[col + 1];
        }
    __syncthreads();

#pragma unroll
    for (int it = 0; it < 16; it++) {
        int idx = tid + it * 256;
        int row = idx >> 5, c4 = idx & 31;
        int m = m0 + row;
        int b = m >> 12, l = m & (LL - 1);
        int n = n0 + c4 * 4;
        int h = n >> 6, d = n & 63;
        float4 v;
        v.x = Cs[row * 132 + c4 * 4 + 0];
        v.y = Cs[row * 132 + c4 * 4 + 1];
        v.z = Cs[row * 132 + c4 * 4 + 2];
        v.w = Cs[row * 132 + c4 * 4 + 3];
        *(float4*)&P[((size_t)(b * HH + h) * LL + l) * DD + d] = v;
    }
}

// ---------------- sampled scoring via MMA: 128x48x64 per block ----------------
__global__ __launch_bounds__(128) void score_mma(const int* __restrict__ sidx)
{
    __shared__ __align__(16) char AH[16384];
    __shared__ __align__(16) char AL[16384];
    __shared__ __align__(16) char BHs[6144];
    __shared__ __align__(16) char BLs[6144];
    __shared__ int ssi[UU];
    int bh = blockIdx.x, m0 = blockIdx.y * 128;
    int tid = threadIdx.x, lane = tid & 31, wm = tid >> 5;

    if (tid < UU) ssi[tid] = sidx[tid];
    for (int i = tid; i < 6144 / 16; i += 128) {
        ((uint4*)BHs)[i] = make_uint4(0, 0, 0, 0);
        ((uint4*)BLs)[i] = make_uint4(0, 0, 0, 0);
    }
    __syncthreads();

    for (int u = tid; u < UU * 8; u += 128) {
        int j = u >> 3, c = u & 7;
        const float* src = g_K + ((size_t)bh * LL + ssi[j]) * DD + c * 8;
        float4 f0 = *(const float4*)src, f1 = *(const float4*)(src + 4);
        float xs[8] = {f0.x, f0.y, f0.z, f0.w, f1.x, f1.y, f1.z, f1.w};
        __align__(16) __nv_bfloat16 h[8], l[8];
        split8(xs, h, l);
        uint32_t sw = SWZ128((uint32_t)(j * 128 + c * 16));
        *(uint4*)(BHs + sw) = *(uint4*)h;
        *(uint4*)(BLs + sw) = *(uint4*)l;
    }
#pragma unroll
    for (int t = 0; t < 8; t++) {
        int idx = tid + 128 * t;
        int r = idx >> 3, c = idx & 7;
        const float* src = g_Q + ((size_t)bh * LL + m0 + r) * DD + c * 8;
        float4 f0 = *(const float4*)src, f1 = *(const float4*)(src + 4);
        float xs[8] = {f0.x, f0.y, f0.z, f0.w, f1.x, f1.y, f1.z, f1.w};
        __align__(16) __nv_bfloat16 h[8], l[8];
        split8(xs, h, l);
        uint32_t sw = SWZ128((uint32_t)(r * 128 + c * 16));
        *(uint4*)(AH + sw) = *(uint4*)h;
        *(uint4*)(AL + sw) = *(uint4*)l;
    }
    __syncthreads();

    float acc[2][6][4];
#pragma unroll
    for (int a = 0; a < 2; a++)
#pragma unroll
        for (int b = 0; b < 6; b++)
#pragma unroll
            for (int c = 0; c < 4; c++) acc[a][b][c] = 0.f;

    uint32_t suA_h = smem_u32(AH), suA_l = smem_u32(AL);
    uint32_t suB_h = smem_u32(BHs), suB_l = smem_u32(BLs);
    int a_row = (lane & 15), a_k16 = (lane >> 4) << 4;
    int b_grp = lane >> 3;
    int b_row = ((b_grp >> 1) << 3) + (lane & 7);
    int b_k16 = (b_grp & 1) << 4;

#pragma unroll
    for (int ks = 0; ks < 4; ks++) {
        uint32_t ah[2][4], al[2][4], bhf[12], blf[12];
#pragma unroll
        for (int mf = 0; mf < 2; mf++) {
            int row = wm * 32 + mf * 16 + a_row;
            uint32_t off = SWZ128((uint32_t)(row * 128 + ks * 32 + a_k16));
            ldsm_x4(ah[mf], suA_h + off);
            ldsm_x4(al[mf], suA_l + off);
        }
#pragma unroll
        for (int g2 = 0; g2 < 3; g2++) {
            int row = g2 * 16 + b_row;
            uint32_t off = SWZ128((uint32_t)(row * 128 + ks * 32 + b_k16));
            ldsm_x4(&bhf[g2 * 4], suB_h + off);
            ldsm_x4(&blf[g2 * 4], suB_l + off);
        }
#pragma unroll
        for (int mf = 0; mf < 2; mf++)
#pragma unroll
            for (int nf = 0; nf < 6; nf++)
                mma16816(acc[mf][nf], ah[mf], &bhf[nf * 2], acc[mf][nf]);
#pragma unroll
        for (int mf = 0; mf < 2; mf++)
#pragma unroll
            for (int nf = 0; nf < 6; nf++)
                mma16816(acc[mf][nf], ah[mf], &blf[nf * 2], acc[mf][nf]);
#pragma unroll
        for (int mf = 0; mf < 2; mf++)
#pragma unroll
            for (int nf = 0; nf < 6; nf++)
                mma16816(acc[mf][nf], al[mf], &bhf[nf * 2], acc[mf][nf]);
    }

    int cbase = (lane & 3) * 2;
#pragma unroll
    for (int mf = 0; mf < 2; mf++) {
        float mx0 = -1e30f, sm0 = 0.f, mx1 = -1e30f, sm1 = 0.f;
#pragma unroll
        for (int nf = 0; nf < 6; nf++) {
            int c0 = nf * 8 + cbase, c1 = c0 + 1;
            if (c0 < UU) { mx0 = fmaxf(mx0, acc[mf][nf][0]); sm0 += acc[mf][nf][0]; }
            if (c1 < UU) { mx0 = fmaxf(mx0, acc[mf][nf][1]); sm0 += acc[mf][nf][1]; }
            if (c0 < UU) { mx1 = fmaxf(mx1, acc[mf][nf][2]); sm1 += acc[mf][nf][2]; }
            if (c1 < UU) { mx1 = fmaxf(mx1, acc[mf][nf][3]); sm1 += acc[mf][nf][3]; }
        }
#pragma unroll
        for (int off = 1; off < 4; off <<= 1) {
            mx0 = fmaxf(mx0, __shfl_xor_sync(0xffffffffu, mx0, off));
            sm0 += __shfl_xor_sync(0xffffffffu, sm0, off);
            mx1 = fmaxf(mx1, __shfl_xor_sync(0xffffffffu, mx1, off));
            sm1 += __shfl_xor_sync(0xffffffffu, sm1, off);
        }
        if ((lane & 3) == 0) {
            int r = wm * 32 + mf * 16 + (lane >> 2);
            g_M[(size_t)bh * LL + m0 + r]     = (mx0 - sm0 * (1.f / UU)) * SCALE;
            g_M[(size_t)bh * LL + m0 + r + 8] = (mx1 - sm1 * (1.f / UU)) * SCALE;
        }
    }
}

// ---------------- top-45 via radix select ----------------
__global__ __launch_bounds__(256) void topk_kernel()
{
    __shared__ uint32_t uvals[LL];
    __shared__ int histw[8][256];
    __shared__ int scan[256];
    __shared__ int sel_byte, new_k;
    __shared__ int cnt_g, cnt_e;
    __shared__ int eq[256];
    int bh = blockIdx.x, tid = threadIdx.x;
    int w = tid >> 5;

    for (int i = tid; i < LL; i += 256) {
        uint32_t u = __float_as_uint(g_M[(size_t)bh * LL + i]);
        uvals[i] = (u & 0x80000000u) ? ~u : (u | 0x80000000u);
    }

    uint32_t prefix = 0, mask = 0;
    int k = UU;
    for (int pass = 0; pass < 4; pass++) {
        int shift = 24 - pass * 8;
#pragma unroll
        for (int ww = 0; ww < 8; ww++) histw[ww][tid] = 0;
        __syncthreads();
        for (int i = tid; i < LL; i += 256) {
            uint32_t u = uvals[i];
            if ((u & mask) == prefix)
                atomicAdd(&histw[w][(u >> shift) & 255], 1);
        }
        __syncthreads();
        int c = 0;
#pragma unroll
        for (int ww = 0; ww < 8; ww++) c += histw[ww][tid];
        scan[tid] = c;
        __syncthreads();
#pragma unroll
        for (int off = 1; off < 256; off <<= 1) {
            int v = (tid + off < 256) ? scan[tid + off] : 0;
            __syncthreads();
            scan[tid] += v;
            __syncthreads();
        }
        {
            int snext = (tid < 255) ? scan[tid + 1] : 0;
            if (scan[tid] >= k && snext < k) {
                sel_byte = tid;
                new_k = k - snext;
            }
        }
        __syncthreads();
        prefix |= ((uint32_t)sel_byte << shift);
        mask |= (255u << shift);
        k = new_k;
        __syncthreads();
    }
    uint32_t T = prefix;

    if (tid == 0) { cnt_g = 0; cnt_e = 0; }
    __syncthreads();
    for (int i = tid; i < LL; i += 256) {
        uint32_t u = uvals[i];
        if (u > T) {
            int p = atomicAdd(&cnt_g, 1);
            g_top[bh * UU + p] = i;
        } else if (u == T) {
            int p = atomicAdd(&cnt_e, 1);
            if (p < 256) eq[p] = i;
        }
    }
    __syncthreads();
    int ng = cnt_g;
    int need = UU - ng;
    if (tid == 0 && need > 0) {
        if (cnt_e <= 256) {
            int ec = cnt_e;
            for (int s = 0; s < need; s++) {
                int best = s;
                for (int j = s + 1; j < ec; j++)
                    if (eq[j] < eq[best]) best = j;
                int t = eq[s]; eq[s] = eq[best]; eq[best] = t;
                g_top[bh * UU + ng + s] = eq[s];
            }
        } else {
            int got = 0;
            for (int i = 0; i < LL && got < need; i++)
                if (uvals[i] == T) { g_top[bh * UU + ng + got] = i; got++; }
        }
    }
}

// ---------------- hit map: per (b,row) list of (h,j) ----------------
__global__ __launch_bounds__(256) void zero_hits()
{
    int i = blockIdx.x * 256 + threadIdx.x;
    g_hitcnt[i] = 0;
}
__global__ __launch_bounds__(64) void build_hits()
{
    int bh = blockIdx.x, tid = threadIdx.x;
    if (tid < UU) {
        int b = bh >> 3, h = bh & 7;
        int t = g_top[bh * UU + tid];
        int p = atomicAdd(&g_hitcnt[b * LL + t], 1);
        g_hitlist[(b * LL + t) * 8 + p] = (h << 8) | tid;
    }
}

// ---------------- mean(V): 4-way split partials + reduce ----------------
__global__ __launch_bounds__(256) void meanv_part()
{
    __shared__ float red[4][64];
    int bh = blockIdx.x, part = blockIdx.y, tid = threadIdx.x;
    int d = tid & 63, sub = tid >> 6;
    const float* base =
        g_V + ((size_t)bh * LL + part * (LL / 4) + sub * (LL / 16)) * DD + d;
    float s0 = 0.f, s1 = 0.f, s2 = 0.f, s3 = 0.f;
    for (int i = 0; i < LL / 16; i += 4) {
        s0 += base[(size_t)(i + 0) * DD];
        s1 += base[(size_t)(i + 1) * DD];
        s2 += base[(size_t)(i + 2) * DD];
        s3 += base[(size_t)(i + 3) * DD];
    }
    red[sub][d] = (s0 + s1) + (s2 + s3);
    __syncthreads();
    if (sub == 0)
        g_mv4[part][bh * DD + d] =
            (red[0][d] + red[1][d]) + (red[2][d] + red[3][d]);
}

__global__ __launch_bounds__(64) void mv_reduce()
{
    int bh = blockIdx.x, d = threadIdx.x;
    g_meanV[bh * DD + d] =
        ((g_mv4[0][bh * DD + d] + g_mv4[1][bh * DD + d]) +
         (g_mv4[2][bh * DD + d] + g_mv4[3][bh * DD + d])) * (1.f / LL);
}

// ---------------- base row per batch ----------------
__global__ __launch_bounds__(512) void base_kernel(const float* __restrict__ Wo,
                                                   const float* __restrict__ bo)
{
    int b = blockIdx.x, c = threadIdx.x;
    float acc = bo[c];
    const float* mv = g_meanV + b * DM;
    for (int k = 0; k < DM; k++) acc += mv[k] * Wo[(size_t)k * DM + c];
    g_base[b * DM + c] = acc;
}

// ---------------- flash attention for top-45 queries ----------------
__global__ __launch_bounds__(384) void att_kernel()
{
    __shared__ __align__(16) float Qs[UU * 64];
    __shared__ __align__(16) float Ks[64 * 68];
    __shared__ __align__(16) float Vs[64 * 64];
    int bh = blockIdx.x, ch = blockIdx.y;
    int tid = threadIdx.x;
    int q = tid >> 3, lane8 = tid & 7;
    int qe = (q < UU) ? q : (UU - 1);

    for (int i = tid; i < UU * 64; i += 384) {
        int qq = i >> 6, d = i & 63;
        int l = g_top[bh * UU + qq];
        Qs[i] = g_Q[((size_t)bh * LL + l) * DD + d];
    }
    __syncthreads();

    float4 q4[16];
#pragma unroll
    for (int dd = 0; dd < 16; dd++) q4[dd] = *(const float4*)(Qs + qe * 64 + dd * 4);

    float m = -1e30f, lsum = 0.f;
    float acc[8];
#pragma unroll
    for (int i = 0; i < 8; i++) acc[i] = 0.f;

    int key0 = ch * CHUNK;
    for (int t0 = 0; t0 < CHUNK; t0 += 64) {
        __syncthreads();
        for (int i = tid; i < 1024; i += 384) {
            int r = i >> 4, c4 = (i & 15) << 2;
            size_t gidx = ((size_t)bh * LL + key0 + t0 + r) * DD + c4;
            *(float4*)&Ks[r * 68 + c4] = *(const float4*)&g_K[gidx];
            *(float4*)&Vs[r * 64 + c4] = *(const float4*)&g_V[gidx];
        }
        __syncthreads();

        float s[8];
#pragma unroll
        for (int tt = 0; tt < 8; tt++) {
            int j = lane8 + 8 * tt;
            const float* kr = Ks + j * 68;
            float sv = 0.f;
#pragma unroll
            for (int dd = 0; dd < 16; dd++) {
                float4 kv = *(const float4*)(kr + dd * 4);
                sv += q4[dd].x * kv.x + q4[dd].y * kv.y +
                      q4[dd].z * kv.z + q4[dd].w * kv.w;
            }
            s[tt] = sv * SCALE;
        }
        float tmax = s[0];
#pragma unroll
        for (int tt = 1; tt < 8; tt++) tmax = fmaxf(tmax, s[tt]);
#pragma unroll
        for (int off = 4; off; off >>= 1)
            tmax = fmaxf(tmax, __shfl_xor_sync(0xffffffffu, tmax, off));
        float mnew = fmaxf(m, tmax);
        float alpha = __expf(m - mnew);
        lsum *= alpha;
#pragma unroll
        for (int i = 0; i < 8; i++) acc[i] *= alpha;
        float p[8];
#pragma unroll
        for (int tt = 0; tt < 8; tt++) {
            p[tt] = __expf(s[tt] - mnew);
            lsum += p[tt];
        }
        m = mnew;
#pragma unroll
        for (int j = 0; j < 64; j++) {
            float pj = __shfl_sync(0xffffffffu, p[j >> 3], j & 7, 8);
            const float* vr = Vs + j * 64 + lane8 * 8;
            float4 v0 = *(const float4*)vr;
            float4 v1 = *(const float4*)(vr + 4);
            acc[0] += pj * v0.x; acc[1] += pj * v0.y;
            acc[2] += pj * v0.z; acc[3] += pj * v0.w;
            acc[4] += pj * v1.x; acc[5] += pj * v1.y;
            acc[6] += pj * v1.z; acc[7] += pj * v1.w;
        }
    }
#pragma unroll
    for (int off = 4; off; off >>= 1)
        lsum += __shfl_xor_sync(0xffffffffu, lsum, off);

    if (q < UU) {
        int idx = (bh * NCH + ch) * UU + q;
        if (lane8 == 0) { g_pm[idx] = m; g_pl[idx] = lsum; }
        float* pa = g_pacc + (size_t)idx * DD + lane8 * 8;
#pragma unroll
        for (int i = 0; i < 8; i++) pa[i] = acc[i];
    }
}

// ---------------- merge split-L partials ----------------
__global__ __launch_bounds__(64) void combine_kernel()
{
    int r = blockIdx.x;
    int d = threadIdx.x;
    int bh = r / UU, q = r % UU;
    float M = -1e30f;
#pragma unroll
    for (int c = 0; c < NCH; c++)
        M = fmaxf(M, g_pm[(bh * NCH + c) * UU + q]);
    float Ltot = 0.f, acc = 0.f;
#pragma unroll
    for (int c = 0; c < NCH; c++) {
        int idx = (bh * NCH + c) * UU + q;
        float e = __expf(g_pm[idx] - M);
        Ltot += g_pl[idx] * e;
        acc  += e * g_pacc[(size_t)idx * DD + d];
    }
    g_attn[(size_t)(bh * UU + q) * DD + d] = acc / Ltot;
}

// ---------------- final output: hit-list driven ----------------
__global__ __launch_bounds__(128) void final_kernel(const float* __restrict__ Wo,
                                                    float* __restrict__ out)
{
    __shared__ float delta[64];
    __shared__ int hits[8];
    int qrow = blockIdx.x, b = blockIdx.y;
    int tid = threadIdx.x;
    int c0 = tid * 4;

    int cnt = g_hitcnt[b * LL + qrow];
    float4 acc = *(const float4*)&g_base[b * DM + c0];

    if (cnt > 0) {
        if (tid < cnt) hits[tid] = g_hitlist[(b * LL + qrow) * 8 + tid];
        __syncthreads();
        if (tid == 0) {   // head-ascending order to match reference sum order
            for (int s = 1; s < cnt; s++) {
                int v = hits[s], j2 = s;
                while (j2 > 0 && hits[j2 - 1] > v) { hits[j2] = hits[j2 - 1]; j2--; }
                hits[j2] = v;
            }
        }
        __syncthreads();
        for (int i = 0; i < cnt; i++) {
            int e = hits[i];
            int h = e >> 8, j = e & 255;
            if (tid < 64)
                delta[tid] = g_attn[((size_t)(b * HH + h) * UU + j) * DD + tid] -
                             g_meanV[(b * HH + h) * DD + tid];
            __syncthreads();
#pragma unroll 4
            for (int d = 0; d < 64; d++) {
                float dv = delta[d];
                float4 w = *(const float4*)&Wo[(size_t)(h * 64 + d) * DM + c0];
                acc.x += dv * w.x; acc.y += dv * w.y;
                acc.z += dv * w.z; acc.w += dv * w.w;
            }
            __syncthreads();
        }
    }
    *(float4*)&out[((size_t)b * LL + qrow) * DM + c0] = acc;
}

// ---------------- launcher ----------------
extern "C" void kernel_launch(void* const* d_in, const int* in_sizes, int n_in,
                              void* d_out, int out_size)
{
    const float* queries = (const float*)d_in[0];
    const float* keys    = (const float*)d_in[1];
    const float* values  = (const float*)d_in[2];
    const int*   sidx    = (const int*)d_in[3];
    const float* Wq = (const float*)d_in[4];
    const float* bq = (const float*)d_in[5];
    const float* Wk = (const float*)d_in[6];
    const float* bk = (const float*)d_in[7];
    const float* Wv = (const float*)d_in[8];
    const float* bv = (const float*)d_in[9];
    const float* Wo = (const float*)d_in[10];
    const float* bo = (const float*)d_in[11];
    float* out = (float*)d_out;

    static int smem_set = 0;
    if (!smem_set) {
        cudaFuncSetAttribute(proj_mma, cudaFuncAttributeMaxDynamicSharedMemorySize, DYN_SMEM);
        smem_set = 1;
    }

    prep_w<<<dim3(256, 3), 256>>>(Wq, Wk, Wv);
    zero_hits<<<BB * LL / 256, 256>>>();

    proj_mma<<<dim3(DM / 128, BL / 128, 3), 256, DYN_SMEM>>>(
        queries, keys, values, bq, bk, bv);

    meanv_part<<<dim3(BB * HH, 4), 256>>>();
    score_mma<<<dim3(BB * HH, LL / 128), 128>>>(sidx);
    topk_kernel<<<BB * HH, 256>>>();
    build_hits<<<BB * HH, 64>>>();
    mv_reduce<<<BB * HH, 64>>>();
    base_kernel<<<BB, 512>>>(Wo, bo);
    att_kernel<<<dim3(BB * HH, NCH), 384>>>();
    combine_kernel<<<BB * HH * UU, 64>>>();
    final_kernel<<<dim3(LL, BB), 128>>>(Wo, out);
}

// round 15
// speedup vs baseline: 1.7297x; 1.3703x over previous
#include <cuda_runtime.h>
#include <cuda_bf16.h>
#include <cstdint>

#define BB 8
#define LL 4096
#define DM 512
#define HH 8
#define DD 64
#define UU 45
#define NCH 16
#define CHUNK (LL / NCH)
#define SCALE 0.125f
#define BL (BB * LL)

// ---------------- scratch ----------------
__device__ float g_Q[BB * HH * LL * DD];
__device__ float g_K[BB * HH * LL * DD];
__device__ float g_V[BB * HH * LL * DD];
__device__ float g_M[BB * HH * LL];
__device__ int   g_top[BB * HH * UU];
__device__ float g_meanV[BB * HH * DD];
__device__ float g_mv4[4][BB * HH * DD];
__device__ float g_base[BB * DM];
__device__ float g_pm[BB * HH * NCH * UU];
__device__ float g_pl[BB * HH * NCH * UU];
__device__ float g_pacc[BB * HH * NCH * UU * DD];
__device__ float g_attn[BB * HH * UU * DD];
__device__ int g_hitcnt[BB * LL];
__device__ int g_hitlist[BB * LL * 8];
__device__ __align__(16) __nv_bfloat16 g_Wth[3][DM * DM];
__device__ __align__(16) __nv_bfloat16 g_Wtl[3][DM * DM];

// ================= PTX helpers =================
__device__ __forceinline__ uint32_t smem_u32(const void* p) {
    uint32_t a;
    asm("{ .reg .u64 t; cvta.to.shared.u64 t, %1; cvt.u32.u64 %0, t; }"
        : "=r"(a) : "l"(p));
    return a;
}
#define SWZ128(off)   ((off) ^ (((off) >> 3) & 0x70))

#define CP_ASYNC16(dst, src) \
    asm volatile("cp.async.cg.shared.global [%0], [%1], 16;" :: "r"(dst), "l"(src))
#define CP_COMMIT() asm volatile("cp.async.commit_group;" ::: "memory")
#define CP_WAIT(n)  asm volatile("cp.async.wait_group %0;" :: "n"(n) : "memory")

__device__ __forceinline__ void ldsm_x4(uint32_t* r, uint32_t addr) {
    asm volatile("ldmatrix.sync.aligned.m8n8.x4.shared.b16 {%0,%1,%2,%3}, [%4];"
        : "=r"(r[0]), "=r"(r[1]), "=r"(r[2]), "=r"(r[3]) : "r"(addr));
}
__device__ __forceinline__ void mma16816(float* d, const uint32_t* a,
                                         const uint32_t* b, const float* c) {
    asm volatile(
        "mma.sync.aligned.m16n8k16.row.col.f32.bf16.bf16.f32 "
        "{%0,%1,%2,%3},{%4,%5,%6,%7},{%8,%9},{%10,%11,%12,%13};"
        : "=f"(d[0]), "=f"(d[1]), "=f"(d[2]), "=f"(d[3])
        : "r"(a[0]), "r"(a[1]), "r"(a[2]), "r"(a[3]),
          "r"(b[0]), "r"(b[1]),
          "f"(c[0]), "f"(c[1]), "f"(c[2]), "f"(c[3]));
}

__device__ __forceinline__ void split8(const float* xs, __nv_bfloat16* h,
                                       __nv_bfloat16* l) {
#pragma unroll
    for (int i = 0; i < 8; i++) {
        __nv_bfloat16 hb = __float2bfloat16(xs[i]);
        h[i] = hb;
        l[i] = __float2bfloat16(xs[i] - __bfloat162float(hb));
    }
}
__device__ __forceinline__ uint32_t pack2(float a, float b) {
    __nv_bfloat162 v;
    v.x = __float2bfloat16(a);
    v.y = __float2bfloat16(b);
    return *(uint32_t*)&v;
}

#define T_AH 0
#define T_AL 16384
#define T_WH 32768
#define T_WL 49152
#define STAGE_SZ 65536
#define OFF_BIAS 131072
#define DYN_SMEM (131072 + 1024)

// att_mma smem offsets
#define A_QH 0
#define A_QL 8192
#define A_KH 16384
#define A_KL 24576
#define A_VH 32768
#define A_VL 40960
#define A_TOP 49152
#define DYN_SMEM_ATT (49152 + 256)

// ---------------- W prep: transpose + split to bf16 hi/lo ----------------
__global__ __launch_bounds__(256) void prep_w(const float* __restrict__ Wq,
                                              const float* __restrict__ Wk,
                                              const float* __restrict__ Wv)
{
    int which = blockIdx.y;
    const float* W = (which == 0) ? Wq : (which == 1) ? Wk : Wv;
    int idx = (blockIdx.x * 256 + threadIdx.x) * 4;
    int n = idx >> 9, k = idx & 511;
#pragma unroll
    for (int i = 0; i < 4; i++) {
        float x = W[(size_t)(k + i) * DM + n];
        __nv_bfloat16 hb = __float2bfloat16(x);
        g_Wth[which][(size_t)n * DM + k + i] = hb;
        g_Wtl[which][(size_t)n * DM + k + i] = __float2bfloat16(x - __bfloat162float(hb));
    }
}

// ---------------- split-bf16 mma.sync GEMM with fused fp32->bf16 A split ----------------
__global__ __launch_bounds__(256) void proj_mma(
    const float* __restrict__ qin, const float* __restrict__ kin,
    const float* __restrict__ vin,
    const float* __restrict__ bq, const float* __restrict__ bk,
    const float* __restrict__ bv)
{
    extern __shared__ char dsm[];
    int which = blockIdx.z;
    float* P = (which == 0) ? g_Q : (which == 1) ? g_K : g_V;
    const float* bias = (which == 0) ? bq : (which == 1) ? bk : bv;
    const float* Afp = (which == 0) ? qin : (which == 1) ? kin : vin;
    const __nv_bfloat16* Wh = g_Wth[which];
    const __nv_bfloat16* Wl = g_Wtl[which];

    uint32_t su = smem_u32(dsm);
    int tid = threadIdx.x;
    int lane = tid & 31, wid = tid >> 5;
    int wm = wid & 3, wn = wid >> 2;
    int m0 = blockIdx.y * 128, n0 = blockIdx.x * 128;

    float* bias_s = (float*)(dsm + OFF_BIAS);
    if (tid < 128) bias_s[tid] = bias[n0 + tid];

    float acc[2][8][4];
#pragma unroll
    for (int a = 0; a < 2; a++)
#pragma unroll
        for (int b = 0; b < 8; b++)
#pragma unroll
            for (int c = 0; c < 4; c++) acc[a][b][c] = 0.f;

    float4 areg[4][2];
    auto ldA = [&](int k0) {
#pragma unroll
        for (int t = 0; t < 4; t++) {
            int idx = tid + 256 * t;
            int r = idx >> 3, c = idx & 7;
            const float* src = Afp + (size_t)(m0 + r) * DM + k0 + c * 8;
            areg[t][0] = *(const float4*)src;
            areg[t][1] = *(const float4*)(src + 4);
        }
    };
    auto stsA = [&](int stage) {
#pragma unroll
        for (int t = 0; t < 4; t++) {
            int idx = tid + 256 * t;
            int r = idx >> 3, c = idx & 7;
            float xs[8] = {areg[t][0].x, areg[t][0].y, areg[t][0].z, areg[t][0].w,
                           areg[t][1].x, areg[t][1].y, areg[t][1].z, areg[t][1].w};
            __align__(16) __nv_bfloat16 h[8], l[8];
            split8(xs, h, l);
            uint32_t sw = SWZ128((uint32_t)(r * 128 + c * 16));
            *(uint4*)(dsm + stage * STAGE_SZ + T_AH + sw) = *(uint4*)h;
            *(uint4*)(dsm + stage * STAGE_SZ + T_AL + sw) = *(uint4*)l;
        }
    };
    auto cpW = [&](int stage, int k0) {
        uint32_t sb = su + stage * STAGE_SZ;
#pragma unroll
        for (int t = 0; t < 4; t++) {
            int idx = tid + 256 * t;
            int r = idx >> 3, c = idx & 7;
            uint32_t sw = SWZ128((uint32_t)(r * 128 + c * 16));
            CP_ASYNC16(sb + T_WH + sw, Wh + (size_t)(n0 + r) * DM + k0 + c * 8);
            CP_ASYNC16(sb + T_WL + sw, Wl + (size_t)(n0 + r) * DM + k0 + c * 8);
        }
        CP_COMMIT();
    };

    ldA(0);
    cpW(0, 0);
    stsA(0);
    ldA(64);

    int a_row = (lane & 15), a_k16 = (lane >> 4) << 4;
    int b_grp = lane >> 3;
    int b_row = ((b_grp >> 1) << 3) + (lane & 7);
    int b_k16 = (b_grp & 1) << 4;

    for (int chunk = 0; chunk < 8; chunk++) {
        if (chunk < 7) cpW((chunk + 1) & 1, (chunk + 1) * 64);
        if (chunk < 7) { CP_WAIT(1); } else { CP_WAIT(0); }
        __syncthreads();

        if (chunk < 7) stsA((chunk + 1) & 1);
        if (chunk < 6) ldA((chunk + 2) * 64);

        uint32_t sb = su + (chunk & 1) * STAGE_SZ;
#pragma unroll
        for (int ks = 0; ks < 4; ks++) {
            uint32_t ah[2][4], al[2][4], bh[16], bl[16];
#pragma unroll
            for (int mf = 0; mf < 2; mf++) {
                int row = wm * 32 + mf * 16 + a_row;
                uint32_t off = SWZ128((uint32_t)(row * 128 + ks * 32 + a_k16));
                ldsm_x4(ah[mf], sb + T_AH + off);
                ldsm_x4(al[mf], sb + T_AL + off);
            }
#pragma unroll
            for (int g2 = 0; g2 < 4; g2++) {
                int row = wn * 64 + g2 * 16 + b_row;
                uint32_t off = SWZ128((uint32_t)(row * 128 + ks * 32 + b_k16));
                ldsm_x4(&bh[g2 * 4], sb + T_WH + off);
                ldsm_x4(&bl[g2 * 4], sb + T_WL + off);
            }
#pragma unroll
            for (int mf = 0; mf < 2; mf++)
#pragma unroll
                for (int nf = 0; nf < 8; nf++)
                    mma16816(acc[mf][nf], ah[mf], &bh[nf * 2], acc[mf][nf]);
#pragma unroll
            for (int mf = 0; mf < 2; mf++)
#pragma unroll
                for (int nf = 0; nf < 8; nf++)
                    mma16816(acc[mf][nf], ah[mf], &bl[nf * 2], acc[mf][nf]);
#pragma unroll
            for (int mf = 0; mf < 2; mf++)
#pragma unroll
                for (int nf = 0; nf < 8; nf++)
                    mma16816(acc[mf][nf], al[mf], &bh[nf * 2], acc[mf][nf]);
        }
        __syncthreads();
    }

    float* Cs = (float*)dsm;
#pragma unroll
    for (int mf = 0; mf < 2; mf++)
#pragma unroll
        for (int nf = 0; nf < 8; nf++) {
            int r = wm * 32 + mf * 16 + (lane >> 2);
            int col = wn * 64 + nf * 8 + (lane & 3) * 2;
            Cs[r * 132 + col]           = acc[mf][nf][0] + bias_s[col];
            Cs[r * 132 + col + 1]       = acc[mf][nf][1] + bias_s[col + 1];
            Cs[(r + 8) * 132 + col]     = acc[mf][nf][2] + bias_s[col];
            Cs[(r + 8) * 132 + col + 1] = acc[mf][nf][3] + bias_s[col + 1];
        }
    __syncthreads();

#pragma unroll
    for (int it = 0; it < 16; it++) {
        int idx = tid + it * 256;
        int row = idx >> 5, c4 = idx & 31;
        int m = m0 + row;
        int b = m >> 12, l = m & (LL - 1);
        int n = n0 + c4 * 4;
        int h = n >> 6, d = n & 63;
        float4 v;
        v.x = Cs[row * 132 + c4 * 4 + 0];
        v.y = Cs[row * 132 + c4 * 4 + 1];
        v.z = Cs[row * 132 + c4 * 4 + 2];
        v.w = Cs[row * 132 + c4 * 4 + 3];
        *(float4*)&P[((size_t)(b * HH + h) * LL + l) * DD + d] = v;
    }
}

// ---------------- sampled scoring via MMA: 128x48x64 per block ----------------
__global__ __launch_bounds__(128) void score_mma(const int* __restrict__ sidx)
{
    __shared__ __align__(16) char AH[16384];
    __shared__ __align__(16) char AL[16384];
    __shared__ __align__(16) char BHs[6144];
    __shared__ __align__(16) char BLs[6144];
    __shared__ int ssi[UU];
    int bh = blockIdx.x, m0 = blockIdx.y * 128;
    int tid = threadIdx.x, lane = tid & 31, wm = tid >> 5;

    if (tid < UU) ssi[tid] = sidx[tid];
    for (int i = tid; i < 6144 / 16; i += 128) {
        ((uint4*)BHs)[i] = make_uint4(0, 0, 0, 0);
        ((uint4*)BLs)[i] = make_uint4(0, 0, 0, 0);
    }
    __syncthreads();

    for (int u = tid; u < UU * 8; u += 128) {
        int j = u >> 3, c = u & 7;
        const float* src = g_K + ((size_t)bh * LL + ssi[j]) * DD + c * 8;
        float4 f0 = *(const float4*)src, f1 = *(const float4*)(src + 4);
        float xs[8] = {f0.x, f0.y, f0.z, f0.w, f1.x, f1.y, f1.z, f1.w};
        __align__(16) __nv_bfloat16 h[8], l[8];
        split8(xs, h, l);
        uint32_t sw = SWZ128((uint32_t)(j * 128 + c * 16));
        *(uint4*)(BHs + sw) = *(uint4*)h;
        *(uint4*)(BLs + sw) = *(uint4*)l;
    }
#pragma unroll
    for (int t = 0; t < 8; t++) {
        int idx = tid + 128 * t;
        int r = idx >> 3, c = idx & 7;
        const float* src = g_Q + ((size_t)bh * LL + m0 + r) * DD + c * 8;
        float4 f0 = *(const float4*)src, f1 = *(const float4*)(src + 4);
        float xs[8] = {f0.x, f0.y, f0.z, f0.w, f1.x, f1.y, f1.z, f1.w};
        __align__(16) __nv_bfloat16 h[8], l[8];
        split8(xs, h, l);
        uint32_t sw = SWZ128((uint32_t)(r * 128 + c * 16));
        *(uint4*)(AH + sw) = *(uint4*)h;
        *(uint4*)(AL + sw) = *(uint4*)l;
    }
    __syncthreads();

    float acc[2][6][4];
#pragma unroll
    for (int a = 0; a < 2; a++)
#pragma unroll
        for (int b = 0; b < 6; b++)
#pragma unroll
            for (int c = 0; c < 4; c++) acc[a][b][c] = 0.f;

    uint32_t suA_h = smem_u32(AH), suA_l = smem_u32(AL);
    uint32_t suB_h = smem_u32(BHs), suB_l = smem_u32(BLs);
    int a_row = (lane & 15), a_k16 = (lane >> 4) << 4;
    int b_grp = lane >> 3;
    int b_row = ((b_grp >> 1) << 3) + (lane & 7);
    int b_k16 = (b_grp & 1) << 4;

#pragma unroll
    for (int ks = 0; ks < 4; ks++) {
        uint32_t ah[2][4], al[2][4], bhf[12], blf[12];
#pragma unroll
        for (int mf = 0; mf < 2; mf++) {
            int row = wm * 32 + mf * 16 + a_row;
            uint32_t off = SWZ128((uint32_t)(row * 128 + ks * 32 + a_k16));
            ldsm_x4(ah[mf], suA_h + off);
            ldsm_x4(al[mf], suA_l + off);
        }
#pragma unroll
        for (int g2 = 0; g2 < 3; g2++) {
            int row = g2 * 16 + b_row;
            uint32_t off = SWZ128((uint32_t)(row * 128 + ks * 32 + b_k16));
            ldsm_x4(&bhf[g2 * 4], suB_h + off);
            ldsm_x4(&blf[g2 * 4], suB_l + off);
        }
#pragma unroll
        for (int mf = 0; mf < 2; mf++)
#pragma unroll
            for (int nf = 0; nf < 6; nf++)
                mma16816(acc[mf][nf], ah[mf], &bhf[nf * 2], acc[mf][nf]);
#pragma unroll
        for (int mf = 0; mf < 2; mf++)
#pragma unroll
            for (int nf = 0; nf < 6; nf++)
                mma16816(acc[mf][nf], ah[mf], &blf[nf * 2], acc[mf][nf]);
#pragma unroll
        for (int mf = 0; mf < 2; mf++)
#pragma unroll
            for (int nf = 0; nf < 6; nf++)
                mma16816(acc[mf][nf], al[mf], &bhf[nf * 2], acc[mf][nf]);
    }

    int cbase = (lane & 3) * 2;
#pragma unroll
    for (int mf = 0; mf < 2; mf++) {
        float mx0 = -1e30f, sm0 = 0.f, mx1 = -1e30f, sm1 = 0.f;
#pragma unroll
        for (int nf = 0; nf < 6; nf++) {
            int c0 = nf * 8 + cbase, c1 = c0 + 1;
            if (c0 < UU) { mx0 = fmaxf(mx0, acc[mf][nf][0]); sm0 += acc[mf][nf][0]; }
            if (c1 < UU) { mx0 = fmaxf(mx0, acc[mf][nf][1]); sm0 += acc[mf][nf][1]; }
            if (c0 < UU) { mx1 = fmaxf(mx1, acc[mf][nf][2]); sm1 += acc[mf][nf][2]; }
            if (c1 < UU) { mx1 = fmaxf(mx1, acc[mf][nf][3]); sm1 += acc[mf][nf][3]; }
        }
#pragma unroll
        for (int off = 1; off < 4; off <<= 1) {
            mx0 = fmaxf(mx0, __shfl_xor_sync(0xffffffffu, mx0, off));
            sm0 += __shfl_xor_sync(0xffffffffu, sm0, off);
            mx1 = fmaxf(mx1, __shfl_xor_sync(0xffffffffu, mx1, off));
            sm1 += __shfl_xor_sync(0xffffffffu, sm1, off);
        }
        if ((lane & 3) == 0) {
            int r = wm * 32 + mf * 16 + (lane >> 2);
            g_M[(size_t)bh * LL + m0 + r]     = (mx0 - sm0 * (1.f / UU)) * SCALE;
            g_M[(size_t)bh * LL + m0 + r + 8] = (mx1 - sm1 * (1.f / UU)) * SCALE;
        }
    }
}

// ---------------- top-45 via radix select ----------------
__global__ __launch_bounds__(256) void topk_kernel()
{
    __shared__ uint32_t uvals[LL];
    __shared__ int histw[8][256];
    __shared__ int scan[256];
    __shared__ int sel_byte, new_k;
    __shared__ int cnt_g, cnt_e;
    __shared__ int eq[256];
    int bh = blockIdx.x, tid = threadIdx.x;
    int w = tid >> 5;

    for (int i = tid; i < LL; i += 256) {
        uint32_t u = __float_as_uint(g_M[(size_t)bh * LL + i]);
        uvals[i] = (u & 0x80000000u) ? ~u : (u | 0x80000000u);
    }

    uint32_t prefix = 0, mask = 0;
    int k = UU;
    for (int pass = 0; pass < 4; pass++) {
        int shift = 24 - pass * 8;
#pragma unroll
        for (int ww = 0; ww < 8; ww++) histw[ww][tid] = 0;
        __syncthreads();
        for (int i = tid; i < LL; i += 256) {
            uint32_t u = uvals[i];
            if ((u & mask) == prefix)
                atomicAdd(&histw[w][(u >> shift) & 255], 1);
        }
        __syncthreads();
        int c = 0;
#pragma unroll
        for (int ww = 0; ww < 8; ww++) c += histw[ww][tid];
        scan[tid] = c;
        __syncthreads();
#pragma unroll
        for (int off = 1; off < 256; off <<= 1) {
            int v = (tid + off < 256) ? scan[tid + off] : 0;
            __syncthreads();
            scan[tid] += v;
            __syncthreads();
        }
        {
            int snext = (tid < 255) ? scan[tid + 1] : 0;
            if (scan[tid] >= k && snext < k) {
                sel_byte = tid;
                new_k = k - snext;
            }
        }
        __syncthreads();
        prefix |= ((uint32_t)sel_byte << shift);
        mask |= (255u << shift);
        k = new_k;
        __syncthreads();
    }
    uint32_t T = prefix;

    if (tid == 0) { cnt_g = 0; cnt_e = 0; }
    __syncthreads();
    for (int i = tid; i < LL; i += 256) {
        uint32_t u = uvals[i];
        if (u > T) {
            int p = atomicAdd(&cnt_g, 1);
            g_top[bh * UU + p] = i;
        } else if (u == T) {
            int p = atomicAdd(&cnt_e, 1);
            if (p < 256) eq[p] = i;
        }
    }
    __syncthreads();
    int ng = cnt_g;
    int need = UU - ng;
    if (tid == 0 && need > 0) {
        if (cnt_e <= 256) {
            int ec = cnt_e;
            for (int s = 0; s < need; s++) {
                int best = s;
                for (int j = s + 1; j < ec; j++)
                    if (eq[j] < eq[best]) best = j;
                int t = eq[s]; eq[s] = eq[best]; eq[best] = t;
                g_top[bh * UU + ng + s] = eq[s];
            }
        } else {
            int got = 0;
            for (int i = 0; i < LL && got < need; i++)
                if (uvals[i] == T) { g_top[bh * UU + ng + got] = i; got++; }
        }
    }
}

// ---------------- hit map ----------------
__global__ __launch_bounds__(256) void zero_hits()
{
    int i = blockIdx.x * 256 + threadIdx.x;
    g_hitcnt[i] = 0;
}
__global__ __launch_bounds__(64) void build_hits()
{
    int bh = blockIdx.x, tid = threadIdx.x;
    if (tid < UU) {
        int b = bh >> 3, h = bh & 7;
        int t = g_top[bh * UU + tid];
        int p = atomicAdd(&g_hitcnt[b * LL + t], 1);
        g_hitlist[(b * LL + t) * 8 + p] = (h << 8) | tid;
    }
}

// ---------------- mean(V): 4-way split partials + reduce ----------------
__global__ __launch_bounds__(256) void meanv_part()
{
    __shared__ float red[4][64];
    int bh = blockIdx.x, part = blockIdx.y, tid = threadIdx.x;
    int d = tid & 63, sub = tid >> 6;
    const float* base =
        g_V + ((size_t)bh * LL + part * (LL / 4) + sub * (LL / 16)) * DD + d;
    float s0 = 0.f, s1 = 0.f, s2 = 0.f, s3 = 0.f;
    for (int i = 0; i < LL / 16; i += 4) {
        s0 += base[(size_t)(i + 0) * DD];
        s1 += base[(size_t)(i + 1) * DD];
        s2 += base[(size_t)(i + 2) * DD];
        s3 += base[(size_t)(i + 3) * DD];
    }
    red[sub][d] = (s0 + s1) + (s2 + s3);
    __syncthreads();
    if (sub == 0)
        g_mv4[part][bh * DD + d] =
            (red[0][d] + red[1][d]) + (red[2][d] + red[3][d]);
}

__global__ __launch_bounds__(64) void mv_reduce()
{
    int bh = blockIdx.x, d = threadIdx.x;
    g_meanV[bh * DD + d] =
        ((g_mv4[0][bh * DD + d] + g_mv4[1][bh * DD + d]) +
         (g_mv4[2][bh * DD + d] + g_mv4[3][bh * DD + d])) * (1.f / LL);
}

// ---------------- base row per batch ----------------
__global__ __launch_bounds__(512) void base_kernel(const float* __restrict__ Wo,
                                                   const float* __restrict__ bo)
{
    int b = blockIdx.x, c = threadIdx.x;
    float acc = bo[c];
    const float* mv = g_meanV + b * DM;
    for (int k = 0; k < DM; k++) acc += mv[k] * Wo[(size_t)k * DM + c];
    g_base[b * DM + c] = acc;
}

// ---------------- flash attention via MMA, split over NCH chunks ----------------
__global__ __launch_bounds__(128) void att_mma()
{
    extern __shared__ char sm[];
    int bh = blockIdx.x, ch = blockIdx.y;
    int tid = threadIdx.x, lane = tid & 31, w = tid >> 5;
    int* tops = (int*)(sm + A_TOP);

    if (tid < UU) tops[tid] = g_top[bh * UU + tid];
    // zero Q tiles (rows 45..63 stay zero)
    for (int i = tid; i < 1024; i += 128) {
        ((uint4*)(sm + A_QH))[i] = make_uint4(0, 0, 0, 0);
        ((uint4*)(sm + A_QL))[i] = make_uint4(0, 0, 0, 0);
    }
    __syncthreads();
    // gather Q_red rows, split to bf16
    for (int u = tid; u < UU * 8; u += 128) {
        int j = u >> 3, c = u & 7;
        const float* src = g_Q + ((size_t)bh * LL + tops[j]) * DD + c * 8;
        float4 f0 = *(const float4*)src, f1 = *(const float4*)(src + 4);
        float xs[8] = {f0.x, f0.y, f0.z, f0.w, f1.x, f1.y, f1.z, f1.w};
        __align__(16) __nv_bfloat16 h[8], l[8];
        split8(xs, h, l);
        uint32_t sw = SWZ128((uint32_t)(j * 128 + c * 16));
        *(uint4*)(sm + A_QH + sw) = *(uint4*)h;
        *(uint4*)(sm + A_QL + sw) = *(uint4*)l;
    }
    __syncthreads();

    uint32_t su = smem_u32(sm);
    int a_row = (lane & 15), a_k16 = (lane >> 4) << 4;
    int b_grp = lane >> 3;
    int b_row = ((b_grp >> 1) << 3) + (lane & 7);
    int b_k16 = (b_grp & 1) << 4;

    // preload Q fragments (held all kernel)
    uint32_t qah[4][4], qal[4][4];
#pragma unroll
    for (int ks = 0; ks < 4; ks++) {
        int row = w * 16 + a_row;
        uint32_t off = SWZ128((uint32_t)(row * 128 + ks * 32 + a_k16));
        ldsm_x4(qah[ks], su + A_QH + off);
        ldsm_x4(qal[ks], su + A_QL + off);
    }

    float mrow[2] = {-1e30f, -1e30f};
    float lsum[2] = {0.f, 0.f};
    float oacc[8][4];
#pragma unroll
    for (int nf = 0; nf < 8; nf++)
#pragma unroll
        for (int c = 0; c < 4; c++) oacc[nf][c] = 0.f;

    int key0 = ch * CHUNK;
    for (int t0 = 0; t0 < CHUNK; t0 += 64) {
        __syncthreads();   // protect K/V smem reuse
        // load K tile [64 keys x 64] and V^T tile [64 dims x 64 keys], split bf16
        for (int i = tid; i < 1024; i += 128) {
            int r = i >> 4, c4 = i & 15;   // key r, dims c4*4..+3
            const float* ks_ = g_K + ((size_t)bh * LL + key0 + t0 + r) * DD + c4 * 4;
            float4 kv = *(const float4*)ks_;
            float xk[4] = {kv.x, kv.y, kv.z, kv.w};
            __nv_bfloat16 h4[4], l4[4];
#pragma unroll
            for (int q2 = 0; q2 < 4; q2++) {
                __nv_bfloat16 hb = __float2bfloat16(xk[q2]);
                h4[q2] = hb;
                l4[q2] = __float2bfloat16(xk[q2] - __bfloat162float(hb));
            }
            uint32_t sw = SWZ128((uint32_t)(r * 128 + c4 * 8));
            *(uint2*)(sm + A_KH + sw) = *(uint2*)h4;
            *(uint2*)(sm + A_KL + sw) = *(uint2*)l4;

            const float* vs_ = g_V + ((size_t)bh * LL + key0 + t0 + r) * DD + c4 * 4;
            float4 vv = *(const float4*)vs_;
            float xv[4] = {vv.x, vv.y, vv.z, vv.w};
#pragma unroll
            for (int q2 = 0; q2 < 4; q2++) {
                int d = c4 * 4 + q2;
                __nv_bfloat16 hb = __float2bfloat16(xv[q2]);
                __nv_bfloat16 lb = __float2bfloat16(xv[q2] - __bfloat162float(hb));
                uint32_t swv = SWZ128((uint32_t)(d * 128 + r * 2));
                *(__nv_bfloat16*)(sm + A_VH + swv) = hb;
                *(__nv_bfloat16*)(sm + A_VL + swv) = lb;
            }
        }
        __syncthreads();

        // ---- S = Q . K^T (split, 3 products) ----
        float sacc[8][4];
#pragma unroll
        for (int nf = 0; nf < 8; nf++)
#pragma unroll
            for (int c = 0; c < 4; c++) sacc[nf][c] = 0.f;
#pragma unroll
        for (int ks = 0; ks < 4; ks++) {
            uint32_t kbh[16], kbl[16];
#pragma unroll
            for (int g2 = 0; g2 < 4; g2++) {
                int row = g2 * 16 + b_row;
                uint32_t off = SWZ128((uint32_t)(row * 128 + ks * 32 + b_k16));
                ldsm_x4(&kbh[g2 * 4], su + A_KH + off);
                ldsm_x4(&kbl[g2 * 4], su + A_KL + off);
            }
#pragma unroll
            for (int nf = 0; nf < 8; nf++)
                mma16816(sacc[nf], qah[ks], &kbh[nf * 2], sacc[nf]);
#pragma unroll
            for (int nf = 0; nf < 8; nf++)
                mma16816(sacc[nf], qah[ks], &kbl[nf * 2], sacc[nf]);
#pragma unroll
            for (int nf = 0; nf < 8; nf++)
                mma16816(sacc[nf], qal[ks], &kbh[nf * 2], sacc[nf]);
        }
        // ---- online softmax (rows r=lane>>2 and r+8) ----
#pragma unroll
        for (int nf = 0; nf < 8; nf++)
#pragma unroll
            for (int c = 0; c < 4; c++) sacc[nf][c] *= SCALE;
        float tmax0 = -1e30f, tmax1 = -1e30f;
#pragma unroll
        for (int nf = 0; nf < 8; nf++) {
            tmax0 = fmaxf(tmax0, fmaxf(sacc[nf][0], sacc[nf][1]));
            tmax1 = fmaxf(tmax1, fmaxf(sacc[nf][2], sacc[nf][3]));
        }
#pragma unroll
        for (int off = 1; off < 4; off <<= 1) {
            tmax0 = fmaxf(tmax0, __shfl_xor_sync(0xffffffffu, tmax0, off));
            tmax1 = fmaxf(tmax1, __shfl_xor_sync(0xffffffffu, tmax1, off));
        }
        float mn0 = fmaxf(mrow[0], tmax0), mn1 = fmaxf(mrow[1], tmax1);
        float al0 = __expf(mrow[0] - mn0), al1 = __expf(mrow[1] - mn1);
        float rs0 = 0.f, rs1 = 0.f;
#pragma unroll
        for (int nf = 0; nf < 8; nf++) {
            sacc[nf][0] = __expf(sacc[nf][0] - mn0);
            sacc[nf][1] = __expf(sacc[nf][1] - mn0);
            sacc[nf][2] = __expf(sacc[nf][2] - mn1);
            sacc[nf][3] = __expf(sacc[nf][3] - mn1);
            rs0 += sacc[nf][0] + sacc[nf][1];
            rs1 += sacc[nf][2] + sacc[nf][3];
        }
#pragma unroll
        for (int off = 1; off < 4; off <<= 1) {
            rs0 += __shfl_xor_sync(0xffffffffu, rs0, off);
            rs1 += __shfl_xor_sync(0xffffffffu, rs1, off);
        }
        lsum[0] = lsum[0] * al0 + rs0;
        lsum[1] = lsum[1] * al1 + rs1;
        mrow[0] = mn0;
        mrow[1] = mn1;
#pragma unroll
        for (int nf = 0; nf < 8; nf++) {
            oacc[nf][0] *= al0; oacc[nf][1] *= al0;
            oacc[nf][2] *= al1; oacc[nf][3] *= al1;
        }
        // ---- O += P . V  (P from fragments, split) ----
#pragma unroll
        for (int ks = 0; ks < 4; ks++) {
            uint32_t pah[4], pal[4];
            {
                float p0 = sacc[2 * ks][0],     p1 = sacc[2 * ks][1];
                float p2 = sacc[2 * ks][2],     p3 = sacc[2 * ks][3];
                float p4 = sacc[2 * ks + 1][0], p5 = sacc[2 * ks + 1][1];
                float p6 = sacc[2 * ks + 1][2], p7 = sacc[2 * ks + 1][3];
                float h0 = __bfloat162float(__float2bfloat16(p0));
                float h1 = __bfloat162float(__float2bfloat16(p1));
                float h2 = __bfloat162float(__float2bfloat16(p2));
                float h3 = __bfloat162float(__float2bfloat16(p3));
                float h4 = __bfloat162float(__float2bfloat16(p4));
                float h5 = __bfloat162float(__float2bfloat16(p5));
                float h6 = __bfloat162float(__float2bfloat16(p6));
                float h7 = __bfloat162float(__float2bfloat16(p7));
                pah[0] = pack2(p0, p1); pah[1] = pack2(p2, p3);
                pah[2] = pack2(p4, p5); pah[3] = pack2(p6, p7);
                pal[0] = pack2(p0 - h0, p1 - h1); pal[1] = pack2(p2 - h2, p3 - h3);
                pal[2] = pack2(p4 - h4, p5 - h5); pal[3] = pack2(p6 - h6, p7 - h7);
            }
            uint32_t vbh[16], vbl[16];
#pragma unroll
            for (int g2 = 0; g2 < 4; g2++) {
                int row = g2 * 16 + b_row;   // dim rows
                uint32_t off = SWZ128((uint32_t)(row * 128 + ks * 32 + b_k16));
                ldsm_x4(&vbh[g2 * 4], su + A_VH + off);
                ldsm_x4(&vbl[g2 * 4], su + A_VL + off);
            }
#pragma unroll
            for (int nf = 0; nf < 8; nf++)
                mma16816(oacc[nf], pah, &vbh[nf * 2], oacc[nf]);
#pragma unroll
            for (int nf = 0; nf < 8; nf++)
                mma16816(oacc[nf], pah, &vbl[nf * 2], oacc[nf]);
#pragma unroll
            for (int nf = 0; nf < 8; nf++)
                mma16816(oacc[nf], pal, &vbh[nf * 2], oacc[nf]);
        }
    }

    // ---- write partials (same layout as before) ----
    int r0 = w * 16 + (lane >> 2);
    int r1 = r0 + 8;
    int cb = (lane & 3) * 2;
    if (r0 < UU) {
        int idx = (bh * NCH + ch) * UU + r0;
        if ((lane & 3) == 0) { g_pm[idx] = mrow[0]; g_pl[idx] = lsum[0]; }
        float* pa = g_pacc + (size_t)idx * DD;
#pragma unroll
        for (int nf = 0; nf < 8; nf++) {
            pa[nf * 8 + cb]     = oacc[nf][0];
            pa[nf * 8 + cb + 1] = oacc[nf][1];
        }
    }
    if (r1 < UU) {
        int idx = (bh * NCH + ch) * UU + r1;
        if ((lane & 3) == 0) { g_pm[idx] = mrow[1]; g_pl[idx] = lsum[1]; }
        float* pa = g_pacc + (size_t)idx * DD;
#pragma unroll
        for (int nf = 0; nf < 8; nf++) {
            pa[nf * 8 + cb]     = oacc[nf][2];
            pa[nf * 8 + cb + 1] = oacc[nf][3];
        }
    }
}

// ---------------- merge split-L partials ----------------
__global__ __launch_bounds__(64) void combine_kernel()
{
    int r = blockIdx.x;
    int d = threadIdx.x;
    int bh = r / UU, q = r % UU;
    float M = -1e30f;
#pragma unroll
    for (int c = 0; c < NCH; c++)
        M = fmaxf(M, g_pm[(bh * NCH + c) * UU + q]);
    float Ltot = 0.f, acc = 0.f;
#pragma unroll
    for (int c = 0; c < NCH; c++) {
        int idx = (bh * NCH + c) * UU + q;
        float e = __expf(g_pm[idx] - M);
        Ltot += g_pl[idx] * e;
        acc  += e * g_pacc[(size_t)idx * DD + d];
    }
    g_attn[(size_t)(bh * UU + q) * DD + d] = acc / Ltot;
}

// ---------------- final output: hit-list driven ----------------
__global__ __launch_bounds__(128) void final_kernel(const float* __restrict__ Wo,
                                                    float* __restrict__ out)
{
    __shared__ float delta[64];
    __shared__ int hits[8];
    int qrow = blockIdx.x, b = blockIdx.y;
    int tid = threadIdx.x;
    int c0 = tid * 4;

    int cnt = g_hitcnt[b * LL + qrow];
    float4 acc = *(const float4*)&g_base[b * DM + c0];

    if (cnt > 0) {
        if (tid < cnt) hits[tid] = g_hitlist[(b * LL + qrow) * 8 + tid];
        __syncthreads();
        if (tid == 0) {
            for (int s = 1; s < cnt; s++) {
                int v = hits[s], j2 = s;
                while (j2 > 0 && hits[j2 - 1] > v) { hits[j2] = hits[j2 - 1]; j2--; }
                hits[j2] = v;
            }
        }
        __syncthreads();
        for (int i = 0; i < cnt; i++) {
            int e = hits[i];
            int h = e >> 8, j = e & 255;
            if (tid < 64)
                delta[tid] = g_attn[((size_t)(b * HH + h) * UU + j) * DD + tid] -
                             g_meanV[(b * HH + h) * DD + tid];
            __syncthreads();
#pragma unroll 4
            for (int d = 0; d < 64; d++) {
                float dv = delta[d];
                float4 w = *(const float4*)&Wo[(size_t)(h * 64 + d) * DM + c0];
                acc.x += dv * w.x; acc.y += dv * w.y;
                acc.z += dv * w.z; acc.w += dv * w.w;
            }
            __syncthreads();
        }
    }
    *(float4*)&out[((size_t)b * LL + qrow) * DM + c0] = acc;
}

// ---------------- launcher ----------------
extern "C" void kernel_launch(void* const* d_in, const int* in_sizes, int n_in,
                              void* d_out, int out_size)
{
    const float* queries = (const float*)d_in[0];
    const float* keys    = (const float*)d_in[1];
    const float* values  = (const float*)d_in[2];
    const int*   sidx    = (const int*)d_in[3];
    const float* Wq = (const float*)d_in[4];
    const float* bq = (const float*)d_in[5];
    const float* Wk = (const float*)d_in[6];
    const float* bk = (const float*)d_in[7];
    const float* Wv = (const float*)d_in[8];
    const float* bv = (const float*)d_in[9];
    const float* Wo = (const float*)d_in[10];
    const float* bo = (const float*)d_in[11];
    float* out = (float*)d_out;

    static int smem_set = 0;
    if (!smem_set) {
        cudaFuncSetAttribute(proj_mma, cudaFuncAttributeMaxDynamicSharedMemorySize, DYN_SMEM);
        cudaFuncSetAttribute(att_mma, cudaFuncAttributeMaxDynamicSharedMemorySize, DYN_SMEM_ATT);
        smem_set = 1;
    }

    prep_w<<<dim3(256, 3), 256>>>(Wq, Wk, Wv);
    zero_hits<<<BB * LL / 256, 256>>>();

    proj_mma<<<dim3(DM / 128, BL / 128, 3), 256, DYN_SMEM>>>(
        queries, keys, values, bq, bk, bv);

    meanv_part<<<dim3(BB * HH, 4), 256>>>();
    score_mma<<<dim3(BB * HH, LL / 128), 128>>>(sidx);
    topk_kernel<<<BB * HH, 256>>>();
    build_hits<<<BB * HH, 64>>>();
    mv_reduce<<<BB * HH, 64>>>();
    base_kernel<<<BB, 512>>>(Wo, bo);
    att_mma<<<dim3(BB * HH, NCH), 128, DYN_SMEM_ATT>>>();
    combine_kernel<<<BB * HH * UU, 64>>>();
    final_kernel<<<dim3(LL, BB), 128>>>(Wo, out);
}